// round 2
// baseline (speedup 1.0000x reference)
#include <cuda_runtime.h>
#include <cuda_bf16.h>
#include <math.h>

// ---------------------------------------------------------------------------
// Problem constants
//   L=1024, K=8, R=128, T=32, B=64, DIN=300, REG=36, R3=384, H3=3072
// ---------------------------------------------------------------------------

// ---------------- scratch layout (floats) ----------------
#define SZ_GI      (32L*64*3072)     // 6291456   per direction
#define SZ_HS      (64L*32*1024)     // 2097152
#define SZ_HST     (2L*2*64*1024)    // 262144    2 dirs x 2 ping-pong x (64x1024)
#define SZ_CR      (2048L*128)       // 262144
#define SZ_QK      (2048L*128)       // 262144
#define SZ_V       (2048L*1024)      // 2097152
#define SZ_ATT     (2048L*32)        // 65536
#define SZ_AW      (64L*32)
#define SZ_TE      (64L*1024)
#define SZ_IEG     (64L*1024)
#define SZ_IVN     (64L*1024)
#define SZ_IGV     (64L*128)
#define SZ_WG      (64L*49152)       // 3145728 per weight set
#define SZ_BG      (64L*384)
#define SZ_GIG     (64L*2048*384)    // 50331648
#define SZ_HG      (2L*64*64*128)    // 1048576
#define SZ_HMAX    (64L*64*128)      // 524288
#define SZ_FCB     (64L*1024)
#define SZ_Y       (64L*64*1024)     // 4194304

#define O_GI_F  0L
#define O_GI_B  (O_GI_F + SZ_GI)
#define O_HSF   (O_GI_B + SZ_GI)
#define O_HSB   (O_HSF + SZ_HS)
#define O_TXT   (O_HSB + SZ_HS)
#define O_HST   (O_TXT + SZ_HS)
#define O_CR    (O_HST + SZ_HST)
#define O_Q     (O_CR + SZ_CR)
#define O_K     (O_Q + SZ_QK)
#define O_V     (O_K + SZ_QK)
#define O_ATT   (O_V + SZ_V)
#define O_AW    (O_ATT + SZ_ATT)
#define O_TE    (O_AW + SZ_AW)
#define O_IEG   (O_TE + SZ_TE)
#define O_IVN   (O_IEG + SZ_IEG)
#define O_IGV   (O_IVN + SZ_IVN)
#define O_WIH   (O_IGV + SZ_IGV)
#define O_WHH   (O_WIH + SZ_WG)
#define O_BIH   (O_WHH + SZ_WG)
#define O_BHH   (O_BIH + SZ_BG)
#define O_GIG   (O_BHH + SZ_BG)
#define O_HG    (O_GIG + SZ_GIG)
#define O_HMAX  (O_HG + SZ_HG)
#define O_FCB   (O_HMAX + SZ_HMAX)
#define O_Y     (O_FCB + SZ_FCB)
#define SCRATCH_TOTAL (O_Y + SZ_Y)

__device__ float g_scratch[SCRATCH_TOTAL];

__device__ __forceinline__ float sigf(float x) { return 1.f / (1.f + expf(-x)); }

// ---------------------------------------------------------------------------
// init: zero GRU states (both ping-pong buffers), hmax = -inf
// ---------------------------------------------------------------------------
__global__ __launch_bounds__(256) void init_k() {
    long idx = (long)blockIdx.x * 256 + threadIdx.x;
    if (idx < SZ_HST)  g_scratch[O_HST + idx] = 0.f;
    if (idx < SZ_HG)   g_scratch[O_HG + idx] = 0.f;
    if (idx < SZ_HMAX) g_scratch[O_HMAX + idx] = -1e30f;
}

// ---------------------------------------------------------------------------
// Generic tiled SGEMM: C[m,n] = sum_k A(m,k) * W[n*ldw + k] (+bias[n]) (+Cadd[m,n])
// MODE selects the A indexing:
//   0: A[m*K + k]                                (natural row-major, lda=K)
//   1: m=t*64+b over cap_embed (B,T,300):  A[(m&63)*9600 + (m>>6)*300 + k]
//   2: m=t*64+b over cap_reduced (B,T,128): A[((m&63)*32 + (m>>6))*128 + k]
// batch index = blockIdx.z with per-tensor strides.
// ---------------------------------------------------------------------------
template <int MODE>
__device__ __forceinline__ long a_idx(int m, int k, int K) {
    if (MODE == 0) return (long)m * K + k;
    if (MODE == 1) { int b = m & 63, t = m >> 6; return (long)b * 9600 + (long)t * 300 + k; }
    { int b = m & 63, t = m >> 6; return ((long)(b * 32 + t)) * 128 + k; }
}

template <int MODE>
__global__ __launch_bounds__(256) void gemm_k(
    const float* __restrict__ A, const float* __restrict__ W,
    const float* __restrict__ bias, const float* __restrict__ Cadd,
    float* __restrict__ C,
    int M, int N, int K, int ldw,
    long aBS, long wBS, long bBS, long cBS)
{
    int bz = blockIdx.z;
    A += (long)bz * aBS;
    W += (long)bz * wBS;
    C += (long)bz * cBS;
    const float* biasp = bias ? (bias + (long)bz * bBS) : nullptr;

    __shared__ float As[16][65];
    __shared__ float Bs[16][65];
    int tid = threadIdx.x;
    int tx = tid & 15, ty = tid >> 4;
    int m0 = blockIdx.y * 64, n0 = blockIdx.x * 64;

    float acc[4][4];
#pragma unroll
    for (int i = 0; i < 4; i++)
#pragma unroll
        for (int j = 0; j < 4; j++) acc[i][j] = 0.f;

    for (int k0 = 0; k0 < K; k0 += 16) {
#pragma unroll
        for (int r = 0; r < 4; r++) {
            int i = tid + r * 256;
            int mm = i >> 4, kk = i & 15;
            int m = m0 + mm, k = k0 + kk;
            As[kk][mm] = (m < M && k < K) ? A[a_idx<MODE>(m, k, K)] : 0.f;
        }
#pragma unroll
        for (int r = 0; r < 4; r++) {
            int i = tid + r * 256;
            int nn = i >> 4, kk = i & 15;
            int n = n0 + nn, k = k0 + kk;
            Bs[kk][nn] = (n < N && k < K) ? W[(long)n * ldw + k] : 0.f;
        }
        __syncthreads();
#pragma unroll
        for (int kk = 0; kk < 16; kk++) {
            float av[4], bv[4];
#pragma unroll
            for (int i = 0; i < 4; i++) av[i] = As[kk][ty * 4 + i];
#pragma unroll
            for (int j = 0; j < 4; j++) bv[j] = Bs[kk][tx * 4 + j];
#pragma unroll
            for (int i = 0; i < 4; i++)
#pragma unroll
                for (int j = 0; j < 4; j++) acc[i][j] += av[i] * bv[j];
        }
        __syncthreads();
    }

#pragma unroll
    for (int i = 0; i < 4; i++) {
        int m = m0 + ty * 4 + i;
        if (m >= M) continue;
#pragma unroll
        for (int j = 0; j < 4; j++) {
            int n = n0 + tx * 4 + j;
            if (n >= N) continue;
            float v = acc[i][j];
            if (biasp) v += biasp[n];
            if (Cadd) v += Cadd[(long)m * N + n];
            C[(long)m * N + n] = v;
        }
    }
}

// ---------------------------------------------------------------------------
// Main GRU step: both directions in one launch (grid.y = dir).
// dir 0 processes time t (forward), dir 1 processes time 31-t (backward).
// Per block: 16 h-columns, M=64 rows, computes 3 gate GEMM slices (K=1024),
// fuses gate math, ping-pong state, writes hs.
// ---------------------------------------------------------------------------
__global__ __launch_bounds__(256) void gru_step_k(
    int t,
    const float* __restrict__ Whh_f, const float* __restrict__ bhh_f,
    const float* __restrict__ Whh_b, const float* __restrict__ bhh_b)
{
    int dir = blockIdx.y;
    const float* Whh = dir ? Whh_b : Whh_f;
    const float* bhh = dir ? bhh_b : bhh_f;
    const float* gi  = g_scratch + (dir ? O_GI_B : O_GI_F);
    float* hs        = g_scratch + (dir ? O_HSB : O_HSF);
    float* hbase     = g_scratch + O_HST + (long)dir * 131072;
    const float* hin = hbase + (long)(t & 1) * 65536;
    float* hout      = hbase + (long)((t + 1) & 1) * 65536;
    int tt = dir ? (31 - t) : t;

    __shared__ float As[32][65];   // [k][m] tile of h
    __shared__ float Bs[32][49];   // [k][c] 48 gate columns
    int tid = threadIdx.x;
    int tx = tid & 15, ty = tid >> 4;
    int j0 = blockIdx.x * 16;

    float acc[3][4];
#pragma unroll
    for (int g = 0; g < 3; g++)
#pragma unroll
        for (int i = 0; i < 4; i++) acc[g][i] = 0.f;

    for (int k0 = 0; k0 < 1024; k0 += 32) {
#pragma unroll
        for (int r = 0; r < 8; r++) {
            int i = tid + r * 256;
            int mm = i >> 5, kk = i & 31;
            As[kk][mm] = hin[mm * 1024 + k0 + kk];
        }
#pragma unroll
        for (int r = 0; r < 6; r++) {
            int i = tid + r * 256;
            int cc = i >> 5, kk = i & 31;       // cc in [0,48)
            int gate = cc >> 4, jj = cc & 15;
            Bs[kk][cc] = Whh[(long)(gate * 1024 + j0 + jj) * 1024 + k0 + kk];
        }
        __syncthreads();
#pragma unroll
        for (int kk = 0; kk < 32; kk++) {
            float av[4], bv[3];
#pragma unroll
            for (int i = 0; i < 4; i++) av[i] = As[kk][ty * 4 + i];
#pragma unroll
            for (int g = 0; g < 3; g++) bv[g] = Bs[kk][g * 16 + tx];
#pragma unroll
            for (int g = 0; g < 3; g++)
#pragma unroll
                for (int i = 0; i < 4; i++) acc[g][i] += av[i] * bv[g];
        }
        __syncthreads();
    }

    int col = j0 + tx;
#pragma unroll
    for (int i = 0; i < 4; i++) {
        int m = ty * 4 + i;
        const float* girow = gi + ((long)tt * 64 + m) * 3072;
        float ghr = acc[0][i] + bhh[col];
        float ghz = acc[1][i] + bhh[1024 + col];
        float ghn = acc[2][i] + bhh[2048 + col];
        float r = sigf(girow[col] + ghr);
        float z = sigf(girow[1024 + col] + ghz);
        float n = tanhf(girow[2048 + col] + r * ghn);
        float hold = hin[m * 1024 + col];
        float hn = (1.f - z) * n + z * hold;
        hout[m * 1024 + col] = hn;
        hs[(long)m * 32768 + (long)tt * 1024 + col] = hn;
    }
}

// txt = 0.5*(hsf + hsb)
__global__ __launch_bounds__(256) void combine_k() {
    long i = (long)blockIdx.x * 256 + threadIdx.x;
    if (i < SZ_HS)
        g_scratch[O_TXT + i] = 0.5f * (g_scratch[O_HSF + i] + g_scratch[O_HSB + i]);
}

// ---------------------------------------------------------------------------
// img pooling: img_embed_global (mean over regions) + its l2-normalized copy
// ---------------------------------------------------------------------------
__global__ __launch_bounds__(256) void img_pool_k(const float* __restrict__ img_embed) {
    int b = blockIdx.x, tid = threadIdx.x;
    float vals[4], ss = 0.f;
#pragma unroll
    for (int i = 0; i < 4; i++) {
        int c = i * 256 + tid;
        float s = 0.f;
        for (int g = 0; g < 36; g++) s += img_embed[(long)b * 36864 + (long)g * 1024 + c];
        s *= (1.f / 36.f);
        vals[i] = s;
        ss += s * s;
        g_scratch[O_IEG + (long)b * 1024 + c] = s;
    }
    __shared__ float red[256];
    red[tid] = ss;
    __syncthreads();
    for (int o = 128; o > 0; o >>= 1) { if (tid < o) red[tid] += red[tid + o]; __syncthreads(); }
    float inv = 1.f / (sqrtf(red[0]) + 1e-8f);
#pragma unroll
    for (int i = 0; i < 4; i++) {
        int c = i * 256 + tid;
        g_scratch[O_IVN + (long)b * 1024 + c] = vals[i] * inv;
    }
}

// ---------------------------------------------------------------------------
// attention scores + softmax: one warp per (b,t)
// ---------------------------------------------------------------------------
__global__ __launch_bounds__(256) void attn_k() {
    int gw = (blockIdx.x * blockDim.x + threadIdx.x) >> 5;
    int lane = threadIdx.x & 31;
    if (gw >= 2048) return;
    int b = gw >> 5;
    const float* qr = g_scratch + O_Q + (long)gw * 128;
    const float* kr = g_scratch + O_K + ((long)b * 32 + lane) * 128;
    float s = 0.f;
#pragma unroll 8
    for (int o = 0; o < 128; o++) s += qr[o] * kr[o];
    float mx = s;
#pragma unroll
    for (int off = 16; off > 0; off >>= 1) mx = fmaxf(mx, __shfl_xor_sync(0xffffffffu, mx, off));
    float e = expf(s - mx);
    float sum = e;
#pragma unroll
    for (int off = 16; off > 0; off >>= 1) sum += __shfl_xor_sync(0xffffffffu, sum, off);
    g_scratch[O_ATT + (long)gw * 32 + lane] = e / sum;
}

// aw[b,s] = sum_{t<len} attn[b,t,s]
__global__ __launch_bounds__(32) void aw_k(const int* __restrict__ lens) {
    int b = blockIdx.x, s = threadIdx.x;
    int len = lens[b];
    float a = 0.f;
    for (int tt = 0; tt < len; tt++) a += g_scratch[O_ATT + ((long)b * 32 + tt) * 32 + s];
    g_scratch[O_AW + b * 32 + s] = a;
}

// txt_embed[b,c] = (sum_{t<len} txt[b,t,c] + gamma * sum_s aw[b,s]*v[b,s,c]) / len
__global__ __launch_bounds__(256) void txt_embed_k(const int* __restrict__ lens,
                                                   const float* __restrict__ gamma) {
    int b = blockIdx.y;
    int c = blockIdx.x * 256 + threadIdx.x;
    __shared__ float saw[32];
    if (threadIdx.x < 32) saw[threadIdx.x] = g_scratch[O_AW + b * 32 + threadIdx.x];
    __syncthreads();
    int len = lens[b];
    float g = *gamma;
    float a1 = 0.f;
    for (int tt = 0; tt < len; tt++) a1 += g_scratch[O_TXT + ((long)b * 32 + tt) * 1024 + c];
    float a2 = 0.f;
#pragma unroll
    for (int s = 0; s < 32; s++) a2 += saw[s] * g_scratch[O_V + ((long)b * 32 + s) * 1024 + c];
    g_scratch[O_TE + (long)b * 1024 + c] = (a1 + g * a2) / (float)len;
}

// ---------------------------------------------------------------------------
// Generated-weight GRU step: grid (4 h-tiles of 32, 64 images).
// gh = h_i @ Whh_g[i]^T, gate fuse, running max.
// ---------------------------------------------------------------------------
__global__ __launch_bounds__(256) void gen_step_k(int t) {
    int img = blockIdx.y;
    int j0 = blockIdx.x * 32;
    const float* Whh = g_scratch + O_WHH + (long)img * 49152;
    const float* bhh = g_scratch + O_BHH + (long)img * 384;
    const float* gi  = g_scratch + O_GIG + (long)img * 786432 + (long)t * 64 * 384;
    float* hbase = g_scratch + O_HG;
    const float* hin = hbase + (long)(t & 1) * 524288 + (long)img * 8192;
    float* hout      = hbase + (long)((t + 1) & 1) * 524288 + (long)img * 8192;
    float* hmax = g_scratch + O_HMAX + (long)img * 8192;

    __shared__ float As[32][65];
    __shared__ float Bs[32][97];
    int tid = threadIdx.x;
    int tx = tid & 31, ty = tid >> 5;

    float acc[3][8];
#pragma unroll
    for (int g = 0; g < 3; g++)
#pragma unroll
        for (int i = 0; i < 8; i++) acc[g][i] = 0.f;

    for (int k0 = 0; k0 < 128; k0 += 32) {
#pragma unroll
        for (int r = 0; r < 8; r++) {
            int i = tid + r * 256;
            int mm = i >> 5, kk = i & 31;
            As[kk][mm] = hin[mm * 128 + k0 + kk];
        }
#pragma unroll
        for (int r = 0; r < 12; r++) {
            int i = tid + r * 256;
            int cc = i >> 5, kk = i & 31;       // cc in [0,96)
            int gate = cc >> 5, jj = cc & 31;
            Bs[kk][cc] = Whh[(long)(gate * 128 + j0 + jj) * 128 + k0 + kk];
        }
        __syncthreads();
#pragma unroll
        for (int kk = 0; kk < 32; kk++) {
            float av[8], bv[3];
#pragma unroll
            for (int i = 0; i < 8; i++) av[i] = As[kk][ty * 8 + i];
#pragma unroll
            for (int g = 0; g < 3; g++) bv[g] = Bs[kk][g * 32 + tx];
#pragma unroll
            for (int g = 0; g < 3; g++)
#pragma unroll
                for (int i = 0; i < 8; i++) acc[g][i] += av[i] * bv[g];
        }
        __syncthreads();
    }

    int col = j0 + tx;
#pragma unroll
    for (int i = 0; i < 8; i++) {
        int m = ty * 8 + i;
        const float* girow = gi + m * 384;
        float ghr = acc[0][i] + bhh[col];
        float ghz = acc[1][i] + bhh[128 + col];
        float ghn = acc[2][i] + bhh[256 + col];
        float r = sigf(girow[col] + ghr);
        float z = sigf(girow[128 + col] + ghz);
        float n = tanhf(girow[256 + col] + r * ghn);
        float hold = hin[m * 128 + col];
        float hn = (1.f - z) * n + z * hold;
        hout[m * 128 + col] = hn;
        hmax[m * 128 + col] = fmaxf(hmax[m * 128 + col], hn);
    }
}

// sims[i,b] = (y . iv_i) / (|y| + eps)
__global__ __launch_bounds__(256) void sims_k(float* __restrict__ out) {
    int img = blockIdx.y, b = blockIdx.x;
    int tid = threadIdx.x;
    const float* y = g_scratch + O_Y + (long)img * 65536 + (long)b * 1024;
    const float* iv = g_scratch + O_IVN + (long)img * 1024;
    float ss = 0.f, dp = 0.f;
#pragma unroll
    for (int i = 0; i < 4; i++) {
        int c = i * 256 + tid;
        float v = y[c];
        ss += v * v;
        dp += v * iv[c];
    }
    __shared__ float r1[256], r2[256];
    r1[tid] = ss; r2[tid] = dp;
    __syncthreads();
    for (int o = 128; o > 0; o >>= 1) {
        if (tid < o) { r1[tid] += r1[tid + o]; r2[tid] += r2[tid + o]; }
        __syncthreads();
    }
    if (tid == 0) out[img * 64 + b] = r2[0] / (sqrtf(r1[0]) + 1e-8f);
}

// ---------------------------------------------------------------------------
// host launcher
// ---------------------------------------------------------------------------
extern "C" void kernel_launch(void* const* d_in, const int* in_sizes, int n_in,
                              void* d_out, int out_size) {
    const float* img_embed    = (const float*)d_in[0];
    const float* cap_embed    = (const float*)d_in[1];
    const int*   lens         = (const int*)d_in[2];
    const float* W_reduce_img = (const float*)d_in[3];
    const float* b_reduce_img = (const float*)d_in[4];
    const float* W_reduce_txt = (const float*)d_in[5];
    const float* b_reduce_txt = (const float*)d_in[6];
    const float* gru_Wih_f    = (const float*)d_in[7];
    const float* gru_Whh_f    = (const float*)d_in[8];
    const float* gru_bih_f    = (const float*)d_in[9];
    const float* gru_bhh_f    = (const float*)d_in[10];
    const float* gru_Wih_b    = (const float*)d_in[11];
    const float* gru_Whh_b    = (const float*)d_in[12];
    const float* gru_bih_b    = (const float*)d_in[13];
    const float* gru_bhh_b    = (const float*)d_in[14];
    const float* sa_Wq        = (const float*)d_in[15];
    const float* sa_bq        = (const float*)d_in[16];
    const float* sa_Wk        = (const float*)d_in[17];
    const float* sa_bk        = (const float*)d_in[18];
    const float* sa_Wv        = (const float*)d_in[19];
    const float* sa_bv        = (const float*)d_in[20];
    const float* sa_gamma     = (const float*)d_in[21];
    const float* gen_Wih      = (const float*)d_in[22];
    const float* gen_bih      = (const float*)d_in[23];
    const float* gen_Whh      = (const float*)d_in[24];
    const float* gen_bhh      = (const float*)d_in[25];
    const float* gen_Wbih     = (const float*)d_in[26];
    const float* gen_bbih     = (const float*)d_in[27];
    const float* gen_Wbhh     = (const float*)d_in[28];
    const float* gen_bbhh     = (const float*)d_in[29];
    const float* W_txt_fc     = (const float*)d_in[30];
    const float* b_txt_fc     = (const float*)d_in[31];

    float* S = nullptr;
    cudaGetSymbolAddress((void**)&S, g_scratch);

    init_k<<<4096, 256>>>();

    // GRU input projections gi = cap_embed @ Wih^T + bih, layout (T,B,3072)
    gemm_k<1><<<dim3(48, 32, 1), 256>>>(cap_embed, gru_Wih_f, gru_bih_f, nullptr,
                                        S + O_GI_F, 2048, 3072, 300, 300, 0, 0, 0, 0);
    gemm_k<1><<<dim3(48, 32, 1), 256>>>(cap_embed, gru_Wih_b, gru_bih_b, nullptr,
                                        S + O_GI_B, 2048, 3072, 300, 300, 0, 0, 0, 0);
    // cap_reduced (B,T,128)
    gemm_k<0><<<dim3(2, 32, 1), 256>>>(cap_embed, W_reduce_txt, b_reduce_txt, nullptr,
                                       S + O_CR, 2048, 128, 300, 300, 0, 0, 0, 0);
    // image global pooling + normalized copy
    img_pool_k<<<64, 256>>>(img_embed);
    // img_global_vec = img_embed_global @ W_reduce_img^T + b
    gemm_k<0><<<dim3(2, 1, 1), 256>>>(S + O_IEG, W_reduce_img, b_reduce_img, nullptr,
                                      S + O_IGV, 64, 128, 1024, 1024, 0, 0, 0, 0);

    // bidirectional GRU: 32 steps, both directions per launch
    for (int t = 0; t < 32; t++)
        gru_step_k<<<dim3(64, 2, 1), 256>>>(t, gru_Whh_f, gru_bhh_f, gru_Whh_b, gru_bhh_b);
    combine_k<<<8192, 256>>>();

    // self-attention projections
    gemm_k<0><<<dim3(2, 32, 1), 256>>>(S + O_TXT, sa_Wq, sa_bq, nullptr,
                                       S + O_Q, 2048, 128, 1024, 1024, 0, 0, 0, 0);
    gemm_k<0><<<dim3(2, 32, 1), 256>>>(S + O_TXT, sa_Wk, sa_bk, nullptr,
                                       S + O_K, 2048, 128, 1024, 1024, 0, 0, 0, 0);
    gemm_k<0><<<dim3(16, 32, 1), 256>>>(S + O_TXT, sa_Wv, sa_bv, nullptr,
                                        S + O_V, 2048, 1024, 1024, 1024, 0, 0, 0, 0);
    attn_k<<<256, 256>>>();
    aw_k<<<64, 32>>>(lens);
    txt_embed_k<<<dim3(4, 64), 256>>>(lens, sa_gamma);

    // generated GRU weights per image
    gemm_k<0><<<dim3(768, 1, 1), 256>>>(S + O_IGV, gen_Wih, gen_bih, nullptr,
                                        S + O_WIH, 64, 49152, 128, 128, 0, 0, 0, 0);
    gemm_k<0><<<dim3(768, 1, 1), 256>>>(S + O_IGV, gen_Whh, gen_bhh, nullptr,
                                        S + O_WHH, 64, 49152, 128, 128, 0, 0, 0, 0);
    gemm_k<0><<<dim3(6, 1, 1), 256>>>(S + O_IGV, gen_Wbih, gen_bbih, nullptr,
                                      S + O_BIH, 64, 384, 128, 128, 0, 0, 0, 0);
    gemm_k<0><<<dim3(6, 1, 1), 256>>>(S + O_IGV, gen_Wbhh, gen_bbhh, nullptr,
                                      S + O_BHH, 64, 384, 128, 128, 0, 0, 0, 0);
    // gi_gen: batched over 64 images, gi = cap_reduced @ Wih_g^T + bih_g, (T,B,384)
    gemm_k<2><<<dim3(6, 32, 64), 256>>>(S + O_CR, S + O_WIH, S + O_BIH, nullptr,
                                        S + O_GIG, 2048, 384, 128, 128,
                                        0, 49152, 384, 786432);
    // generated GRU: 32 steps, all 64 images per launch, running max fused
    for (int t = 0; t < 32; t++)
        gen_step_k<<<dim3(4, 64, 1), 256>>>(t);

    // final FC: shared part (txt_embed) + per-image correction (hmax)
    gemm_k<0><<<dim3(16, 1, 1), 256>>>(S + O_TE, W_txt_fc, b_txt_fc, nullptr,
                                       S + O_FCB, 64, 1024, 1024, 1152, 0, 0, 0, 0);
    gemm_k<0><<<dim3(16, 1, 64), 256>>>(S + O_HMAX, W_txt_fc + 1024, nullptr, S + O_FCB,
                                        S + O_Y, 64, 1024, 128, 1152,
                                        64L * 128, 0, 0, 64L * 1024);

    sims_k<<<dim3(64, 64), 256>>>((float*)d_out);
}

// round 4
// speedup vs baseline: 1.5697x; 1.5697x over previous
#include <cuda_runtime.h>
#include <cuda_bf16.h>
#include <math.h>

// ---------------------------------------------------------------------------
// Problem constants:  L=1024, R=128, T=32, B=64, DIN=300, REG=36, R3=384, H3=3072
// ---------------------------------------------------------------------------

// ---------------- scratch layout (floats) ----------------
#define SZ_GI      (32L*64*3072)
#define SZ_HS      (64L*32*1024)
#define SZ_HST     (2L*2*64*1024)
#define SZ_CR      (2048L*128)
#define SZ_QK      (2048L*128)
#define SZ_V       (2048L*1024)
#define SZ_ATT     (2048L*32)
#define SZ_AW      (64L*32)
#define SZ_TE      (64L*1024)
#define SZ_IEG     (64L*1024)
#define SZ_IVN     (64L*1024)
#define SZ_IGV     (64L*128)
#define SZ_WG      (64L*49152)
#define SZ_BG      (64L*384)
#define SZ_GIG     (64L*2048*384)
#define SZ_HG      (2L*64*64*128)
#define SZ_HMAX    (64L*64*128)
#define SZ_FCB     (64L*1024)
#define SZ_Y       (64L*64*1024)

#define O_GI_F  0L
#define O_GI_B  (O_GI_F + SZ_GI)
#define O_HSF   (O_GI_B + SZ_GI)
#define O_HSB   (O_HSF + SZ_HS)
#define O_TXT   (O_HSB + SZ_HS)
#define O_HST   (O_TXT + SZ_HS)
#define O_CR    (O_HST + SZ_HST)
#define O_Q     (O_CR + SZ_CR)
#define O_K     (O_Q + SZ_QK)
#define O_V     (O_K + SZ_QK)
#define O_ATT   (O_V + SZ_V)
#define O_AW    (O_ATT + SZ_ATT)
#define O_TE    (O_AW + SZ_AW)
#define O_IEG   (O_TE + SZ_TE)
#define O_IVN   (O_IEG + SZ_IEG)
#define O_IGV   (O_IVN + SZ_IVN)
#define O_WIH   (O_IGV + SZ_IGV)
#define O_WHH   (O_WIH + SZ_WG)
#define O_BIH   (O_WHH + SZ_WG)
#define O_BHH   (O_BIH + SZ_BG)
#define O_GIG   (O_BHH + SZ_BG)
#define O_HG    (O_GIG + SZ_GIG)
#define O_HMAX  (O_HG + SZ_HG)
#define O_FCB   (O_HMAX + SZ_HMAX)
#define O_Y     (O_FCB + SZ_FCB)
#define SCRATCH_TOTAL (O_Y + SZ_Y)

__device__ float g_scratch[SCRATCH_TOTAL];

__device__ __forceinline__ float sigf(float x) { return 1.f / (1.f + expf(-x)); }

// ---------------------------------------------------------------------------
__global__ __launch_bounds__(256) void init_k() {
    long idx = (long)blockIdx.x * 256 + threadIdx.x;
    if (idx < SZ_HST)  g_scratch[O_HST + idx] = 0.f;
    if (idx < SZ_HG)   g_scratch[O_HG + idx] = 0.f;
    if (idx < SZ_HMAX) g_scratch[O_HMAX + idx] = -1e30f;
}

// ---------------------------------------------------------------------------
// A indexing modes (shared by both GEMM kernels)
//   0: A[m*K + k]
//   1: m=t*64+b over cap_embed (B,T,300):  A[(m&63)*9600 + (m>>6)*300 + k]
//   2: m=t*64+b over cap_reduced (B,T,128): A[((m&63)*32 + (m>>6))*128 + k]
// ---------------------------------------------------------------------------
template <int MODE>
__device__ __forceinline__ long a_idx(int m, int k, int K) {
    if (MODE == 0) return (long)m * K + k;
    if (MODE == 1) { int b = m & 63, t = m >> 6; return (long)b * 9600 + (long)t * 300 + k; }
    { int b = m & 63, t = m >> 6; return ((long)(b * 32 + t)) * 128 + k; }
}

// ---------------------------------------------------------------------------
// Small-tile SGEMM (64x64, 4x4/thread) -- kept for small/narrow shapes.
// ---------------------------------------------------------------------------
template <int MODE>
__global__ __launch_bounds__(256) void gemm_k(
    const float* __restrict__ A, const float* __restrict__ W,
    const float* __restrict__ bias, const float* __restrict__ Cadd,
    float* __restrict__ C,
    int M, int N, int K, int ldw,
    long aBS, long wBS, long bBS, long cBS)
{
    int bz = blockIdx.z;
    A += (long)bz * aBS;
    W += (long)bz * wBS;
    C += (long)bz * cBS;
    const float* biasp = bias ? (bias + (long)bz * bBS) : nullptr;

    __shared__ float As[16][65];
    __shared__ float Bs[16][65];
    int tid = threadIdx.x;
    int tx = tid & 15, ty = tid >> 4;
    int m0 = blockIdx.y * 64, n0 = blockIdx.x * 64;

    float acc[4][4];
#pragma unroll
    for (int i = 0; i < 4; i++)
#pragma unroll
        for (int j = 0; j < 4; j++) acc[i][j] = 0.f;

    for (int k0 = 0; k0 < K; k0 += 16) {
#pragma unroll
        for (int r = 0; r < 4; r++) {
            int i = tid + r * 256;
            int mm = i >> 4, kk = i & 15;
            int m = m0 + mm, k = k0 + kk;
            As[kk][mm] = (m < M && k < K) ? A[a_idx<MODE>(m, k, K)] : 0.f;
        }
#pragma unroll
        for (int r = 0; r < 4; r++) {
            int i = tid + r * 256;
            int nn = i >> 4, kk = i & 15;
            int n = n0 + nn, k = k0 + kk;
            Bs[kk][nn] = (n < N && k < K) ? W[(long)n * ldw + k] : 0.f;
        }
        __syncthreads();
#pragma unroll
        for (int kk = 0; kk < 16; kk++) {
            float av[4], bv[4];
#pragma unroll
            for (int i = 0; i < 4; i++) av[i] = As[kk][ty * 4 + i];
#pragma unroll
            for (int j = 0; j < 4; j++) bv[j] = Bs[kk][tx * 4 + j];
#pragma unroll
            for (int i = 0; i < 4; i++)
#pragma unroll
                for (int j = 0; j < 4; j++) acc[i][j] += av[i] * bv[j];
        }
        __syncthreads();
    }

#pragma unroll
    for (int i = 0; i < 4; i++) {
        int m = m0 + ty * 4 + i;
        if (m >= M) continue;
#pragma unroll
        for (int j = 0; j < 4; j++) {
            int n = n0 + tx * 4 + j;
            if (n >= N) continue;
            float v = acc[i][j];
            if (biasp) v += biasp[n];
            if (Cadd) v += Cadd[(long)m * N + n];
            C[(long)m * N + n] = v;
        }
    }
}

// ---------------------------------------------------------------------------
// Big-tile SGEMM: 128x128 block tile, 8x8 per-thread, float4 staging.
// Requires K % 4 == 0 and 16B-aligned rows (all our shapes satisfy this).
// FFMA-bound: per kk, 4 LDS.128 + 64 FFMA per thread.
// ---------------------------------------------------------------------------
template <int MODE>
__global__ __launch_bounds__(256) void gemm_big(
    const float* __restrict__ A, const float* __restrict__ W,
    const float* __restrict__ bias, const float* __restrict__ Cadd,
    float* __restrict__ C,
    int M, int N, int K, int ldw,
    long aBS, long wBS, long bBS, long cBS)
{
    int bz = blockIdx.z;
    A += (long)bz * aBS;
    W += (long)bz * wBS;
    C += (long)bz * cBS;
    const float* biasp = bias ? (bias + (long)bz * bBS) : nullptr;

    __shared__ float As[16][132];
    __shared__ float Bs[16][132];
    int tid = threadIdx.x;
    int tx = tid & 15, ty = tid >> 4;
    int m0 = blockIdx.y * 128, n0 = blockIdx.x * 128;

    float acc[8][8];
#pragma unroll
    for (int i = 0; i < 8; i++)
#pragma unroll
        for (int j = 0; j < 8; j++) acc[i][j] = 0.f;

    for (int k0 = 0; k0 < K; k0 += 16) {
        // A tile: 128 rows x 16 k = 512 float4; 2 per thread
#pragma unroll
        for (int r = 0; r < 2; r++) {
            int idx = tid + r * 256;
            int mm = idx >> 2, k4 = idx & 3;
            int m = m0 + mm, k = k0 + k4 * 4;
            float4 v = make_float4(0.f, 0.f, 0.f, 0.f);
            if (m < M && k < K)
                v = *reinterpret_cast<const float4*>(&A[a_idx<MODE>(m, k, K)]);
            As[k4 * 4 + 0][mm] = v.x;
            As[k4 * 4 + 1][mm] = v.y;
            As[k4 * 4 + 2][mm] = v.z;
            As[k4 * 4 + 3][mm] = v.w;
        }
        // B tile: 128 rows x 16 k
#pragma unroll
        for (int r = 0; r < 2; r++) {
            int idx = tid + r * 256;
            int nn = idx >> 2, k4 = idx & 3;
            int n = n0 + nn, k = k0 + k4 * 4;
            float4 v = make_float4(0.f, 0.f, 0.f, 0.f);
            if (n < N && k < K)
                v = *reinterpret_cast<const float4*>(&W[(long)n * ldw + k]);
            Bs[k4 * 4 + 0][nn] = v.x;
            Bs[k4 * 4 + 1][nn] = v.y;
            Bs[k4 * 4 + 2][nn] = v.z;
            Bs[k4 * 4 + 3][nn] = v.w;
        }
        __syncthreads();
#pragma unroll
        for (int kk = 0; kk < 16; kk++) {
            float4 a0 = *reinterpret_cast<const float4*>(&As[kk][ty * 8]);
            float4 a1 = *reinterpret_cast<const float4*>(&As[kk][ty * 8 + 4]);
            float4 b0 = *reinterpret_cast<const float4*>(&Bs[kk][tx * 8]);
            float4 b1 = *reinterpret_cast<const float4*>(&Bs[kk][tx * 8 + 4]);
            float av[8] = {a0.x, a0.y, a0.z, a0.w, a1.x, a1.y, a1.z, a1.w};
            float bv[8] = {b0.x, b0.y, b0.z, b0.w, b1.x, b1.y, b1.z, b1.w};
#pragma unroll
            for (int i = 0; i < 8; i++)
#pragma unroll
                for (int j = 0; j < 8; j++) acc[i][j] += av[i] * bv[j];
        }
        __syncthreads();
    }

#pragma unroll
    for (int i = 0; i < 8; i++) {
        int m = m0 + ty * 8 + i;
        if (m >= M) continue;
#pragma unroll
        for (int j = 0; j < 8; j++) {
            int n = n0 + tx * 8 + j;
            if (n >= N) continue;
            float v = acc[i][j];
            if (biasp) v += biasp[n];
            if (Cadd) v += Cadd[(long)m * N + n];
            C[(long)m * N + n] = v;
        }
    }
}

// ---------------------------------------------------------------------------
// Combined recurrent step: one launch per t.
//   blocks [0,128):   main bi-GRU. dir = bx>>6, 16 h-cols per block.
//   blocks [128,384): generated GRU. img = (bx-128)>>2, 32 h-cols per block.
// 128 threads. Vectorized LDS.128 inner loops, gate fusion in epilogue.
// ---------------------------------------------------------------------------
__global__ __launch_bounds__(128) void step_k(
    int t,
    const float* __restrict__ Whh_f, const float* __restrict__ bhh_f,
    const float* __restrict__ Whh_b, const float* __restrict__ bhh_b)
{
    __shared__ float As[32][64];
    __shared__ float Bs[32][128];
    int tid = threadIdx.x;

    if (blockIdx.x < 128) {
        // ---------------- main bi-GRU ----------------
        int bx = blockIdx.x;
        int dir = bx >> 6;
        int j0 = (bx & 63) * 16;
        const float* Whh = dir ? Whh_b : Whh_f;
        const float* bhh = dir ? bhh_b : bhh_f;
        const float* gi  = g_scratch + (dir ? O_GI_B : O_GI_F);
        float* hs        = g_scratch + (dir ? O_HSB : O_HSF);
        float* hbase     = g_scratch + O_HST + (long)dir * 131072;
        const float* hin = hbase + (long)(t & 1) * 65536;
        float* hout      = hbase + (long)((t + 1) & 1) * 65536;
        int tt = dir ? (31 - t) : t;

        int tx = tid & 15, ty = tid >> 4;  // tx: j col, ty: 8-row group

        float acc[3][8];
#pragma unroll
        for (int g = 0; g < 3; g++)
#pragma unroll
            for (int i = 0; i < 8; i++) acc[g][i] = 0.f;

        for (int k0 = 0; k0 < 1024; k0 += 32) {
            // h tile: 64 m x 32 kk = 512 f4, 4 per thread
#pragma unroll
            for (int r = 0; r < 4; r++) {
                int idx = tid + r * 128;
                int mm = idx >> 3, k4 = idx & 7;
                float4 v = *reinterpret_cast<const float4*>(&hin[mm * 1024 + k0 + k4 * 4]);
                As[k4 * 4 + 0][mm] = v.x;
                As[k4 * 4 + 1][mm] = v.y;
                As[k4 * 4 + 2][mm] = v.z;
                As[k4 * 4 + 3][mm] = v.w;
            }
            // W tile: 48 rows (3g x 16j) x 32 kk = 384 f4, 3 per thread
#pragma unroll
            for (int r = 0; r < 3; r++) {
                int idx = tid + r * 128;
                int row = idx >> 3, k4 = idx & 7;
                int g = row >> 4, j = row & 15;
                float4 v = *reinterpret_cast<const float4*>(
                    &Whh[(long)(g * 1024 + j0 + j) * 1024 + k0 + k4 * 4]);
                Bs[k4 * 4 + 0][j * 4 + g] = v.x;
                Bs[k4 * 4 + 1][j * 4 + g] = v.y;
                Bs[k4 * 4 + 2][j * 4 + g] = v.z;
                Bs[k4 * 4 + 3][j * 4 + g] = v.w;
            }
            __syncthreads();
#pragma unroll
            for (int kk = 0; kk < 32; kk++) {
                float4 a0 = *reinterpret_cast<const float4*>(&As[kk][ty * 8]);
                float4 a1 = *reinterpret_cast<const float4*>(&As[kk][ty * 8 + 4]);
                float4 b  = *reinterpret_cast<const float4*>(&Bs[kk][tx * 4]);
                float av[8] = {a0.x, a0.y, a0.z, a0.w, a1.x, a1.y, a1.z, a1.w};
#pragma unroll
                for (int i = 0; i < 8; i++) {
                    acc[0][i] += av[i] * b.x;
                    acc[1][i] += av[i] * b.y;
                    acc[2][i] += av[i] * b.z;
                }
            }
            __syncthreads();
        }

        int col = j0 + tx;
        float br = bhh[col], bz = bhh[1024 + col], bn = bhh[2048 + col];
#pragma unroll
        for (int i = 0; i < 8; i++) {
            int m = ty * 8 + i;
            const float* girow = gi + ((long)tt * 64 + m) * 3072;
            float r = sigf(girow[col] + acc[0][i] + br);
            float z = sigf(girow[1024 + col] + acc[1][i] + bz);
            float n = tanhf(girow[2048 + col] + r * (acc[2][i] + bn));
            float hold = hin[m * 1024 + col];
            float hn = (1.f - z) * n + z * hold;
            hout[m * 1024 + col] = hn;
            hs[(long)m * 32768 + (long)tt * 1024 + col] = hn;
        }
    } else {
        // ---------------- generated-weight GRU ----------------
        int b2 = blockIdx.x - 128;
        int img = b2 >> 2;
        int j0 = (b2 & 3) * 32;
        const float* Whh = g_scratch + O_WHH + (long)img * 49152;
        const float* bhh = g_scratch + O_BHH + (long)img * 384;
        const float* gi  = g_scratch + O_GIG + (long)img * 786432 + (long)t * 64 * 384;
        float* hb = g_scratch + O_HG;
        const float* hin = hb + (long)(t & 1) * 524288 + (long)img * 8192;
        float* hout      = hb + (long)((t + 1) & 1) * 524288 + (long)img * 8192;
        float* hmax = g_scratch + O_HMAX + (long)img * 8192;

        int tx = tid & 31, ty = tid >> 5;  // tx: j col, ty: 16-row group

        float acc[3][16];
#pragma unroll
        for (int g = 0; g < 3; g++)
#pragma unroll
            for (int i = 0; i < 16; i++) acc[g][i] = 0.f;

        for (int k0 = 0; k0 < 128; k0 += 32) {
            // h tile: 64 m x 32 kk = 512 f4, 4 per thread
#pragma unroll
            for (int r = 0; r < 4; r++) {
                int idx = tid + r * 128;
                int mm = idx >> 3, k4 = idx & 7;
                float4 v = *reinterpret_cast<const float4*>(&hin[mm * 128 + k0 + k4 * 4]);
                As[k4 * 4 + 0][mm] = v.x;
                As[k4 * 4 + 1][mm] = v.y;
                As[k4 * 4 + 2][mm] = v.z;
                As[k4 * 4 + 3][mm] = v.w;
            }
            // W tile: 96 rows (3g x 32j) x 32 kk = 768 f4, 6 per thread
#pragma unroll
            for (int r = 0; r < 6; r++) {
                int idx = tid + r * 128;
                int row = idx >> 3, k4 = idx & 7;
                int g = row >> 5, j = row & 31;
                float4 v = *reinterpret_cast<const float4*>(
                    &Whh[(long)(g * 128 + j0 + j) * 128 + k0 + k4 * 4]);
                Bs[k4 * 4 + 0][j * 4 + g] = v.x;
                Bs[k4 * 4 + 1][j * 4 + g] = v.y;
                Bs[k4 * 4 + 2][j * 4 + g] = v.z;
                Bs[k4 * 4 + 3][j * 4 + g] = v.w;
            }
            __syncthreads();
#pragma unroll
            for (int kk = 0; kk < 32; kk++) {
                float4 a0 = *reinterpret_cast<const float4*>(&As[kk][ty * 16]);
                float4 a1 = *reinterpret_cast<const float4*>(&As[kk][ty * 16 + 4]);
                float4 a2 = *reinterpret_cast<const float4*>(&As[kk][ty * 16 + 8]);
                float4 a3 = *reinterpret_cast<const float4*>(&As[kk][ty * 16 + 12]);
                float4 b  = *reinterpret_cast<const float4*>(&Bs[kk][tx * 4]);
                float av[16] = {a0.x, a0.y, a0.z, a0.w, a1.x, a1.y, a1.z, a1.w,
                                a2.x, a2.y, a2.z, a2.w, a3.x, a3.y, a3.z, a3.w};
#pragma unroll
                for (int i = 0; i < 16; i++) {
                    acc[0][i] += av[i] * b.x;
                    acc[1][i] += av[i] * b.y;
                    acc[2][i] += av[i] * b.z;
                }
            }
            __syncthreads();
        }

        int col = j0 + tx;
        float br = bhh[col], bz = bhh[128 + col], bn = bhh[256 + col];
#pragma unroll
        for (int i = 0; i < 16; i++) {
            int m = ty * 16 + i;
            const float* girow = gi + m * 384;
            float r = sigf(girow[col] + acc[0][i] + br);
            float z = sigf(girow[128 + col] + acc[1][i] + bz);
            float n = tanhf(girow[256 + col] + r * (acc[2][i] + bn));
            float hold = hin[m * 128 + col];
            float hn = (1.f - z) * n + z * hold;
            hout[m * 128 + col] = hn;
            hmax[m * 128 + col] = fmaxf(hmax[m * 128 + col], hn);
        }
    }
}

// txt = 0.5*(hsf + hsb)
__global__ __launch_bounds__(256) void combine_k() {
    long i = (long)blockIdx.x * 256 + threadIdx.x;
    if (i < SZ_HS)
        g_scratch[O_TXT + i] = 0.5f * (g_scratch[O_HSF + i] + g_scratch[O_HSB + i]);
}

// ---------------------------------------------------------------------------
__global__ __launch_bounds__(256) void img_pool_k(const float* __restrict__ img_embed) {
    int b = blockIdx.x, tid = threadIdx.x;
    float vals[4], ss = 0.f;
#pragma unroll
    for (int i = 0; i < 4; i++) {
        int c = i * 256 + tid;
        float s = 0.f;
        for (int g = 0; g < 36; g++) s += img_embed[(long)b * 36864 + (long)g * 1024 + c];
        s *= (1.f / 36.f);
        vals[i] = s;
        ss += s * s;
        g_scratch[O_IEG + (long)b * 1024 + c] = s;
    }
    __shared__ float red[256];
    red[tid] = ss;
    __syncthreads();
    for (int o = 128; o > 0; o >>= 1) { if (tid < o) red[tid] += red[tid + o]; __syncthreads(); }
    float inv = 1.f / (sqrtf(red[0]) + 1e-8f);
#pragma unroll
    for (int i = 0; i < 4; i++) {
        int c = i * 256 + tid;
        g_scratch[O_IVN + (long)b * 1024 + c] = vals[i] * inv;
    }
}

// attention scores + softmax: one warp per (b,t)
__global__ __launch_bounds__(256) void attn_k() {
    int gw = (blockIdx.x * blockDim.x + threadIdx.x) >> 5;
    int lane = threadIdx.x & 31;
    if (gw >= 2048) return;
    int b = gw >> 5;
    const float* qr = g_scratch + O_Q + (long)gw * 128;
    const float* kr = g_scratch + O_K + ((long)b * 32 + lane) * 128;
    float s = 0.f;
#pragma unroll 8
    for (int o = 0; o < 128; o++) s += qr[o] * kr[o];
    float mx = s;
#pragma unroll
    for (int off = 16; off > 0; off >>= 1) mx = fmaxf(mx, __shfl_xor_sync(0xffffffffu, mx, off));
    float e = expf(s - mx);
    float sum = e;
#pragma unroll
    for (int off = 16; off > 0; off >>= 1) sum += __shfl_xor_sync(0xffffffffu, sum, off);
    g_scratch[O_ATT + (long)gw * 32 + lane] = e / sum;
}

__global__ __launch_bounds__(32) void aw_k(const int* __restrict__ lens) {
    int b = blockIdx.x, s = threadIdx.x;
    int len = lens[b];
    float a = 0.f;
    for (int tt = 0; tt < len; tt++) a += g_scratch[O_ATT + ((long)b * 32 + tt) * 32 + s];
    g_scratch[O_AW + b * 32 + s] = a;
}

__global__ __launch_bounds__(256) void txt_embed_k(const int* __restrict__ lens,
                                                   const float* __restrict__ gamma) {
    int b = blockIdx.y;
    int c = blockIdx.x * 256 + threadIdx.x;
    __shared__ float saw[32];
    if (threadIdx.x < 32) saw[threadIdx.x] = g_scratch[O_AW + b * 32 + threadIdx.x];
    __syncthreads();
    int len = lens[b];
    float g = *gamma;
    float a1 = 0.f;
    for (int tt = 0; tt < len; tt++) a1 += g_scratch[O_TXT + ((long)b * 32 + tt) * 1024 + c];
    float a2 = 0.f;
#pragma unroll
    for (int s = 0; s < 32; s++) a2 += saw[s] * g_scratch[O_V + ((long)b * 32 + s) * 1024 + c];
    g_scratch[O_TE + (long)b * 1024 + c] = (a1 + g * a2) / (float)len;
}

// sims[i,b] = (y . iv_i) / (|y| + eps)
__global__ __launch_bounds__(256) void sims_k(float* __restrict__ out) {
    int img = blockIdx.y, b = blockIdx.x;
    int tid = threadIdx.x;
    const float* y = g_scratch + O_Y + (long)img * 65536 + (long)b * 1024;
    const float* iv = g_scratch + O_IVN + (long)img * 1024;
    float ss = 0.f, dp = 0.f;
#pragma unroll
    for (int i = 0; i < 4; i++) {
        int c = i * 256 + tid;
        float v = y[c];
        ss += v * v;
        dp += v * iv[c];
    }
    __shared__ float r1[256], r2[256];
    r1[tid] = ss; r2[tid] = dp;
    __syncthreads();
    for (int o = 128; o > 0; o >>= 1) {
        if (tid < o) { r1[tid] += r1[tid + o]; r2[tid] += r2[tid + o]; }
        __syncthreads();
    }
    if (tid == 0) out[img * 64 + b] = r2[0] / (sqrtf(r1[0]) + 1e-8f);
}

// ---------------------------------------------------------------------------
extern "C" void kernel_launch(void* const* d_in, const int* in_sizes, int n_in,
                              void* d_out, int out_size) {
    const float* img_embed    = (const float*)d_in[0];
    const float* cap_embed    = (const float*)d_in[1];
    const int*   lens         = (const int*)d_in[2];
    const float* W_reduce_img = (const float*)d_in[3];
    const float* b_reduce_img = (const float*)d_in[4];
    const float* W_reduce_txt = (const float*)d_in[5];
    const float* b_reduce_txt = (const float*)d_in[6];
    const float* gru_Wih_f    = (const float*)d_in[7];
    const float* gru_Whh_f    = (const float*)d_in[8];
    const float* gru_bih_f    = (const float*)d_in[9];
    const float* gru_bhh_f    = (const float*)d_in[10];
    const float* gru_Wih_b    = (const float*)d_in[11];
    const float* gru_Whh_b    = (const float*)d_in[12];
    const float* gru_bih_b    = (const float*)d_in[13];
    const float* gru_bhh_b    = (const float*)d_in[14];
    const float* sa_Wq        = (const float*)d_in[15];
    const float* sa_bq        = (const float*)d_in[16];
    const float* sa_Wk        = (const float*)d_in[17];
    const float* sa_bk        = (const float*)d_in[18];
    const float* sa_Wv        = (const float*)d_in[19];
    const float* sa_bv        = (const float*)d_in[20];
    const float* sa_gamma     = (const float*)d_in[21];
    const float* gen_Wih      = (const float*)d_in[22];
    const float* gen_bih      = (const float*)d_in[23];
    const float* gen_Whh      = (const float*)d_in[24];
    const float* gen_bhh      = (const float*)d_in[25];
    const float* gen_Wbih     = (const float*)d_in[26];
    const float* gen_bbih     = (const float*)d_in[27];
    const float* gen_Wbhh     = (const float*)d_in[28];
    const float* gen_bbhh     = (const float*)d_in[29];
    const float* W_txt_fc     = (const float*)d_in[30];
    const float* b_txt_fc     = (const float*)d_in[31];

    float* S = nullptr;
    cudaGetSymbolAddress((void**)&S, g_scratch);

    init_k<<<4096, 256>>>();

    // GRU input projections gi = cap_embed @ Wih^T + bih, layout (T,B,3072)
    gemm_big<1><<<dim3(24, 16, 1), 256>>>(cap_embed, gru_Wih_f, gru_bih_f, nullptr,
                                          S + O_GI_F, 2048, 3072, 300, 300, 0, 0, 0, 0);
    gemm_big<1><<<dim3(24, 16, 1), 256>>>(cap_embed, gru_Wih_b, gru_bih_b, nullptr,
                                          S + O_GI_B, 2048, 3072, 300, 300, 0, 0, 0, 0);
    // cap_reduced (B,T,128)
    gemm_k<0><<<dim3(2, 32, 1), 256>>>(cap_embed, W_reduce_txt, b_reduce_txt, nullptr,
                                       S + O_CR, 2048, 128, 300, 300, 0, 0, 0, 0);
    // image global pooling + normalized copy
    img_pool_k<<<64, 256>>>(img_embed);
    // img_global_vec
    gemm_k<0><<<dim3(2, 1, 1), 256>>>(S + O_IEG, W_reduce_img, b_reduce_img, nullptr,
                                      S + O_IGV, 64, 128, 1024, 1024, 0, 0, 0, 0);

    // generated GRU weights per image (big-N GEMMs)
    gemm_big<0><<<dim3(384, 1, 1), 256>>>(S + O_IGV, gen_Wih, gen_bih, nullptr,
                                          S + O_WIH, 64, 49152, 128, 128, 0, 0, 0, 0);
    gemm_big<0><<<dim3(384, 1, 1), 256>>>(S + O_IGV, gen_Whh, gen_bhh, nullptr,
                                          S + O_WHH, 64, 49152, 128, 128, 0, 0, 0, 0);
    gemm_k<0><<<dim3(6, 1, 1), 256>>>(S + O_IGV, gen_Wbih, gen_bbih, nullptr,
                                      S + O_BIH, 64, 384, 128, 128, 0, 0, 0, 0);
    gemm_k<0><<<dim3(6, 1, 1), 256>>>(S + O_IGV, gen_Wbhh, gen_bbhh, nullptr,
                                      S + O_BHH, 64, 384, 128, 128, 0, 0, 0, 0);
    // gi_gen: batched over 64 images, (T,B,384)
    gemm_big<2><<<dim3(3, 16, 64), 256>>>(S + O_CR, S + O_WIH, S + O_BIH, nullptr,
                                          S + O_GIG, 2048, 384, 128, 128,
                                          0, 49152, 384, 786432);

    // 32 combined recurrent steps (main bi-GRU + generated GRU in one launch)
    for (int t = 0; t < 32; t++)
        step_k<<<384, 128>>>(t, gru_Whh_f, gru_bhh_f, gru_Whh_b, gru_bhh_b);
    combine_k<<<8192, 256>>>();

    // self-attention projections
    gemm_k<0><<<dim3(2, 32, 1), 256>>>(S + O_TXT, sa_Wq, sa_bq, nullptr,
                                       S + O_Q, 2048, 128, 1024, 1024, 0, 0, 0, 0);
    gemm_k<0><<<dim3(2, 32, 1), 256>>>(S + O_TXT, sa_Wk, sa_bk, nullptr,
                                       S + O_K, 2048, 128, 1024, 1024, 0, 0, 0, 0);
    gemm_big<0><<<dim3(8, 16, 1), 256>>>(S + O_TXT, sa_Wv, sa_bv, nullptr,
                                         S + O_V, 2048, 1024, 1024, 1024, 0, 0, 0, 0);
    attn_k<<<256, 256>>>();
    aw_k<<<64, 32>>>(lens);
    txt_embed_k<<<dim3(4, 64), 256>>>(lens, sa_gamma);

    // final FC: shared part + per-image correction
    gemm_k<0><<<dim3(16, 1, 1), 256>>>(S + O_TE, W_txt_fc, b_txt_fc, nullptr,
                                       S + O_FCB, 64, 1024, 1024, 1152, 0, 0, 0, 0);
    gemm_big<0><<<dim3(8, 1, 64), 256>>>(S + O_HMAX, W_txt_fc + 1024, nullptr, S + O_FCB,
                                         S + O_Y, 64, 1024, 128, 1152,
                                         64L * 128, 0, 0, 64L * 1024);

    sims_k<<<dim3(64, 64), 256>>>((float*)d_out);
}

// round 5
// speedup vs baseline: 1.8778x; 1.1962x over previous
#include <cuda_runtime.h>
#include <cuda_bf16.h>
#include <math.h>
#include <stdint.h>

// ---------------------------------------------------------------------------
// Problem constants:  L=1024, R=128, T=32, B=64, DIN=300, REG=36, R3=384, H3=3072
// ---------------------------------------------------------------------------

// ---------------- scratch layout (floats) ----------------
#define SZ_GI      (32L*64*3072)
#define SZ_HS      (64L*32*1024)
#define SZ_HST     (2L*2*64*1024)
#define SZ_CR      (2048L*128)
#define SZ_QK      (2048L*128)
#define SZ_V       (2048L*1024)
#define SZ_ATT     (2048L*32)
#define SZ_AW      (64L*32)
#define SZ_TE      (64L*1024)
#define SZ_IEG     (64L*1024)
#define SZ_IVN     (64L*1024)
#define SZ_IGV     (64L*128)
#define SZ_WG      (64L*49152)
#define SZ_BG      (64L*384)
#define SZ_GIG     (64L*2048*384)
#define SZ_HG      (2L*64*64*128)
#define SZ_HMAX    (64L*64*128)
#define SZ_FCB     (64L*1024)
#define SZ_Y       (64L*64*1024)

#define O_GI_F  0L
#define O_GI_B  (O_GI_F + SZ_GI)
#define O_HSF   (O_GI_B + SZ_GI)
#define O_HSB   (O_HSF + SZ_HS)
#define O_TXT   (O_HSB + SZ_HS)
#define O_HST   (O_TXT + SZ_HS)
#define O_CR    (O_HST + SZ_HST)
#define O_Q     (O_CR + SZ_CR)
#define O_K     (O_Q + SZ_QK)
#define O_V     (O_K + SZ_QK)
#define O_ATT   (O_V + SZ_V)
#define O_AW    (O_ATT + SZ_ATT)
#define O_TE    (O_AW + SZ_AW)
#define O_IEG   (O_TE + SZ_TE)
#define O_IVN   (O_IEG + SZ_IEG)
#define O_IGV   (O_IVN + SZ_IVN)
#define O_WIH   (O_IGV + SZ_IGV)
#define O_WHH   (O_WIH + SZ_WG)
#define O_BIH   (O_WHH + SZ_WG)
#define O_BHH   (O_BIH + SZ_BG)
#define O_GIG   (O_BHH + SZ_BG)
#define O_HG    (O_GIG + SZ_GIG)
#define O_HMAX  (O_HG + SZ_HG)
#define O_FCB   (O_HMAX + SZ_HMAX)
#define O_Y     (O_FCB + SZ_FCB)
#define SCRATCH_TOTAL (O_Y + SZ_Y)

__device__ float g_scratch[SCRATCH_TOTAL];

__device__ __forceinline__ float sigf(float x) { return 1.f / (1.f + expf(-x)); }

__device__ __forceinline__ uint32_t f2tf32(float x) {
    uint32_t r;
    asm("cvt.rna.tf32.f32 %0, %1;" : "=r"(r) : "f"(x));
    return r;
}

__device__ __forceinline__ void ldsm4(uint32_t* r, uint32_t addr) {
    asm volatile("ldmatrix.sync.aligned.m8n8.x4.shared.b16 {%0,%1,%2,%3}, [%4];"
                 : "=r"(r[0]), "=r"(r[1]), "=r"(r[2]), "=r"(r[3]) : "r"(addr));
}

__device__ __forceinline__ void mma_tf32(float* c, const uint32_t* a, const uint32_t* b) {
    asm volatile(
        "mma.sync.aligned.m16n8k8.row.col.f32.tf32.tf32.f32 "
        "{%0,%1,%2,%3}, {%4,%5,%6,%7}, {%8,%9}, {%0,%1,%2,%3};"
        : "+f"(c[0]), "+f"(c[1]), "+f"(c[2]), "+f"(c[3])
        : "r"(a[0]), "r"(a[1]), "r"(a[2]), "r"(a[3]), "r"(b[0]), "r"(b[1]));
}

// ---------------------------------------------------------------------------
__global__ __launch_bounds__(256) void init_k() {
    long idx = (long)blockIdx.x * 256 + threadIdx.x;
    if (idx < SZ_HST)  g_scratch[O_HST + idx] = 0.f;
    if (idx < SZ_HG)   g_scratch[O_HG + idx] = 0.f;
    if (idx < SZ_HMAX) g_scratch[O_HMAX + idx] = -1e30f;
}

// ---------------------------------------------------------------------------
// A indexing modes:
//   0: A[m*K + k]
//   1: m=t*64+b over cap_embed (B,T,300):  A[(m&63)*9600 + (m>>6)*300 + k]
//   2: m=t*64+b over cap_reduced (B,T,128): A[((m&63)*32 + (m>>6))*128 + k]
// ---------------------------------------------------------------------------
template <int MODE>
__device__ __forceinline__ long a_idx(int m, int k, int K) {
    if (MODE == 0) return (long)m * K + k;
    if (MODE == 1) { int b = m & 63, t = m >> 6; return (long)b * 9600 + (long)t * 300 + k; }
    { int b = m & 63, t = m >> 6; return ((long)(b * 32 + t)) * 128 + k; }
}

// ---------------------------------------------------------------------------
// Small-tile SGEMM (64x64, 4x4/thread) -- for tiny shapes only.
// ---------------------------------------------------------------------------
template <int MODE>
__global__ __launch_bounds__(256) void gemm_k(
    const float* __restrict__ A, const float* __restrict__ W,
    const float* __restrict__ bias, const float* __restrict__ Cadd,
    float* __restrict__ C,
    int M, int N, int K, int ldw,
    long aBS, long wBS, long bBS, long cBS)
{
    int bz = blockIdx.z;
    A += (long)bz * aBS;
    W += (long)bz * wBS;
    C += (long)bz * cBS;
    const float* biasp = bias ? (bias + (long)bz * bBS) : nullptr;

    __shared__ float As[16][65];
    __shared__ float Bs[16][65];
    int tid = threadIdx.x;
    int tx = tid & 15, ty = tid >> 4;
    int m0 = blockIdx.y * 64, n0 = blockIdx.x * 64;

    float acc[4][4];
#pragma unroll
    for (int i = 0; i < 4; i++)
#pragma unroll
        for (int j = 0; j < 4; j++) acc[i][j] = 0.f;

    for (int k0 = 0; k0 < K; k0 += 16) {
#pragma unroll
        for (int r = 0; r < 4; r++) {
            int i = tid + r * 256;
            int mm = i >> 4, kk = i & 15;
            int m = m0 + mm, k = k0 + kk;
            As[kk][mm] = (m < M && k < K) ? A[a_idx<MODE>(m, k, K)] : 0.f;
        }
#pragma unroll
        for (int r = 0; r < 4; r++) {
            int i = tid + r * 256;
            int nn = i >> 4, kk = i & 15;
            int n = n0 + nn, k = k0 + kk;
            Bs[kk][nn] = (n < N && k < K) ? W[(long)n * ldw + k] : 0.f;
        }
        __syncthreads();
#pragma unroll
        for (int kk = 0; kk < 16; kk++) {
            float av[4], bv[4];
#pragma unroll
            for (int i = 0; i < 4; i++) av[i] = As[kk][ty * 4 + i];
#pragma unroll
            for (int j = 0; j < 4; j++) bv[j] = Bs[kk][tx * 4 + j];
#pragma unroll
            for (int i = 0; i < 4; i++)
#pragma unroll
                for (int j = 0; j < 4; j++) acc[i][j] += av[i] * bv[j];
        }
        __syncthreads();
    }

#pragma unroll
    for (int i = 0; i < 4; i++) {
        int m = m0 + ty * 4 + i;
        if (m >= M) continue;
#pragma unroll
        for (int j = 0; j < 4; j++) {
            int n = n0 + tx * 4 + j;
            if (n >= N) continue;
            float v = acc[i][j];
            if (biasp) v += biasp[n];
            if (Cadd) v += Cadd[(long)m * N + n];
            C[(long)m * N + n] = v;
        }
    }
}

// ---------------------------------------------------------------------------
// TF32 tensor-core GEMM: 128x128 tile, 8 warps (2x4), each warp 64x32 via
// m16n8k8 mma.sync. Operands converted to tf32 once at staging. SMEM rows
// padded to 36 floats for conflict-free ldmatrix.
// C[m,n] = sum_k A(m,k) * W[n*ldw+k] (+bias[n]) (+Cadd[m,n])
// Requires K % 4 == 0 (all shapes satisfy); zero-pads K to multiple of 32.
// ---------------------------------------------------------------------------
#define TRS 36   // smem row stride in floats

template <int MODE>
__global__ __launch_bounds__(256) void gemm_tf32(
    const float* __restrict__ A, const float* __restrict__ W,
    const float* __restrict__ bias, const float* __restrict__ Cadd,
    float* __restrict__ C,
    int M, int N, int K, int ldw,
    long aBS, long wBS, long bBS, long cBS)
{
    __shared__ float As[128 * TRS];
    __shared__ float Bs[128 * TRS];

    int bz = blockIdx.z;
    A += (long)bz * aBS;
    W += (long)bz * wBS;
    C += (long)bz * cBS;
    const float* biasp = bias ? (bias + (long)bz * bBS) : nullptr;

    int tid = threadIdx.x;
    int warp = tid >> 5, lane = tid & 31;
    int wr = warp >> 2, wc = warp & 3;       // warp row (0-1) x col (0-3)
    int m0 = blockIdx.y * 128, n0 = blockIdx.x * 128;

    float acc[4][4][4];
#pragma unroll
    for (int mt = 0; mt < 4; mt++)
#pragma unroll
        for (int nt = 0; nt < 4; nt++)
#pragma unroll
            for (int q = 0; q < 4; q++) acc[mt][nt][q] = 0.f;

    uint32_t as_base = (uint32_t)__cvta_generic_to_shared(As);
    uint32_t bs_base = (uint32_t)__cvta_generic_to_shared(Bs);

    // ldmatrix per-lane offsets
    int rowA = (lane & 7) + ((lane >> 3) & 1) * 8;
    int colA = (lane >> 4) * 4;
    int rowB = (lane & 7) + (lane >> 4) * 8;
    int colB = ((lane >> 3) & 1) * 4;

    for (int k0 = 0; k0 < K; k0 += 32) {
        // stage A: 128 rows x 32 k = 1024 float4, 4/thread
#pragma unroll
        for (int r = 0; r < 4; r++) {
            int idx = tid + r * 256;
            int mm = idx >> 3, k4 = idx & 7;
            int m = m0 + mm, k = k0 + k4 * 4;
            float4 v = make_float4(0.f, 0.f, 0.f, 0.f);
            if (m < M && k < K)
                v = *reinterpret_cast<const float4*>(&A[a_idx<MODE>(m, k, K)]);
            float* p = &As[mm * TRS + k4 * 4];
            p[0] = __uint_as_float(f2tf32(v.x));
            p[1] = __uint_as_float(f2tf32(v.y));
            p[2] = __uint_as_float(f2tf32(v.z));
            p[3] = __uint_as_float(f2tf32(v.w));
        }
        // stage B (weights, n-major rows)
#pragma unroll
        for (int r = 0; r < 4; r++) {
            int idx = tid + r * 256;
            int nn = idx >> 3, k4 = idx & 7;
            int n = n0 + nn, k = k0 + k4 * 4;
            float4 v = make_float4(0.f, 0.f, 0.f, 0.f);
            if (n < N && k < K)
                v = *reinterpret_cast<const float4*>(&W[(long)n * ldw + k]);
            float* p = &Bs[nn * TRS + k4 * 4];
            p[0] = __uint_as_float(f2tf32(v.x));
            p[1] = __uint_as_float(f2tf32(v.y));
            p[2] = __uint_as_float(f2tf32(v.z));
            p[3] = __uint_as_float(f2tf32(v.w));
        }
        __syncthreads();

#pragma unroll
        for (int kk = 0; kk < 32; kk += 8) {
            uint32_t a[4][4], b[4][2];
#pragma unroll
            for (int mt = 0; mt < 4; mt++) {
                uint32_t addr = as_base +
                    (uint32_t)(((wr * 64 + mt * 16 + rowA) * TRS + kk + colA) * 4);
                ldsm4(a[mt], addr);
            }
#pragma unroll
            for (int p = 0; p < 2; p++) {
                uint32_t r4[4];
                uint32_t addr = bs_base +
                    (uint32_t)(((wc * 32 + p * 16 + rowB) * TRS + kk + colB) * 4);
                ldsm4(r4, addr);
                b[2 * p][0] = r4[0]; b[2 * p][1] = r4[1];
                b[2 * p + 1][0] = r4[2]; b[2 * p + 1][1] = r4[3];
            }
#pragma unroll
            for (int mt = 0; mt < 4; mt++)
#pragma unroll
                for (int nt = 0; nt < 4; nt++)
                    mma_tf32(acc[mt][nt], a[mt], b[nt]);
        }
        __syncthreads();
    }

    // epilogue
    int lr = lane >> 2, lc = (lane & 3) * 2;
#pragma unroll
    for (int mt = 0; mt < 4; mt++) {
#pragma unroll
        for (int part = 0; part < 2; part++) {
            int m = m0 + wr * 64 + mt * 16 + lr + part * 8;
            if (m >= M) continue;
#pragma unroll
            for (int nt = 0; nt < 4; nt++) {
                int n = n0 + wc * 32 + nt * 8 + lc;
                float v0 = acc[mt][nt][part * 2 + 0];
                float v1 = acc[mt][nt][part * 2 + 1];
                if (biasp) { v0 += biasp[n]; v1 += biasp[n + 1]; }
                if (Cadd) {
                    v0 += Cadd[(long)m * N + n];
                    v1 += Cadd[(long)m * N + n + 1];
                }
                C[(long)m * N + n] = v0;
                C[(long)m * N + n + 1] = v1;
            }
        }
    }
}

// ---------------------------------------------------------------------------
// Combined recurrent step: one launch per t.
//   blocks [0,128):   main bi-GRU. dir = bx>>6, 16 h-cols per block.
//   blocks [128,384): generated GRU. img = (bx-128)>>2, 32 h-cols per block.
// ---------------------------------------------------------------------------
__global__ __launch_bounds__(128) void step_k(
    int t,
    const float* __restrict__ Whh_f, const float* __restrict__ bhh_f,
    const float* __restrict__ Whh_b, const float* __restrict__ bhh_b)
{
    __shared__ float As[32][64];
    __shared__ float Bs[32][128];
    int tid = threadIdx.x;

    if (blockIdx.x < 128) {
        // ---------------- main bi-GRU ----------------
        int bx = blockIdx.x;
        int dir = bx >> 6;
        int j0 = (bx & 63) * 16;
        const float* Whh = dir ? Whh_b : Whh_f;
        const float* bhh = dir ? bhh_b : bhh_f;
        const float* gi  = g_scratch + (dir ? O_GI_B : O_GI_F);
        float* hs        = g_scratch + (dir ? O_HSB : O_HSF);
        float* hbase     = g_scratch + O_HST + (long)dir * 131072;
        const float* hin = hbase + (long)(t & 1) * 65536;
        float* hout      = hbase + (long)((t + 1) & 1) * 65536;
        int tt = dir ? (31 - t) : t;

        int tx = tid & 15, ty = tid >> 4;

        float acc[3][8];
#pragma unroll
        for (int g = 0; g < 3; g++)
#pragma unroll
            for (int i = 0; i < 8; i++) acc[g][i] = 0.f;

        for (int k0 = 0; k0 < 1024; k0 += 32) {
#pragma unroll
            for (int r = 0; r < 4; r++) {
                int idx = tid + r * 128;
                int mm = idx >> 3, k4 = idx & 7;
                float4 v = *reinterpret_cast<const float4*>(&hin[mm * 1024 + k0 + k4 * 4]);
                As[k4 * 4 + 0][mm] = v.x;
                As[k4 * 4 + 1][mm] = v.y;
                As[k4 * 4 + 2][mm] = v.z;
                As[k4 * 4 + 3][mm] = v.w;
            }
#pragma unroll
            for (int r = 0; r < 3; r++) {
                int idx = tid + r * 128;
                int row = idx >> 3, k4 = idx & 7;
                int g = row >> 4, j = row & 15;
                float4 v = *reinterpret_cast<const float4*>(
                    &Whh[(long)(g * 1024 + j0 + j) * 1024 + k0 + k4 * 4]);
                Bs[k4 * 4 + 0][j * 4 + g] = v.x;
                Bs[k4 * 4 + 1][j * 4 + g] = v.y;
                Bs[k4 * 4 + 2][j * 4 + g] = v.z;
                Bs[k4 * 4 + 3][j * 4 + g] = v.w;
            }
            __syncthreads();
#pragma unroll
            for (int kk = 0; kk < 32; kk++) {
                float4 a0 = *reinterpret_cast<const float4*>(&As[kk][ty * 8]);
                float4 a1 = *reinterpret_cast<const float4*>(&As[kk][ty * 8 + 4]);
                float4 b  = *reinterpret_cast<const float4*>(&Bs[kk][tx * 4]);
                float av[8] = {a0.x, a0.y, a0.z, a0.w, a1.x, a1.y, a1.z, a1.w};
#pragma unroll
                for (int i = 0; i < 8; i++) {
                    acc[0][i] += av[i] * b.x;
                    acc[1][i] += av[i] * b.y;
                    acc[2][i] += av[i] * b.z;
                }
            }
            __syncthreads();
        }

        int col = j0 + tx;
        float br = bhh[col], bz = bhh[1024 + col], bn = bhh[2048 + col];
#pragma unroll
        for (int i = 0; i < 8; i++) {
            int m = ty * 8 + i;
            const float* girow = gi + ((long)tt * 64 + m) * 3072;
            float r = sigf(girow[col] + acc[0][i] + br);
            float z = sigf(girow[1024 + col] + acc[1][i] + bz);
            float n = tanhf(girow[2048 + col] + r * (acc[2][i] + bn));
            float hold = hin[m * 1024 + col];
            float hn = (1.f - z) * n + z * hold;
            hout[m * 1024 + col] = hn;
            hs[(long)m * 32768 + (long)tt * 1024 + col] = hn;
        }
    } else {
        // ---------------- generated-weight GRU ----------------
        int b2 = blockIdx.x - 128;
        int img = b2 >> 2;
        int j0 = (b2 & 3) * 32;
        const float* Whh = g_scratch + O_WHH + (long)img * 49152;
        const float* bhh = g_scratch + O_BHH + (long)img * 384;
        const float* gi  = g_scratch + O_GIG + (long)img * 786432 + (long)t * 64 * 384;
        float* hb = g_scratch + O_HG;
        const float* hin = hb + (long)(t & 1) * 524288 + (long)img * 8192;
        float* hout      = hb + (long)((t + 1) & 1) * 524288 + (long)img * 8192;
        float* hmax = g_scratch + O_HMAX + (long)img * 8192;

        int tx = tid & 31, ty = tid >> 5;

        float acc[3][16];
#pragma unroll
        for (int g = 0; g < 3; g++)
#pragma unroll
            for (int i = 0; i < 16; i++) acc[g][i] = 0.f;

        for (int k0 = 0; k0 < 128; k0 += 32) {
#pragma unroll
            for (int r = 0; r < 4; r++) {
                int idx = tid + r * 128;
                int mm = idx >> 3, k4 = idx & 7;
                float4 v = *reinterpret_cast<const float4*>(&hin[mm * 128 + k0 + k4 * 4]);
                As[k4 * 4 + 0][mm] = v.x;
                As[k4 * 4 + 1][mm] = v.y;
                As[k4 * 4 + 2][mm] = v.z;
                As[k4 * 4 + 3][mm] = v.w;
            }
#pragma unroll
            for (int r = 0; r < 6; r++) {
                int idx = tid + r * 128;
                int row = idx >> 3, k4 = idx & 7;
                int g = row >> 5, j = row & 31;
                float4 v = *reinterpret_cast<const float4*>(
                    &Whh[(long)(g * 128 + j0 + j) * 128 + k0 + k4 * 4]);
                Bs[k4 * 4 + 0][j * 4 + g] = v.x;
                Bs[k4 * 4 + 1][j * 4 + g] = v.y;
                Bs[k4 * 4 + 2][j * 4 + g] = v.z;
                Bs[k4 * 4 + 3][j * 4 + g] = v.w;
            }
            __syncthreads();
#pragma unroll
            for (int kk = 0; kk < 32; kk++) {
                float4 a0 = *reinterpret_cast<const float4*>(&As[kk][ty * 16]);
                float4 a1 = *reinterpret_cast<const float4*>(&As[kk][ty * 16 + 4]);
                float4 a2 = *reinterpret_cast<const float4*>(&As[kk][ty * 16 + 8]);
                float4 a3 = *reinterpret_cast<const float4*>(&As[kk][ty * 16 + 12]);
                float4 b  = *reinterpret_cast<const float4*>(&Bs[kk][tx * 4]);
                float av[16] = {a0.x, a0.y, a0.z, a0.w, a1.x, a1.y, a1.z, a1.w,
                                a2.x, a2.y, a2.z, a2.w, a3.x, a3.y, a3.z, a3.w};
#pragma unroll
                for (int i = 0; i < 16; i++) {
                    acc[0][i] += av[i] * b.x;
                    acc[1][i] += av[i] * b.y;
                    acc[2][i] += av[i] * b.z;
                }
            }
            __syncthreads();
        }

        int col = j0 + tx;
        float br = bhh[col], bz = bhh[128 + col], bn = bhh[256 + col];
#pragma unroll
        for (int i = 0; i < 16; i++) {
            int m = ty * 16 + i;
            const float* girow = gi + m * 384;
            float r = sigf(girow[col] + acc[0][i] + br);
            float z = sigf(girow[128 + col] + acc[1][i] + bz);
            float n = tanhf(girow[256 + col] + r * (acc[2][i] + bn));
            float hold = hin[m * 128 + col];
            float hn = (1.f - z) * n + z * hold;
            hout[m * 128 + col] = hn;
            hmax[m * 128 + col] = fmaxf(hmax[m * 128 + col], hn);
        }
    }
}

// txt = 0.5*(hsf + hsb)
__global__ __launch_bounds__(256) void combine_k() {
    long i = (long)blockIdx.x * 256 + threadIdx.x;
    if (i < SZ_HS)
        g_scratch[O_TXT + i] = 0.5f * (g_scratch[O_HSF + i] + g_scratch[O_HSB + i]);
}

// ---------------------------------------------------------------------------
__global__ __launch_bounds__(256) void img_pool_k(const float* __restrict__ img_embed) {
    int b = blockIdx.x, tid = threadIdx.x;
    float vals[4], ss = 0.f;
#pragma unroll
    for (int i = 0; i < 4; i++) {
        int c = i * 256 + tid;
        float s = 0.f;
        for (int g = 0; g < 36; g++) s += img_embed[(long)b * 36864 + (long)g * 1024 + c];
        s *= (1.f / 36.f);
        vals[i] = s;
        ss += s * s;
        g_scratch[O_IEG + (long)b * 1024 + c] = s;
    }
    __shared__ float red[256];
    red[tid] = ss;
    __syncthreads();
    for (int o = 128; o > 0; o >>= 1) { if (tid < o) red[tid] += red[tid + o]; __syncthreads(); }
    float inv = 1.f / (sqrtf(red[0]) + 1e-8f);
#pragma unroll
    for (int i = 0; i < 4; i++) {
        int c = i * 256 + tid;
        g_scratch[O_IVN + (long)b * 1024 + c] = vals[i] * inv;
    }
}

// attention scores + softmax: one warp per (b,t)
__global__ __launch_bounds__(256) void attn_k() {
    int gw = (blockIdx.x * blockDim.x + threadIdx.x) >> 5;
    int lane = threadIdx.x & 31;
    if (gw >= 2048) return;
    int b = gw >> 5;
    const float* qr = g_scratch + O_Q + (long)gw * 128;
    const float* kr = g_scratch + O_K + ((long)b * 32 + lane) * 128;
    float s = 0.f;
#pragma unroll 8
    for (int o = 0; o < 128; o++) s += qr[o] * kr[o];
    float mx = s;
#pragma unroll
    for (int off = 16; off > 0; off >>= 1) mx = fmaxf(mx, __shfl_xor_sync(0xffffffffu, mx, off));
    float e = expf(s - mx);
    float sum = e;
#pragma unroll
    for (int off = 16; off > 0; off >>= 1) sum += __shfl_xor_sync(0xffffffffu, sum, off);
    g_scratch[O_ATT + (long)gw * 32 + lane] = e / sum;
}

__global__ __launch_bounds__(32) void aw_k(const int* __restrict__ lens) {
    int b = blockIdx.x, s = threadIdx.x;
    int len = lens[b];
    float a = 0.f;
    for (int tt = 0; tt < len; tt++) a += g_scratch[O_ATT + ((long)b * 32 + tt) * 32 + s];
    g_scratch[O_AW + b * 32 + s] = a;
}

__global__ __launch_bounds__(256) void txt_embed_k(const int* __restrict__ lens,
                                                   const float* __restrict__ gamma) {
    int b = blockIdx.y;
    int c = blockIdx.x * 256 + threadIdx.x;
    __shared__ float saw[32];
    if (threadIdx.x < 32) saw[threadIdx.x] = g_scratch[O_AW + b * 32 + threadIdx.x];
    __syncthreads();
    int len = lens[b];
    float g = *gamma;
    float a1 = 0.f;
    for (int tt = 0; tt < len; tt++) a1 += g_scratch[O_TXT + ((long)b * 32 + tt) * 1024 + c];
    float a2 = 0.f;
#pragma unroll
    for (int s = 0; s < 32; s++) a2 += saw[s] * g_scratch[O_V + ((long)b * 32 + s) * 1024 + c];
    g_scratch[O_TE + (long)b * 1024 + c] = (a1 + g * a2) / (float)len;
}

// sims[i,b] = (y . iv_i) / (|y| + eps)
__global__ __launch_bounds__(256) void sims_k(float* __restrict__ out) {
    int img = blockIdx.y, b = blockIdx.x;
    int tid = threadIdx.x;
    const float* y = g_scratch + O_Y + (long)img * 65536 + (long)b * 1024;
    const float* iv = g_scratch + O_IVN + (long)img * 1024;
    float ss = 0.f, dp = 0.f;
#pragma unroll
    for (int i = 0; i < 4; i++) {
        int c = i * 256 + tid;
        float v = y[c];
        ss += v * v;
        dp += v * iv[c];
    }
    __shared__ float r1[256], r2[256];
    r1[tid] = ss; r2[tid] = dp;
    __syncthreads();
    for (int o = 128; o > 0; o >>= 1) {
        if (tid < o) { r1[tid] += r1[tid + o]; r2[tid] += r2[tid + o]; }
        __syncthreads();
    }
    if (tid == 0) out[img * 64 + b] = r2[0] / (sqrtf(r1[0]) + 1e-8f);
}

// ---------------------------------------------------------------------------
extern "C" void kernel_launch(void* const* d_in, const int* in_sizes, int n_in,
                              void* d_out, int out_size) {
    const float* img_embed    = (const float*)d_in[0];
    const float* cap_embed    = (const float*)d_in[1];
    const int*   lens         = (const int*)d_in[2];
    const float* W_reduce_img = (const float*)d_in[3];
    const float* b_reduce_img = (const float*)d_in[4];
    const float* W_reduce_txt = (const float*)d_in[5];
    const float* b_reduce_txt = (const float*)d_in[6];
    const float* gru_Wih_f    = (const float*)d_in[7];
    const float* gru_Whh_f    = (const float*)d_in[8];
    const float* gru_bih_f    = (const float*)d_in[9];
    const float* gru_bhh_f    = (const float*)d_in[10];
    const float* gru_Wih_b    = (const float*)d_in[11];
    const float* gru_Whh_b    = (const float*)d_in[12];
    const float* gru_bih_b    = (const float*)d_in[13];
    const float* gru_bhh_b    = (const float*)d_in[14];
    const float* sa_Wq        = (const float*)d_in[15];
    const float* sa_bq        = (const float*)d_in[16];
    const float* sa_Wk        = (const float*)d_in[17];
    const float* sa_bk        = (const float*)d_in[18];
    const float* sa_Wv        = (const float*)d_in[19];
    const float* sa_bv        = (const float*)d_in[20];
    const float* sa_gamma     = (const float*)d_in[21];
    const float* gen_Wih      = (const float*)d_in[22];
    const float* gen_bih      = (const float*)d_in[23];
    const float* gen_Whh      = (const float*)d_in[24];
    const float* gen_bhh      = (const float*)d_in[25];
    const float* gen_Wbih     = (const float*)d_in[26];
    const float* gen_bbih     = (const float*)d_in[27];
    const float* gen_Wbhh     = (const float*)d_in[28];
    const float* gen_bbhh     = (const float*)d_in[29];
    const float* W_txt_fc     = (const float*)d_in[30];
    const float* b_txt_fc     = (const float*)d_in[31];

    float* S = nullptr;
    cudaGetSymbolAddress((void**)&S, g_scratch);

    init_k<<<4096, 256>>>();

    // GRU input projections gi = cap_embed @ Wih^T + bih, layout (T,B,3072)
    gemm_tf32<1><<<dim3(24, 16, 1), 256>>>(cap_embed, gru_Wih_f, gru_bih_f, nullptr,
                                           S + O_GI_F, 2048, 3072, 300, 300, 0, 0, 0, 0);
    gemm_tf32<1><<<dim3(24, 16, 1), 256>>>(cap_embed, gru_Wih_b, gru_bih_b, nullptr,
                                           S + O_GI_B, 2048, 3072, 300, 300, 0, 0, 0, 0);
    // cap_reduced (B,T,128)
    gemm_tf32<0><<<dim3(1, 16, 1), 256>>>(cap_embed, W_reduce_txt, b_reduce_txt, nullptr,
                                          S + O_CR, 2048, 128, 300, 300, 0, 0, 0, 0);
    // image global pooling + normalized copy
    img_pool_k<<<64, 256>>>(img_embed);
    // img_global_vec (tiny)
    gemm_k<0><<<dim3(2, 1, 1), 256>>>(S + O_IEG, W_reduce_img, b_reduce_img, nullptr,
                                      S + O_IGV, 64, 128, 1024, 1024, 0, 0, 0, 0);

    // generated GRU weights per image
    gemm_tf32<0><<<dim3(384, 1, 1), 256>>>(S + O_IGV, gen_Wih, gen_bih, nullptr,
                                           S + O_WIH, 64, 49152, 128, 128, 0, 0, 0, 0);
    gemm_tf32<0><<<dim3(384, 1, 1), 256>>>(S + O_IGV, gen_Whh, gen_bhh, nullptr,
                                           S + O_WHH, 64, 49152, 128, 128, 0, 0, 0, 0);
    gemm_k<0><<<dim3(6, 1, 1), 256>>>(S + O_IGV, gen_Wbih, gen_bbih, nullptr,
                                      S + O_BIH, 64, 384, 128, 128, 0, 0, 0, 0);
    gemm_k<0><<<dim3(6, 1, 1), 256>>>(S + O_IGV, gen_Wbhh, gen_bbhh, nullptr,
                                      S + O_BHH, 64, 384, 128, 128, 0, 0, 0, 0);
    // gi_gen: batched over 64 images, (T,B,384)
    gemm_tf32<2><<<dim3(3, 16, 64), 256>>>(S + O_CR, S + O_WIH, S + O_BIH, nullptr,
                                           S + O_GIG, 2048, 384, 128, 128,
                                           0, 49152, 384, 786432);

    // 32 combined recurrent steps
    for (int t = 0; t < 32; t++)
        step_k<<<384, 128>>>(t, gru_Whh_f, gru_bhh_f, gru_Whh_b, gru_bhh_b);
    combine_k<<<8192, 256>>>();

    // self-attention projections
    gemm_tf32<0><<<dim3(1, 16, 1), 256>>>(S + O_TXT, sa_Wq, sa_bq, nullptr,
                                          S + O_Q, 2048, 128, 1024, 1024, 0, 0, 0, 0);
    gemm_tf32<0><<<dim3(1, 16, 1), 256>>>(S + O_TXT, sa_Wk, sa_bk, nullptr,
                                          S + O_K, 2048, 128, 1024, 1024, 0, 0, 0, 0);
    gemm_tf32<0><<<dim3(8, 16, 1), 256>>>(S + O_TXT, sa_Wv, sa_bv, nullptr,
                                          S + O_V, 2048, 1024, 1024, 1024, 0, 0, 0, 0);
    attn_k<<<256, 256>>>();
    aw_k<<<64, 32>>>(lens);
    txt_embed_k<<<dim3(4, 64), 256>>>(lens, sa_gamma);

    // final FC: shared part + per-image correction
    gemm_k<0><<<dim3(16, 1, 1), 256>>>(S + O_TE, W_txt_fc, b_txt_fc, nullptr,
                                       S + O_FCB, 64, 1024, 1024, 1152, 0, 0, 0, 0);
    gemm_tf32<0><<<dim3(8, 1, 64), 256>>>(S + O_HMAX, W_txt_fc + 1024, nullptr, S + O_FCB,
                                          S + O_Y, 64, 1024, 128, 1152,
                                          64L * 128, 0, 0, 64L * 1024);

    sims_k<<<dim3(64, 64), 256>>>((float*)d_out);
}

// round 8
// speedup vs baseline: 1.9766x; 1.0526x over previous
#include <cuda_runtime.h>
#include <cuda_bf16.h>
#include <math.h>
#include <stdint.h>

// ---------------------------------------------------------------------------
// Problem constants:  L=1024, R=128, T=32, B=64, DIN=300, REG=36, R3=384, H3=3072
// ---------------------------------------------------------------------------

// ---------------- scratch layout (floats) ----------------
#define SZ_GIALL   (2048L*6272)      // fused [GI_f | GI_b | CR] rows (t*64+b)
#define SZ_HS      (64L*32*1024)
#define SZ_HST     (2L*2*64*1024)
#define SZ_WGI     (6272L*300)
#define SZ_BGI     (6400L)
#define SZ_QKV     (2048L*1280)
#define SZ_WQKV    (1280L*1024)
#define SZ_BQKV    (1280L)
#define SZ_ATT     (2048L*32)
#define SZ_AW      (64L*32)
#define SZ_TE      (64L*1024)
#define SZ_IEG     (64L*1024)
#define SZ_IVN     (64L*1024)
#define SZ_IGV     (64L*128)
#define SZ_WG      (64L*49152)
#define SZ_BG      (64L*384)
#define SZ_GIG     (64L*2048*384)
#define SZ_HG      (2L*64*64*128)
#define SZ_HMAX    (64L*64*128)
#define SZ_FCB     (64L*1024)
#define SZ_Y       (64L*64*1024)

#define O_GIALL 0L
#define O_HSF   (O_GIALL + SZ_GIALL)
#define O_HSB   (O_HSF + SZ_HS)
#define O_TXT   (O_HSB + SZ_HS)
#define O_HST   (O_TXT + SZ_HS)
#define O_WGI   (O_HST + SZ_HST)
#define O_BGI   (O_WGI + SZ_WGI)
#define O_QKV   (O_BGI + SZ_BGI)
#define O_WQKV  (O_QKV + SZ_QKV)
#define O_BQKV  (O_WQKV + SZ_WQKV)
#define O_ATT   (O_BQKV + SZ_BQKV)
#define O_AW    (O_ATT + SZ_ATT)
#define O_TE    (O_AW + SZ_AW)
#define O_IEG   (O_TE + SZ_TE)
#define O_IVN   (O_IEG + SZ_IEG)
#define O_IGV   (O_IVN + SZ_IVN)
#define O_WIH   (O_IGV + SZ_IGV)
#define O_WHH   (O_WIH + SZ_WG)
#define O_BIH   (O_WHH + SZ_WG)
#define O_BHH   (O_BIH + SZ_BG)
#define O_GIG   (O_BHH + SZ_BG)
#define O_HG    (O_GIG + SZ_GIG)
#define O_HMAX  (O_HG + SZ_HG)
#define O_FCB   (O_HMAX + SZ_HMAX)
#define O_Y     (O_FCB + SZ_FCB)
#define SCRATCH_TOTAL (O_Y + SZ_Y)

__device__ float g_scratch[SCRATCH_TOTAL];

__device__ __forceinline__ float sigf(float x) { return 1.f / (1.f + expf(-x)); }

__device__ __forceinline__ uint32_t f2tf32(float x) {
    uint32_t r;
    asm("cvt.rna.tf32.f32 %0, %1;" : "=r"(r) : "f"(x));
    return r;
}

__device__ __forceinline__ void ldsm4(uint32_t* r, uint32_t addr) {
    asm volatile("ldmatrix.sync.aligned.m8n8.x4.shared.b16 {%0,%1,%2,%3}, [%4];"
                 : "=r"(r[0]), "=r"(r[1]), "=r"(r[2]), "=r"(r[3]) : "r"(addr));
}

__device__ __forceinline__ void mma_tf32(float* c, const uint32_t* a, const uint32_t* b) {
    asm volatile(
        "mma.sync.aligned.m16n8k8.row.col.f32.tf32.tf32.f32 "
        "{%0,%1,%2,%3}, {%4,%5,%6,%7}, {%8,%9}, {%0,%1,%2,%3};"
        : "+f"(c[0]), "+f"(c[1]), "+f"(c[2]), "+f"(c[3])
        : "r"(a[0]), "r"(a[1]), "r"(a[2]), "r"(a[3]), "r"(b[0]), "r"(b[1]));
}

__device__ __forceinline__ void cpasync16(uint32_t dst, const void* src, bool pred) {
    int sz = pred ? 16 : 0;
    asm volatile("cp.async.cg.shared.global [%0], [%1], 16, %2;"
                 :: "r"(dst), "l"(src), "r"(sz));
}

// ---------------------------------------------------------------------------
__global__ __launch_bounds__(256) void init_k() {
    long idx = (long)blockIdx.x * 256 + threadIdx.x;
    if (idx < SZ_HST)  g_scratch[O_HST + idx] = 0.f;
    if (idx < SZ_HG)   g_scratch[O_HG + idx] = 0.f;
    if (idx < SZ_HMAX) g_scratch[O_HMAX + idx] = -1e30f;
}

// ---------------------------------------------------------------------------
// A indexing modes:
//   0: A[m*lda + k]
//   1: m=t*64+b over cap_embed (B,T,300):  A[(m&63)*9600 + (m>>6)*300 + k]
// ---------------------------------------------------------------------------
template <int MODE>
__device__ __forceinline__ long a_idx(int m, int k, int lda) {
    if (MODE == 0) return (long)m * lda + k;
    { int b = m & 63, t = m >> 6; return (long)b * 9600 + (long)t * 300 + k; }
}

// ---------------------------------------------------------------------------
// Small-tile SGEMM (64x64, 4x4/thread) -- for tiny shapes only. lda = K.
// ---------------------------------------------------------------------------
__global__ __launch_bounds__(256) void gemm_k(
    const float* __restrict__ A, const float* __restrict__ W,
    const float* __restrict__ bias, const float* __restrict__ Cadd,
    float* __restrict__ C,
    int M, int N, int K, int ldw,
    long aBS, long wBS, long bBS, long cBS)
{
    int bz = blockIdx.z;
    A += (long)bz * aBS;
    W += (long)bz * wBS;
    C += (long)bz * cBS;
    const float* biasp = bias ? (bias + (long)bz * bBS) : nullptr;

    __shared__ float As[16][65];
    __shared__ float Bs[16][65];
    int tid = threadIdx.x;
    int tx = tid & 15, ty = tid >> 4;
    int m0 = blockIdx.y * 64, n0 = blockIdx.x * 64;

    float acc[4][4];
#pragma unroll
    for (int i = 0; i < 4; i++)
#pragma unroll
        for (int j = 0; j < 4; j++) acc[i][j] = 0.f;

    for (int k0 = 0; k0 < K; k0 += 16) {
#pragma unroll
        for (int r = 0; r < 4; r++) {
            int i = tid + r * 256;
            int mm = i >> 4, kk = i & 15;
            int m = m0 + mm, k = k0 + kk;
            As[kk][mm] = (m < M && k < K) ? A[(long)m * K + k] : 0.f;
        }
#pragma unroll
        for (int r = 0; r < 4; r++) {
            int i = tid + r * 256;
            int nn = i >> 4, kk = i & 15;
            int n = n0 + nn, k = k0 + kk;
            Bs[kk][nn] = (n < N && k < K) ? W[(long)n * ldw + k] : 0.f;
        }
        __syncthreads();
#pragma unroll
        for (int kk = 0; kk < 16; kk++) {
            float av[4], bv[4];
#pragma unroll
            for (int i = 0; i < 4; i++) av[i] = As[kk][ty * 4 + i];
#pragma unroll
            for (int j = 0; j < 4; j++) bv[j] = Bs[kk][tx * 4 + j];
#pragma unroll
            for (int i = 0; i < 4; i++)
#pragma unroll
                for (int j = 0; j < 4; j++) acc[i][j] += av[i] * bv[j];
        }
        __syncthreads();
    }

#pragma unroll
    for (int i = 0; i < 4; i++) {
        int m = m0 + ty * 4 + i;
        if (m >= M) continue;
#pragma unroll
        for (int j = 0; j < 4; j++) {
            int n = n0 + tx * 4 + j;
            if (n >= N) continue;
            float v = acc[i][j];
            if (biasp) v += biasp[n];
            if (Cadd) v += Cadd[(long)m * N + n];
            C[(long)m * N + n] = v;
        }
    }
}

// ---------------------------------------------------------------------------
// TF32 tensor-core GEMM v2: 128x128 tile, 8 warps, m16n8k8 mma.
// cp.async double-buffered staging (raw fp32 bits), cvt.rna.tf32 applied
// after ldmatrix. Dynamic smem: 2 stages x (A+B) x 128x36 floats = 73728 B.
// C[m,n] = sum_k A(m,k) * W[n*ldw+k] (+bias[n]) (+Cadd[m,n])
// Requires K % 4 == 0.
// ---------------------------------------------------------------------------
#define TRS 36
#define STG (128 * TRS)   // floats per matrix per stage

template <int MODE>
__global__ __launch_bounds__(256) void gemm_tf32(
    const float* __restrict__ A, const float* __restrict__ W,
    const float* __restrict__ bias, const float* __restrict__ Cadd,
    float* __restrict__ C,
    int M, int N, int K, int lda, int ldw,
    long aBS, long wBS, long bBS, long cBS)
{
    extern __shared__ float sm[];

    int bz = blockIdx.z;
    A += (long)bz * aBS;
    W += (long)bz * wBS;
    C += (long)bz * cBS;
    const float* biasp = bias ? (bias + (long)bz * bBS) : nullptr;

    int tid = threadIdx.x;
    int warp = tid >> 5, lane = tid & 31;
    int wr = warp >> 2, wc = warp & 3;
    int m0 = blockIdx.y * 128, n0 = blockIdx.x * 128;

    float acc[4][4][4];
#pragma unroll
    for (int mt = 0; mt < 4; mt++)
#pragma unroll
        for (int nt = 0; nt < 4; nt++)
#pragma unroll
            for (int q = 0; q < 4; q++) acc[mt][nt][q] = 0.f;

    uint32_t smbase = (uint32_t)__cvta_generic_to_shared(sm);

    int rowA = (lane & 7) + ((lane >> 3) & 1) * 8;
    int colA = (lane >> 4) * 4;
    int rowB = (lane & 7) + (lane >> 4) * 8;
    int colB = ((lane >> 3) & 1) * 4;

    const int NIT = (K + 31) / 32;

    auto issue = [&](int it, int s) {
        int k0 = it * 32;
        uint32_t abase = smbase + (uint32_t)(s * 2 * STG) * 4u;
        uint32_t bbase = abase + (uint32_t)STG * 4u;
#pragma unroll
        for (int r = 0; r < 4; r++) {
            int idx = tid + r * 256;
            int mm = idx >> 3, k4 = idx & 7;
            int m = m0 + mm, k = k0 + k4 * 4;
            bool p = (m < M) && (k < K);
            const float* src = p ? &A[a_idx<MODE>(m, k, lda)] : A;
            cpasync16(abase + (uint32_t)(mm * TRS + k4 * 4) * 4u, src, p);
        }
#pragma unroll
        for (int r = 0; r < 4; r++) {
            int idx = tid + r * 256;
            int nn = idx >> 3, k4 = idx & 7;
            int n = n0 + nn, k = k0 + k4 * 4;
            bool p = (n < N) && (k < K);
            const float* src = p ? &W[(long)n * ldw + k] : W;
            cpasync16(bbase + (uint32_t)(nn * TRS + k4 * 4) * 4u, src, p);
        }
        asm volatile("cp.async.commit_group;");
    };

    issue(0, 0);
    for (int it = 0; it < NIT; it++) {
        int cur = it & 1;
        if (it + 1 < NIT) {
            issue(it + 1, cur ^ 1);
            asm volatile("cp.async.wait_group 1;");
        } else {
            asm volatile("cp.async.wait_group 0;");
        }
        __syncthreads();

        uint32_t asb = smbase + (uint32_t)(cur * 2 * STG) * 4u;
        uint32_t bsb = asb + (uint32_t)STG * 4u;
#pragma unroll
        for (int kk = 0; kk < 32; kk += 8) {
            uint32_t a[4][4], b[4][2];
#pragma unroll
            for (int mt = 0; mt < 4; mt++) {
                ldsm4(a[mt], asb +
                      (uint32_t)(((wr * 64 + mt * 16 + rowA) * TRS + kk + colA) * 4));
#pragma unroll
                for (int q = 0; q < 4; q++)
                    a[mt][q] = f2tf32(__uint_as_float(a[mt][q]));
            }
#pragma unroll
            for (int p = 0; p < 2; p++) {
                uint32_t r4[4];
                ldsm4(r4, bsb +
                      (uint32_t)(((wc * 32 + p * 16 + rowB) * TRS + kk + colB) * 4));
#pragma unroll
                for (int q = 0; q < 4; q++)
                    r4[q] = f2tf32(__uint_as_float(r4[q]));
                b[2 * p][0] = r4[0]; b[2 * p][1] = r4[1];
                b[2 * p + 1][0] = r4[2]; b[2 * p + 1][1] = r4[3];
            }
#pragma unroll
            for (int mt = 0; mt < 4; mt++)
#pragma unroll
                for (int nt = 0; nt < 4; nt++)
                    mma_tf32(acc[mt][nt], a[mt], b[nt]);
        }
        __syncthreads();
    }

    int lr = lane >> 2, lc = (lane & 3) * 2;
#pragma unroll
    for (int mt = 0; mt < 4; mt++) {
#pragma unroll
        for (int part = 0; part < 2; part++) {
            int m = m0 + wr * 64 + mt * 16 + lr + part * 8;
            if (m >= M) continue;
#pragma unroll
            for (int nt = 0; nt < 4; nt++) {
                int n = n0 + wc * 32 + nt * 8 + lc;
                float v0 = acc[mt][nt][part * 2 + 0];
                float v1 = acc[mt][nt][part * 2 + 1];
                if (biasp) { v0 += biasp[n]; v1 += biasp[n + 1]; }
                if (Cadd) {
                    v0 += Cadd[(long)m * N + n];
                    v1 += Cadd[(long)m * N + n + 1];
                }
                C[(long)m * N + n] = v0;
                C[(long)m * N + n + 1] = v1;
            }
        }
    }
}

// ---------------------------------------------------------------------------
// Combined recurrent step (fp32): blocks [0,128) main bi-GRU, [128,384) gen GRU.
// gi now lives in fused GIALL (row stride 6272; dir offset 0/3072).
// ---------------------------------------------------------------------------
__global__ __launch_bounds__(128) void step_k(
    int t,
    const float* __restrict__ Whh_f, const float* __restrict__ bhh_f,
    const float* __restrict__ Whh_b, const float* __restrict__ bhh_b)
{
    __shared__ float As[32][64];
    __shared__ float Bs[32][128];
    int tid = threadIdx.x;

    if (blockIdx.x < 128) {
        int bx = blockIdx.x;
        int dir = bx >> 6;
        int j0 = (bx & 63) * 16;
        const float* Whh = dir ? Whh_b : Whh_f;
        const float* bhh = dir ? bhh_b : bhh_f;
        const float* gi  = g_scratch + O_GIALL + (long)dir * 3072;
        float* hs        = g_scratch + (dir ? O_HSB : O_HSF);
        float* hbase     = g_scratch + O_HST + (long)dir * 131072;
        const float* hin = hbase + (long)(t & 1) * 65536;
        float* hout      = hbase + (long)((t + 1) & 1) * 65536;
        int tt = dir ? (31 - t) : t;

        int tx = tid & 15, ty = tid >> 4;

        float acc[3][8];
#pragma unroll
        for (int g = 0; g < 3; g++)
#pragma unroll
            for (int i = 0; i < 8; i++) acc[g][i] = 0.f;

        for (int k0 = 0; k0 < 1024; k0 += 32) {
#pragma unroll
            for (int r = 0; r < 4; r++) {
                int idx = tid + r * 128;
                int mm = idx >> 3, k4 = idx & 7;
                float4 v = *reinterpret_cast<const float4*>(&hin[mm * 1024 + k0 + k4 * 4]);
                As[k4 * 4 + 0][mm] = v.x;
                As[k4 * 4 + 1][mm] = v.y;
                As[k4 * 4 + 2][mm] = v.z;
                As[k4 * 4 + 3][mm] = v.w;
            }
#pragma unroll
            for (int r = 0; r < 3; r++) {
                int idx = tid + r * 128;
                int row = idx >> 3, k4 = idx & 7;
                int g = row >> 4, j = row & 15;
                float4 v = *reinterpret_cast<const float4*>(
                    &Whh[(long)(g * 1024 + j0 + j) * 1024 + k0 + k4 * 4]);
                Bs[k4 * 4 + 0][j * 4 + g] = v.x;
                Bs[k4 * 4 + 1][j * 4 + g] = v.y;
                Bs[k4 * 4 + 2][j * 4 + g] = v.z;
                Bs[k4 * 4 + 3][j * 4 + g] = v.w;
            }
            __syncthreads();
#pragma unroll
            for (int kk = 0; kk < 32; kk++) {
                float4 a0 = *reinterpret_cast<const float4*>(&As[kk][ty * 8]);
                float4 a1 = *reinterpret_cast<const float4*>(&As[kk][ty * 8 + 4]);
                float4 b  = *reinterpret_cast<const float4*>(&Bs[kk][tx * 4]);
                float av[8] = {a0.x, a0.y, a0.z, a0.w, a1.x, a1.y, a1.z, a1.w};
#pragma unroll
                for (int i = 0; i < 8; i++) {
                    acc[0][i] += av[i] * b.x;
                    acc[1][i] += av[i] * b.y;
                    acc[2][i] += av[i] * b.z;
                }
            }
            __syncthreads();
        }

        int col = j0 + tx;
        float br = bhh[col], bz = bhh[1024 + col], bn = bhh[2048 + col];
#pragma unroll
        for (int i = 0; i < 8; i++) {
            int m = ty * 8 + i;
            const float* girow = gi + ((long)tt * 64 + m) * 6272;
            float r = sigf(girow[col] + acc[0][i] + br);
            float z = sigf(girow[1024 + col] + acc[1][i] + bz);
            float n = tanhf(girow[2048 + col] + r * (acc[2][i] + bn));
            float hold = hin[m * 1024 + col];
            float hn = (1.f - z) * n + z * hold;
            hout[m * 1024 + col] = hn;
            hs[(long)m * 32768 + (long)tt * 1024 + col] = hn;
        }
    } else {
        int b2 = blockIdx.x - 128;
        int img = b2 >> 2;
        int j0 = (b2 & 3) * 32;
        const float* Whh = g_scratch + O_WHH + (long)img * 49152;
        const float* bhh = g_scratch + O_BHH + (long)img * 384;
        const float* gi  = g_scratch + O_GIG + (long)img * 786432 + (long)t * 64 * 384;
        float* hb = g_scratch + O_HG;
        const float* hin = hb + (long)(t & 1) * 524288 + (long)img * 8192;
        float* hout      = hb + (long)((t + 1) & 1) * 524288 + (long)img * 8192;
        float* hmax = g_scratch + O_HMAX + (long)img * 8192;

        int tx = tid & 31, ty = tid >> 5;

        float acc[3][16];
#pragma unroll
        for (int g = 0; g < 3; g++)
#pragma unroll
            for (int i = 0; i < 16; i++) acc[g][i] = 0.f;

        for (int k0 = 0; k0 < 128; k0 += 32) {
#pragma unroll
            for (int r = 0; r < 4; r++) {
                int idx = tid + r * 128;
                int mm = idx >> 3, k4 = idx & 7;
                float4 v = *reinterpret_cast<const float4*>(&hin[mm * 128 + k0 + k4 * 4]);
                As[k4 * 4 + 0][mm] = v.x;
                As[k4 * 4 + 1][mm] = v.y;
                As[k4 * 4 + 2][mm] = v.z;
                As[k4 * 4 + 3][mm] = v.w;
            }
#pragma unroll
            for (int r = 0; r < 6; r++) {
                int idx = tid + r * 128;
                int row = idx >> 3, k4 = idx & 7;
                int g = row >> 5, j = row & 31;
                float4 v = *reinterpret_cast<const float4*>(
                    &Whh[(long)(g * 128 + j0 + j) * 128 + k0 + k4 * 4]);
                Bs[k4 * 4 + 0][j * 4 + g] = v.x;
                Bs[k4 * 4 + 1][j * 4 + g] = v.y;
                Bs[k4 * 4 + 2][j * 4 + g] = v.z;
                Bs[k4 * 4 + 3][j * 4 + g] = v.w;
            }
            __syncthreads();
#pragma unroll
            for (int kk = 0; kk < 32; kk++) {
                float4 a0 = *reinterpret_cast<const float4*>(&As[kk][ty * 16]);
                float4 a1 = *reinterpret_cast<const float4*>(&As[kk][ty * 16 + 4]);
                float4 a2 = *reinterpret_cast<const float4*>(&As[kk][ty * 16 + 8]);
                float4 a3 = *reinterpret_cast<const float4*>(&As[kk][ty * 16 + 12]);
                float4 b  = *reinterpret_cast<const float4*>(&Bs[kk][tx * 4]);
                float av[16] = {a0.x, a0.y, a0.z, a0.w, a1.x, a1.y, a1.z, a1.w,
                                a2.x, a2.y, a2.z, a2.w, a3.x, a3.y, a3.z, a3.w};
#pragma unroll
                for (int i = 0; i < 16; i++) {
                    acc[0][i] += av[i] * b.x;
                    acc[1][i] += av[i] * b.y;
                    acc[2][i] += av[i] * b.z;
                }
            }
            __syncthreads();
        }

        int col = j0 + tx;
        float br = bhh[col], bz = bhh[128 + col], bn = bhh[256 + col];
#pragma unroll
        for (int i = 0; i < 16; i++) {
            int m = ty * 16 + i;
            const float* girow = gi + m * 384;
            float r = sigf(girow[col] + acc[0][i] + br);
            float z = sigf(girow[128 + col] + acc[1][i] + bz);
            float n = tanhf(girow[256 + col] + r * (acc[2][i] + bn));
            float hold = hin[m * 128 + col];
            float hn = (1.f - z) * n + z * hold;
            hout[m * 128 + col] = hn;
            hmax[m * 128 + col] = fmaxf(hmax[m * 128 + col], hn);
        }
    }
}

// txt = 0.5*(hsf + hsb)
__global__ __launch_bounds__(256) void combine_k() {
    long i = (long)blockIdx.x * 256 + threadIdx.x;
    if (i < SZ_HS)
        g_scratch[O_TXT + i] = 0.5f * (g_scratch[O_HSF + i] + g_scratch[O_HSB + i]);
}

// ---------------------------------------------------------------------------
__global__ __launch_bounds__(256) void img_pool_k(const float* __restrict__ img_embed) {
    int b = blockIdx.x, tid = threadIdx.x;
    float vals[4], ss = 0.f;
#pragma unroll
    for (int i = 0; i < 4; i++) {
        int c = i * 256 + tid;
        float s = 0.f;
        for (int g = 0; g < 36; g++) s += img_embed[(long)b * 36864 + (long)g * 1024 + c];
        s *= (1.f / 36.f);
        vals[i] = s;
        ss += s * s;
        g_scratch[O_IEG + (long)b * 1024 + c] = s;
    }
    __shared__ float red[256];
    red[tid] = ss;
    __syncthreads();
    for (int o = 128; o > 0; o >>= 1) { if (tid < o) red[tid] += red[tid + o]; __syncthreads(); }
    float inv = 1.f / (sqrtf(red[0]) + 1e-8f);
#pragma unroll
    for (int i = 0; i < 4; i++) {
        int c = i * 256 + tid;
        g_scratch[O_IVN + (long)b * 1024 + c] = vals[i] * inv;
    }
}

// attention scores + softmax over fused QKV buffer (row stride 1280)
__global__ __launch_bounds__(256) void attn_k() {
    int gw = (blockIdx.x * blockDim.x + threadIdx.x) >> 5;
    int lane = threadIdx.x & 31;
    if (gw >= 2048) return;
    int b = gw >> 5;
    const float* qr = g_scratch + O_QKV + (long)gw * 1280;
    const float* kr = g_scratch + O_QKV + ((long)b * 32 + lane) * 1280 + 128;
    float s = 0.f;
#pragma unroll 8
    for (int o = 0; o < 128; o++) s += qr[o] * kr[o];
    float mx = s;
#pragma unroll
    for (int off = 16; off > 0; off >>= 1) mx = fmaxf(mx, __shfl_xor_sync(0xffffffffu, mx, off));
    float e = expf(s - mx);
    float sum = e;
#pragma unroll
    for (int off = 16; off > 0; off >>= 1) sum += __shfl_xor_sync(0xffffffffu, sum, off);
    g_scratch[O_ATT + (long)gw * 32 + lane] = e / sum;
}

__global__ __launch_bounds__(32) void aw_k(const int* __restrict__ lens) {
    int b = blockIdx.x, s = threadIdx.x;
    int len = lens[b];
    float a = 0.f;
    for (int tt = 0; tt < len; tt++) a += g_scratch[O_ATT + ((long)b * 32 + tt) * 32 + s];
    g_scratch[O_AW + b * 32 + s] = a;
}

__global__ __launch_bounds__(256) void txt_embed_k(const int* __restrict__ lens,
                                                   const float* __restrict__ gamma) {
    int b = blockIdx.y;
    int c = blockIdx.x * 256 + threadIdx.x;
    __shared__ float saw[32];
    if (threadIdx.x < 32) saw[threadIdx.x] = g_scratch[O_AW + b * 32 + threadIdx.x];
    __syncthreads();
    int len = lens[b];
    float g = *gamma;
    float a1 = 0.f;
    for (int tt = 0; tt < len; tt++) a1 += g_scratch[O_TXT + ((long)b * 32 + tt) * 1024 + c];
    float a2 = 0.f;
#pragma unroll
    for (int s = 0; s < 32; s++)
        a2 += saw[s] * g_scratch[O_QKV + ((long)b * 32 + s) * 1280 + 256 + c];
    g_scratch[O_TE + (long)b * 1024 + c] = (a1 + g * a2) / (float)len;
}

// sims[i,b] = (y . iv_i) / (|y| + eps)
__global__ __launch_bounds__(256) void sims_k(float* __restrict__ out) {
    int img = blockIdx.y, b = blockIdx.x;
    int tid = threadIdx.x;
    const float* y = g_scratch + O_Y + (long)img * 65536 + (long)b * 1024;
    const float* iv = g_scratch + O_IVN + (long)img * 1024;
    float ss = 0.f, dp = 0.f;
#pragma unroll
    for (int i = 0; i < 4; i++) {
        int c = i * 256 + tid;
        float v = y[c];
        ss += v * v;
        dp += v * iv[c];
    }
    __shared__ float r1[256], r2[256];
    r1[tid] = ss; r2[tid] = dp;
    __syncthreads();
    for (int o = 128; o > 0; o >>= 1) {
        if (tid < o) { r1[tid] += r1[tid + o]; r2[tid] += r2[tid + o]; }
        __syncthreads();
    }
    if (tid == 0) out[img * 64 + b] = r2[0] / (sqrtf(r1[0]) + 1e-8f);
}

// ---------------------------------------------------------------------------
extern "C" void kernel_launch(void* const* d_in, const int* in_sizes, int n_in,
                              void* d_out, int out_size) {
    const float* img_embed    = (const float*)d_in[0];
    const float* cap_embed    = (const float*)d_in[1];
    const int*   lens         = (const int*)d_in[2];
    const float* W_reduce_img = (const float*)d_in[3];
    const float* b_reduce_img = (const float*)d_in[4];
    const float* W_reduce_txt = (const float*)d_in[5];
    const float* b_reduce_txt = (const float*)d_in[6];
    const float* gru_Wih_f    = (const float*)d_in[7];
    const float* gru_Whh_f    = (const float*)d_in[8];
    const float* gru_bih_f    = (const float*)d_in[9];
    const float* gru_bhh_f    = (const float*)d_in[10];
    const float* gru_Wih_b    = (const float*)d_in[11];
    const float* gru_Whh_b    = (const float*)d_in[12];
    const float* gru_bih_b    = (const float*)d_in[13];
    const float* gru_bhh_b    = (const float*)d_in[14];
    const float* sa_Wq        = (const float*)d_in[15];
    const float* sa_bq        = (const float*)d_in[16];
    const float* sa_Wk        = (const float*)d_in[17];
    const float* sa_bk        = (const float*)d_in[18];
    const float* sa_Wv        = (const float*)d_in[19];
    const float* sa_bv        = (const float*)d_in[20];
    const float* sa_gamma     = (const float*)d_in[21];
    const float* gen_Wih      = (const float*)d_in[22];
    const float* gen_bih      = (const float*)d_in[23];
    const float* gen_Whh      = (const float*)d_in[24];
    const float* gen_bhh      = (const float*)d_in[25];
    const float* gen_Wbih     = (const float*)d_in[26];
    const float* gen_bbih     = (const float*)d_in[27];
    const float* gen_Wbhh     = (const float*)d_in[28];
    const float* gen_bbhh     = (const float*)d_in[29];
    const float* W_txt_fc     = (const float*)d_in[30];
    const float* b_txt_fc     = (const float*)d_in[31];

    float* S = nullptr;
    cudaGetSymbolAddress((void**)&S, g_scratch);

    const int SMEM_TF32 = 2 * 2 * STG * 4;  // 73728 B
    cudaFuncSetAttribute(gemm_tf32<0>, cudaFuncAttributeMaxDynamicSharedMemorySize, SMEM_TF32);
    cudaFuncSetAttribute(gemm_tf32<1>, cudaFuncAttributeMaxDynamicSharedMemorySize, SMEM_TF32);

    init_k<<<4096, 256>>>();

    // Concatenate weights for fused GEMMs (D2D copies, graph-capturable)
    cudaMemcpyAsync(S + O_WGI,              gru_Wih_f,    3072L*300*4, cudaMemcpyDeviceToDevice);
    cudaMemcpyAsync(S + O_WGI + 3072L*300,  gru_Wih_b,    3072L*300*4, cudaMemcpyDeviceToDevice);
    cudaMemcpyAsync(S + O_WGI + 6144L*300,  W_reduce_txt, 128L*300*4,  cudaMemcpyDeviceToDevice);
    cudaMemcpyAsync(S + O_BGI,              gru_bih_f,    3072L*4,     cudaMemcpyDeviceToDevice);
    cudaMemcpyAsync(S + O_BGI + 3072,       gru_bih_b,    3072L*4,     cudaMemcpyDeviceToDevice);
    cudaMemcpyAsync(S + O_BGI + 6144,       b_reduce_txt, 128L*4,      cudaMemcpyDeviceToDevice);
    cudaMemcpyAsync(S + O_WQKV,             sa_Wq,        128L*1024*4, cudaMemcpyDeviceToDevice);
    cudaMemcpyAsync(S + O_WQKV + 128L*1024, sa_Wk,        128L*1024*4, cudaMemcpyDeviceToDevice);
    cudaMemcpyAsync(S + O_WQKV + 256L*1024, sa_Wv,        1024L*1024*4,cudaMemcpyDeviceToDevice);
    cudaMemcpyAsync(S + O_BQKV,             sa_bq,        128L*4,      cudaMemcpyDeviceToDevice);
    cudaMemcpyAsync(S + O_BQKV + 128,       sa_bk,        128L*4,      cudaMemcpyDeviceToDevice);
    cudaMemcpyAsync(S + O_BQKV + 256,       sa_bv,        1024L*4,     cudaMemcpyDeviceToDevice);

    // Fused GI_f|GI_b|CR projection: (T*B, 6272)
    gemm_tf32<1><<<dim3(49, 16, 1), 256, SMEM_TF32>>>(
        cap_embed, S + O_WGI, S + O_BGI, nullptr, S + O_GIALL,
        2048, 6272, 300, 300, 300, 0, 0, 0, 0);

    // image global pooling + normalized copy
    img_pool_k<<<64, 256>>>(img_embed);
    gemm_k<<<dim3(2, 1, 1), 256>>>(S + O_IEG, W_reduce_img, b_reduce_img, nullptr,
                                   S + O_IGV, 64, 128, 1024, 1024, 0, 0, 0, 0);

    // generated GRU weights per image
    gemm_tf32<0><<<dim3(384, 1, 1), 256, SMEM_TF32>>>(
        S + O_IGV, gen_Wih, gen_bih, nullptr, S + O_WIH,
        64, 49152, 128, 128, 128, 0, 0, 0, 0);
    gemm_tf32<0><<<dim3(384, 1, 1), 256, SMEM_TF32>>>(
        S + O_IGV, gen_Whh, gen_bhh, nullptr, S + O_WHH,
        64, 49152, 128, 128, 128, 0, 0, 0, 0);
    gemm_k<<<dim3(6, 1, 1), 256>>>(S + O_IGV, gen_Wbih, gen_bbih, nullptr,
                                   S + O_BIH, 64, 384, 128, 128, 0, 0, 0, 0);
    gemm_k<<<dim3(6, 1, 1), 256>>>(S + O_IGV, gen_Wbhh, gen_bbhh, nullptr,
                                   S + O_BHH, 64, 384, 128, 128, 0, 0, 0, 0);

    // gi_gen: A = CR columns of GIALL (lda 6272), batched over 64 images
    gemm_tf32<0><<<dim3(3, 16, 64), 256, SMEM_TF32>>>(
        S + O_GIALL + 6144, S + O_WIH, S + O_BIH, nullptr, S + O_GIG,
        2048, 384, 128, 6272, 128, 0, 49152, 384, 786432);

    // 32 combined recurrent steps
    for (int t = 0; t < 32; t++)
        step_k<<<384, 128>>>(t, gru_Whh_f, gru_bhh_f, gru_Whh_b, gru_bhh_b);
    combine_k<<<8192, 256>>>();

    // fused Q|K|V projection: (B*T, 1280)
    gemm_tf32<0><<<dim3(10, 16, 1), 256, SMEM_TF32>>>(
        S + O_TXT, S + O_WQKV, S + O_BQKV, nullptr, S + O_QKV,
        2048, 1280, 1024, 1024, 1024, 0, 0, 0, 0);
    attn_k<<<256, 256>>>();
    aw_k<<<64, 32>>>(lens);
    txt_embed_k<<<dim3(4, 64), 256>>>(lens, sa_gamma);

    // final FC: shared part + per-image correction
    gemm_tf32<0><<<dim3(8, 1, 1), 256, SMEM_TF32>>>(
        S + O_TE, W_txt_fc, b_txt_fc, nullptr, S + O_FCB,
        64, 1024, 1024, 1024, 1152, 0, 0, 0, 0);
    gemm_tf32<0><<<dim3(8, 1, 64), 256, SMEM_TF32>>>(
        S + O_HMAX, W_txt_fc + 1024, nullptr, S + O_FCB, S + O_Y,
        64, 1024, 128, 128, 1152, 64L * 128, 0, 0, 64L * 1024);

    sims_k<<<dim3(64, 64), 256>>>((float*)d_out);
}

// round 9
// speedup vs baseline: 2.8306x; 1.4320x over previous
#include <cuda_runtime.h>
#include <cuda_bf16.h>
#include <math.h>
#include <stdint.h>

// ---------------------------------------------------------------------------
// Problem constants:  L=1024, R=128, T=32, B=64, DIN=300, REG=36, R3=384, H3=3072
// ---------------------------------------------------------------------------

// ---------------- scratch layout (floats) ----------------
#define SZ_GIALL   (2048L*6272)      // fused [GI_f | GI_b | CR] rows (t*64+b)
#define SZ_TXT     (64L*32*1024)
#define SZ_HST     (2L*2*64*1024)
#define SZ_WGI     (6272L*300)
#define SZ_BGI     (6400L)
#define SZ_QKV     (2048L*1280)
#define SZ_WQKV    (1280L*1024)
#define SZ_BQKV    (1280L)
#define SZ_ATT     (2048L*32)
#define SZ_AW      (64L*32)
#define SZ_TE      (64L*1024)
#define SZ_IEG     (64L*1024)
#define SZ_IVN     (64L*1024)
#define SZ_IGV     (64L*128)
#define SZ_WG      (64L*49152)
#define SZ_BG      (64L*384)
#define SZ_GIG     (64L*2048*384)
#define SZ_HG      (2L*64*64*128)
#define SZ_HMAX    (64L*64*128)
#define SZ_FCB     (64L*1024)
#define SZ_Y       (64L*64*1024)

#define O_GIALL 0L
#define O_TXT   (O_GIALL + SZ_GIALL)
#define O_HST   (O_TXT + SZ_TXT)
#define O_WGI   (O_HST + SZ_HST)
#define O_BGI   (O_WGI + SZ_WGI)
#define O_QKV   (O_BGI + SZ_BGI)
#define O_WQKV  (O_QKV + SZ_QKV)
#define O_BQKV  (O_WQKV + SZ_WQKV)
#define O_ATT   (O_BQKV + SZ_BQKV)
#define O_AW    (O_ATT + SZ_ATT)
#define O_TE    (O_AW + SZ_AW)
#define O_IEG   (O_TE + SZ_TE)
#define O_IVN   (O_IEG + SZ_IEG)
#define O_IGV   (O_IVN + SZ_IVN)
#define O_WIH   (O_IGV + SZ_IGV)
#define O_WHH   (O_WIH + SZ_WG)
#define O_BIH   (O_WHH + SZ_WG)
#define O_BHH   (O_BIH + SZ_BG)
#define O_GIG   (O_BHH + SZ_BG)
#define O_HG    (O_GIG + SZ_GIG)
#define O_HMAX  (O_HG + SZ_HG)
#define O_FCB   (O_HMAX + SZ_HMAX)
#define O_Y     (O_FCB + SZ_FCB)
#define SCRATCH_TOTAL (O_Y + SZ_Y)

__device__ float g_scratch[SCRATCH_TOTAL];

__device__ __forceinline__ float sigf(float x) { return 1.f / (1.f + expf(-x)); }

__device__ __forceinline__ uint32_t f2tf32(float x) {
    uint32_t r;
    asm("cvt.rna.tf32.f32 %0, %1;" : "=r"(r) : "f"(x));
    return r;
}

__device__ __forceinline__ void ldsm4(uint32_t* r, uint32_t addr) {
    asm volatile("ldmatrix.sync.aligned.m8n8.x4.shared.b16 {%0,%1,%2,%3}, [%4];"
                 : "=r"(r[0]), "=r"(r[1]), "=r"(r[2]), "=r"(r[3]) : "r"(addr));
}

__device__ __forceinline__ void mma_tf32(float* c, const uint32_t* a, const uint32_t* b) {
    asm volatile(
        "mma.sync.aligned.m16n8k8.row.col.f32.tf32.tf32.f32 "
        "{%0,%1,%2,%3}, {%4,%5,%6,%7}, {%8,%9}, {%0,%1,%2,%3};"
        : "+f"(c[0]), "+f"(c[1]), "+f"(c[2]), "+f"(c[3])
        : "r"(a[0]), "r"(a[1]), "r"(a[2]), "r"(a[3]), "r"(b[0]), "r"(b[1]));
}

__device__ __forceinline__ void cpasync16(uint32_t dst, const void* src, bool pred) {
    int sz = pred ? 16 : 0;
    asm volatile("cp.async.cg.shared.global [%0], [%1], 16, %2;"
                 :: "r"(dst), "l"(src), "r"(sz));
}

// ---------------------------------------------------------------------------
__global__ __launch_bounds__(256) void init_k() {
    long idx = (long)blockIdx.x * 256 + threadIdx.x;
    if (idx < SZ_HST)  g_scratch[O_HST + idx] = 0.f;
    if (idx < SZ_HG)   g_scratch[O_HG + idx] = 0.f;
    if (idx < SZ_HMAX) g_scratch[O_HMAX + idx] = -1e30f;
}

// ---------------------------------------------------------------------------
// A indexing modes:
//   0: A[m*lda + k]
//   1: m=t*64+b over cap_embed (B,T,300):  A[(m&63)*9600 + (m>>6)*300 + k]
// ---------------------------------------------------------------------------
template <int MODE>
__device__ __forceinline__ long a_idx(int m, int k, int lda) {
    if (MODE == 0) return (long)m * lda + k;
    { int b = m & 63, t = m >> 6; return (long)b * 9600 + (long)t * 300 + k; }
}

// ---------------------------------------------------------------------------
// TF32 tensor-core GEMM: 128x128 tile, 8 warps, m16n8k8 mma.
// cp.async double-buffered staging, cvt after ldmatrix.
// Dynamic smem: 2 stages x (A+B) x 128x36 floats = 73728 B.
// ---------------------------------------------------------------------------
#define TRS 36
#define STG (128 * TRS)

template <int MODE>
__global__ __launch_bounds__(256) void gemm_tf32(
    const float* __restrict__ A, const float* __restrict__ W,
    const float* __restrict__ bias, const float* __restrict__ Cadd,
    float* __restrict__ C,
    int M, int N, int K, int lda, int ldw,
    long aBS, long wBS, long bBS, long cBS)
{
    extern __shared__ float sm[];

    int bz = blockIdx.z;
    A += (long)bz * aBS;
    W += (long)bz * wBS;
    C += (long)bz * cBS;
    const float* biasp = bias ? (bias + (long)bz * bBS) : nullptr;

    int tid = threadIdx.x;
    int warp = tid >> 5, lane = tid & 31;
    int wr = warp >> 2, wc = warp & 3;
    int m0 = blockIdx.y * 128, n0 = blockIdx.x * 128;

    float acc[4][4][4];
#pragma unroll
    for (int mt = 0; mt < 4; mt++)
#pragma unroll
        for (int nt = 0; nt < 4; nt++)
#pragma unroll
            for (int q = 0; q < 4; q++) acc[mt][nt][q] = 0.f;

    uint32_t smbase = (uint32_t)__cvta_generic_to_shared(sm);

    int rowA = (lane & 7) + ((lane >> 3) & 1) * 8;
    int colA = (lane >> 4) * 4;
    int rowB = (lane & 7) + (lane >> 4) * 8;
    int colB = ((lane >> 3) & 1) * 4;

    const int NIT = (K + 31) / 32;

    auto issue = [&](int it, int s) {
        int k0 = it * 32;
        uint32_t abase = smbase + (uint32_t)(s * 2 * STG) * 4u;
        uint32_t bbase = abase + (uint32_t)STG * 4u;
#pragma unroll
        for (int r = 0; r < 4; r++) {
            int idx = tid + r * 256;
            int mm = idx >> 3, k4 = idx & 7;
            int m = m0 + mm, k = k0 + k4 * 4;
            bool p = (m < M) && (k < K);
            const float* src = p ? &A[a_idx<MODE>(m, k, lda)] : A;
            cpasync16(abase + (uint32_t)(mm * TRS + k4 * 4) * 4u, src, p);
        }
#pragma unroll
        for (int r = 0; r < 4; r++) {
            int idx = tid + r * 256;
            int nn = idx >> 3, k4 = idx & 7;
            int n = n0 + nn, k = k0 + k4 * 4;
            bool p = (n < N) && (k < K);
            const float* src = p ? &W[(long)n * ldw + k] : W;
            cpasync16(bbase + (uint32_t)(nn * TRS + k4 * 4) * 4u, src, p);
        }
        asm volatile("cp.async.commit_group;");
    };

    issue(0, 0);
    for (int it = 0; it < NIT; it++) {
        int cur = it & 1;
        if (it + 1 < NIT) {
            issue(it + 1, cur ^ 1);
            asm volatile("cp.async.wait_group 1;");
        } else {
            asm volatile("cp.async.wait_group 0;");
        }
        __syncthreads();

        uint32_t asb = smbase + (uint32_t)(cur * 2 * STG) * 4u;
        uint32_t bsb = asb + (uint32_t)STG * 4u;
#pragma unroll
        for (int kk = 0; kk < 32; kk += 8) {
            uint32_t a[4][4], b[4][2];
#pragma unroll
            for (int mt = 0; mt < 4; mt++) {
                ldsm4(a[mt], asb +
                      (uint32_t)(((wr * 64 + mt * 16 + rowA) * TRS + kk + colA) * 4));
#pragma unroll
                for (int q = 0; q < 4; q++)
                    a[mt][q] = f2tf32(__uint_as_float(a[mt][q]));
            }
#pragma unroll
            for (int p = 0; p < 2; p++) {
                uint32_t r4[4];
                ldsm4(r4, bsb +
                      (uint32_t)(((wc * 32 + p * 16 + rowB) * TRS + kk + colB) * 4));
#pragma unroll
                for (int q = 0; q < 4; q++)
                    r4[q] = f2tf32(__uint_as_float(r4[q]));
                b[2 * p][0] = r4[0]; b[2 * p][1] = r4[1];
                b[2 * p + 1][0] = r4[2]; b[2 * p + 1][1] = r4[3];
            }
#pragma unroll
            for (int mt = 0; mt < 4; mt++)
#pragma unroll
                for (int nt = 0; nt < 4; nt++)
                    mma_tf32(acc[mt][nt], a[mt], b[nt]);
        }
        __syncthreads();
    }

    int lr = lane >> 2, lc = (lane & 3) * 2;
#pragma unroll
    for (int mt = 0; mt < 4; mt++) {
#pragma unroll
        for (int part = 0; part < 2; part++) {
            int m = m0 + wr * 64 + mt * 16 + lr + part * 8;
            if (m >= M) continue;
#pragma unroll
            for (int nt = 0; nt < 4; nt++) {
                int n = n0 + wc * 32 + nt * 8 + lc;
                float v0 = acc[mt][nt][part * 2 + 0];
                float v1 = acc[mt][nt][part * 2 + 1];
                if (biasp) { v0 += biasp[n]; v1 += biasp[n + 1]; }
                if (Cadd) {
                    v0 += Cadd[(long)m * N + n];
                    v1 += Cadd[(long)m * N + n + 1];
                }
                C[(long)m * N + n] = v0;
                C[(long)m * N + n + 1] = v1;
            }
        }
    }
}

// ---------------------------------------------------------------------------
// Tensor-core recurrent step. 160 blocks x 256 threads.
//   blocks [0,32):   main bi-GRU. dir = bx>>4, 64-col group jg = bx&15. K=1024.
//   blocks [32,160): gen GRU. img = (bx-32)>>1, jg = (bx-32)&1. K=128.
// Each block computes gh = h @ Whh_slice^T for 3 gates x 64 cols (N=192) via
// tf32 m16n8k8 (8 warps, 2x4, warp tile 32x48), exchanges gh through SMEM,
// fuses GRU gates, writes hout (+TXT avg for main, hmax for gen).
// Dynamic smem: 2 stages x (64+192)x36 floats = 73728 B; gh region reuses it.
// ---------------------------------------------------------------------------
#define SSTG (256 * 36)   // floats per stage (A 64 + B 192 rows)

__global__ __launch_bounds__(256) void step2_k(
    int t,
    const float* __restrict__ Whh_f, const float* __restrict__ bhh_f,
    const float* __restrict__ Whh_b, const float* __restrict__ bhh_b)
{
    extern __shared__ float sm[];
    int tid = threadIdx.x;
    int warp = tid >> 5, lane = tid & 31;
    int wr = warp >> 2, wc = warp & 3;

    bool isMain = blockIdx.x < 32;
    const float *Whh, *bhh, *hin;
    float *hout;
    int K, ldb, gs, ldh, j0, dir = 0, img = 0, tt = 0;

    if (isMain) {
        dir = blockIdx.x >> 4;
        j0  = (blockIdx.x & 15) * 64;
        Whh = dir ? Whh_b : Whh_f;
        bhh = dir ? bhh_b : bhh_f;
        float* hbase = g_scratch + O_HST + (long)dir * 131072;
        hin  = hbase + (long)(t & 1) * 65536;
        hout = hbase + (long)((t + 1) & 1) * 65536;
        tt = dir ? (31 - t) : t;
        K = 1024; ldb = 1024; gs = 1024; ldh = 1024;
    } else {
        int b2 = blockIdx.x - 32;
        img = b2 >> 1;
        j0  = (b2 & 1) * 64;
        Whh = g_scratch + O_WHH + (long)img * 49152;
        bhh = g_scratch + O_BHH + (long)img * 384;
        float* hb = g_scratch + O_HG;
        hin  = hb + (long)(t & 1) * 524288 + (long)img * 8192;
        hout = hb + (long)((t + 1) & 1) * 524288 + (long)img * 8192;
        K = 128; ldb = 128; gs = 128; ldh = 128;
    }

    float acc[2][6][4];
#pragma unroll
    for (int mt = 0; mt < 2; mt++)
#pragma unroll
        for (int nt = 0; nt < 6; nt++)
#pragma unroll
            for (int q = 0; q < 4; q++) acc[mt][nt][q] = 0.f;

    uint32_t smbase = (uint32_t)__cvta_generic_to_shared(sm);

    int rowA = (lane & 7) + ((lane >> 3) & 1) * 8;
    int colA = (lane >> 4) * 4;
    int rowB = (lane & 7) + (lane >> 4) * 8;
    int colB = ((lane >> 3) & 1) * 4;

    const int NIT = K >> 5;

    auto issue = [&](int it, int s) {
        int k0 = it * 32;
        uint32_t abase = smbase + (uint32_t)(s * SSTG) * 4u;
        uint32_t bbase = abase + (uint32_t)(64 * 36) * 4u;
        // A: 64 rows x 32 k = 512 f4, 2/thread
#pragma unroll
        for (int r = 0; r < 2; r++) {
            int idx = tid + r * 256;
            int mm = idx >> 3, k4 = idx & 7;
            cpasync16(abase + (uint32_t)(mm * 36 + k4 * 4) * 4u,
                      &hin[(long)mm * ldh + k0 + k4 * 4], true);
        }
        // B: 192 rows x 32 k = 1536 f4, 6/thread
#pragma unroll
        for (int r = 0; r < 6; r++) {
            int idx = tid + r * 256;
            int rr = idx >> 3, k4 = idx & 7;
            int g = rr >> 6, j = j0 + (rr & 63);
            cpasync16(bbase + (uint32_t)(rr * 36 + k4 * 4) * 4u,
                      &Whh[(long)(g * gs + j) * ldb + k0 + k4 * 4], true);
        }
        asm volatile("cp.async.commit_group;");
    };

    issue(0, 0);
    for (int it = 0; it < NIT; it++) {
        int cur = it & 1;
        if (it + 1 < NIT) {
            issue(it + 1, cur ^ 1);
            asm volatile("cp.async.wait_group 1;");
        } else {
            asm volatile("cp.async.wait_group 0;");
        }
        __syncthreads();

        uint32_t asb = smbase + (uint32_t)(cur * SSTG) * 4u;
        uint32_t bsb = asb + (uint32_t)(64 * 36) * 4u;
#pragma unroll
        for (int kk = 0; kk < 32; kk += 8) {
            uint32_t a[2][4], b[6][2];
#pragma unroll
            for (int mt = 0; mt < 2; mt++) {
                ldsm4(a[mt], asb +
                      (uint32_t)(((wr * 32 + mt * 16 + rowA) * 36 + kk + colA) * 4));
#pragma unroll
                for (int q = 0; q < 4; q++)
                    a[mt][q] = f2tf32(__uint_as_float(a[mt][q]));
            }
#pragma unroll
            for (int p = 0; p < 3; p++) {
                uint32_t r4[4];
                ldsm4(r4, bsb +
                      (uint32_t)(((wc * 48 + p * 16 + rowB) * 36 + kk + colB) * 4));
#pragma unroll
                for (int q = 0; q < 4; q++)
                    r4[q] = f2tf32(__uint_as_float(r4[q]));
                b[2 * p][0] = r4[0]; b[2 * p][1] = r4[1];
                b[2 * p + 1][0] = r4[2]; b[2 * p + 1][1] = r4[3];
            }
#pragma unroll
            for (int mt = 0; mt < 2; mt++)
#pragma unroll
                for (int nt = 0; nt < 6; nt++)
                    mma_tf32(acc[mt][nt], a[mt], b[nt]);
        }
        __syncthreads();
    }

    // exchange gh through smem: gh[m*192 + rr], rr = gate*64 + j
    int lr = lane >> 2, lc = (lane & 3) * 2;
#pragma unroll
    for (int mt = 0; mt < 2; mt++)
#pragma unroll
        for (int nt = 0; nt < 6; nt++)
#pragma unroll
            for (int q = 0; q < 4; q++) {
                int m = wr * 32 + mt * 16 + lr + (q >> 1) * 8;
                int rr = wc * 48 + nt * 8 + lc + (q & 1);
                sm[m * 192 + rr] = acc[mt][nt][q];
            }
    __syncthreads();

    // gate fusion: 256 threads = 64 j x 4 m-groups, 16 m each
    int jj = tid & 63;
    int mg = tid >> 6;
    int col = j0 + jj;

    if (isMain) {
        const float* gi = g_scratch + O_GIALL + (long)dir * 3072;
        float* txt = g_scratch + O_TXT;
        float br = bhh[col], bz2 = bhh[1024 + col], bn = bhh[2048 + col];
        bool storeFirst = dir == 0 ? (tt < 16) : (tt >= 16);
#pragma unroll
        for (int i = 0; i < 16; i++) {
            int m = mg * 16 + i;
            const float* girow = gi + ((long)tt * 64 + m) * 6272;
            const float* ghr = sm + m * 192;
            float r = sigf(girow[col] + ghr[jj] + br);
            float z = sigf(girow[1024 + col] + ghr[64 + jj] + bz2);
            float n = tanhf(girow[2048 + col] + r * (ghr[128 + jj] + bn));
            float hold = hin[m * 1024 + col];
            float hn = (1.f - z) * n + z * hold;
            hout[m * 1024 + col] = hn;
            long ti = ((long)m * 32 + tt) * 1024 + col;
            if (storeFirst) txt[ti] = 0.5f * hn;
            else            txt[ti] += 0.5f * hn;
        }
    } else {
        const float* gi = g_scratch + O_GIG + (long)img * 786432 + (long)t * 24576;
        float* hmax = g_scratch + O_HMAX + (long)img * 8192;
        float br = bhh[col], bz2 = bhh[128 + col], bn = bhh[256 + col];
#pragma unroll
        for (int i = 0; i < 16; i++) {
            int m = mg * 16 + i;
            const float* girow = gi + m * 384;
            const float* ghr = sm + m * 192;
            float r = sigf(girow[col] + ghr[jj] + br);
            float z = sigf(girow[128 + col] + ghr[64 + jj] + bz2);
            float n = tanhf(girow[256 + col] + r * (ghr[128 + jj] + bn));
            float hold = hin[m * 128 + col];
            float hn = (1.f - z) * n + z * hold;
            hout[m * 128 + col] = hn;
            hmax[m * 128 + col] = fmaxf(hmax[m * 128 + col], hn);
        }
    }
}

// ---------------------------------------------------------------------------
// Fused image path: region mean -> IEG, l2norm -> IVN, reduce-proj -> IGV.
// One block per image. 256 threads.
// ---------------------------------------------------------------------------
__global__ __launch_bounds__(256) void imgvec_k(
    const float* __restrict__ img_embed,
    const float* __restrict__ W_reduce_img, const float* __restrict__ b_reduce_img)
{
    __shared__ float s_ieg[1024];
    __shared__ float red[256];
    int b = blockIdx.x, tid = threadIdx.x;
    float vals[4], ss = 0.f;
#pragma unroll
    for (int i = 0; i < 4; i++) {
        int c = i * 256 + tid;
        float s = 0.f;
        for (int g = 0; g < 36; g++) s += img_embed[(long)b * 36864 + (long)g * 1024 + c];
        s *= (1.f / 36.f);
        vals[i] = s;
        ss += s * s;
        s_ieg[c] = s;
        g_scratch[O_IEG + (long)b * 1024 + c] = s;
    }
    red[tid] = ss;
    __syncthreads();
    for (int o = 128; o > 0; o >>= 1) { if (tid < o) red[tid] += red[tid + o]; __syncthreads(); }
    float inv = 1.f / (sqrtf(red[0]) + 1e-8f);
#pragma unroll
    for (int i = 0; i < 4; i++) {
        int c = i * 256 + tid;
        g_scratch[O_IVN + (long)b * 1024 + c] = vals[i] * inv;
    }
    // reduce projection: IGV[b,o] = dot(IEG[b,:], W[o,:]) + bias[o]
    int o = tid >> 1, half = tid & 1;
    const float* wrow = W_reduce_img + (long)o * 1024 + half * 512;
    const float* xrow = s_ieg + half * 512;
    float acc = 0.f;
#pragma unroll 4
    for (int k = 0; k < 512; k += 4) {
        float4 w = *reinterpret_cast<const float4*>(&wrow[k]);
        float4 x = *reinterpret_cast<const float4*>(&xrow[k]);
        acc += w.x * x.x + w.y * x.y + w.z * x.z + w.w * x.w;
    }
    acc += __shfl_xor_sync(0xffffffffu, acc, 1);
    if (half == 0)
        g_scratch[O_IGV + (long)b * 128 + o] = acc + b_reduce_img[o];
}

// attention scores + softmax over fused QKV buffer (row stride 1280)
__global__ __launch_bounds__(256) void attn_k() {
    int gw = (blockIdx.x * blockDim.x + threadIdx.x) >> 5;
    int lane = threadIdx.x & 31;
    if (gw >= 2048) return;
    int b = gw >> 5;
    const float* qr = g_scratch + O_QKV + (long)gw * 1280;
    const float* kr = g_scratch + O_QKV + ((long)b * 32 + lane) * 1280 + 128;
    float s = 0.f;
#pragma unroll 8
    for (int o = 0; o < 128; o++) s += qr[o] * kr[o];
    float mx = s;
#pragma unroll
    for (int off = 16; off > 0; off >>= 1) mx = fmaxf(mx, __shfl_xor_sync(0xffffffffu, mx, off));
    float e = expf(s - mx);
    float sum = e;
#pragma unroll
    for (int off = 16; off > 0; off >>= 1) sum += __shfl_xor_sync(0xffffffffu, sum, off);
    g_scratch[O_ATT + (long)gw * 32 + lane] = e / sum;
}

__global__ __launch_bounds__(32) void aw_k(const int* __restrict__ lens) {
    int b = blockIdx.x, s = threadIdx.x;
    int len = lens[b];
    float a = 0.f;
    for (int tt = 0; tt < len; tt++) a += g_scratch[O_ATT + ((long)b * 32 + tt) * 32 + s];
    g_scratch[O_AW + b * 32 + s] = a;
}

__global__ __launch_bounds__(256) void txt_embed_k(const int* __restrict__ lens,
                                                   const float* __restrict__ gamma) {
    int b = blockIdx.y;
    int c = blockIdx.x * 256 + threadIdx.x;
    __shared__ float saw[32];
    if (threadIdx.x < 32) saw[threadIdx.x] = g_scratch[O_AW + b * 32 + threadIdx.x];
    __syncthreads();
    int len = lens[b];
    float g = *gamma;
    float a1 = 0.f;
    for (int tt = 0; tt < len; tt++) a1 += g_scratch[O_TXT + ((long)b * 32 + tt) * 1024 + c];
    float a2 = 0.f;
#pragma unroll
    for (int s = 0; s < 32; s++)
        a2 += saw[s] * g_scratch[O_QKV + ((long)b * 32 + s) * 1280 + 256 + c];
    g_scratch[O_TE + (long)b * 1024 + c] = (a1 + g * a2) / (float)len;
}

// sims[i,b] = (y . iv_i) / (|y| + eps)
__global__ __launch_bounds__(256) void sims_k(float* __restrict__ out) {
    int img = blockIdx.y, b = blockIdx.x;
    int tid = threadIdx.x;
    const float* y = g_scratch + O_Y + (long)img * 65536 + (long)b * 1024;
    const float* iv = g_scratch + O_IVN + (long)img * 1024;
    float ss = 0.f, dp = 0.f;
#pragma unroll
    for (int i = 0; i < 4; i++) {
        int c = i * 256 + tid;
        float v = y[c];
        ss += v * v;
        dp += v * iv[c];
    }
    __shared__ float r1[256], r2[256];
    r1[tid] = ss; r2[tid] = dp;
    __syncthreads();
    for (int o = 128; o > 0; o >>= 1) {
        if (tid < o) { r1[tid] += r1[tid + o]; r2[tid] += r2[tid + o]; }
        __syncthreads();
    }
    if (tid == 0) out[img * 64 + b] = r2[0] / (sqrtf(r1[0]) + 1e-8f);
}

// ---------------------------------------------------------------------------
extern "C" void kernel_launch(void* const* d_in, const int* in_sizes, int n_in,
                              void* d_out, int out_size) {
    const float* img_embed    = (const float*)d_in[0];
    const float* cap_embed    = (const float*)d_in[1];
    const int*   lens         = (const int*)d_in[2];
    const float* W_reduce_img = (const float*)d_in[3];
    const float* b_reduce_img = (const float*)d_in[4];
    const float* W_reduce_txt = (const float*)d_in[5];
    const float* b_reduce_txt = (const float*)d_in[6];
    const float* gru_Wih_f    = (const float*)d_in[7];
    const float* gru_Whh_f    = (const float*)d_in[8];
    const float* gru_bih_f    = (const float*)d_in[9];
    const float* gru_bhh_f    = (const float*)d_in[10];
    const float* gru_Wih_b    = (const float*)d_in[11];
    const float* gru_Whh_b    = (const float*)d_in[12];
    const float* gru_bih_b    = (const float*)d_in[13];
    const float* gru_bhh_b    = (const float*)d_in[14];
    const float* sa_Wq        = (const float*)d_in[15];
    const float* sa_bq        = (const float*)d_in[16];
    const float* sa_Wk        = (const float*)d_in[17];
    const float* sa_bk        = (const float*)d_in[18];
    const float* sa_Wv        = (const float*)d_in[19];
    const float* sa_bv        = (const float*)d_in[20];
    const float* sa_gamma     = (const float*)d_in[21];
    const float* gen_Wih      = (const float*)d_in[22];
    const float* gen_bih      = (const float*)d_in[23];
    const float* gen_Whh      = (const float*)d_in[24];
    const float* gen_bhh      = (const float*)d_in[25];
    const float* gen_Wbih     = (const float*)d_in[26];
    const float* gen_bbih     = (const float*)d_in[27];
    const float* gen_Wbhh     = (const float*)d_in[28];
    const float* gen_bbhh     = (const float*)d_in[29];
    const float* W_txt_fc     = (const float*)d_in[30];
    const float* b_txt_fc     = (const float*)d_in[31];

    float* S = nullptr;
    cudaGetSymbolAddress((void**)&S, g_scratch);

    const int SMEM_TF32 = 2 * 2 * STG * 4;   // 73728 B
    const int SMEM_STEP = 2 * SSTG * 4;      // 73728 B
    cudaFuncSetAttribute(gemm_tf32<0>, cudaFuncAttributeMaxDynamicSharedMemorySize, SMEM_TF32);
    cudaFuncSetAttribute(gemm_tf32<1>, cudaFuncAttributeMaxDynamicSharedMemorySize, SMEM_TF32);
    cudaFuncSetAttribute(step2_k, cudaFuncAttributeMaxDynamicSharedMemorySize, SMEM_STEP);

    init_k<<<4096, 256>>>();

    // Concatenate weights for fused GEMMs (D2D copies, graph-capturable)
    cudaMemcpyAsync(S + O_WGI,              gru_Wih_f,    3072L*300*4, cudaMemcpyDeviceToDevice);
    cudaMemcpyAsync(S + O_WGI + 3072L*300,  gru_Wih_b,    3072L*300*4, cudaMemcpyDeviceToDevice);
    cudaMemcpyAsync(S + O_WGI + 6144L*300,  W_reduce_txt, 128L*300*4,  cudaMemcpyDeviceToDevice);
    cudaMemcpyAsync(S + O_BGI,              gru_bih_f,    3072L*4,     cudaMemcpyDeviceToDevice);
    cudaMemcpyAsync(S + O_BGI + 3072,       gru_bih_b,    3072L*4,     cudaMemcpyDeviceToDevice);
    cudaMemcpyAsync(S + O_BGI + 6144,       b_reduce_txt, 128L*4,      cudaMemcpyDeviceToDevice);
    cudaMemcpyAsync(S + O_WQKV,             sa_Wq,        128L*1024*4, cudaMemcpyDeviceToDevice);
    cudaMemcpyAsync(S + O_WQKV + 128L*1024, sa_Wk,        128L*1024*4, cudaMemcpyDeviceToDevice);
    cudaMemcpyAsync(S + O_WQKV + 256L*1024, sa_Wv,        1024L*1024*4,cudaMemcpyDeviceToDevice);
    cudaMemcpyAsync(S + O_BQKV,             sa_bq,        128L*4,      cudaMemcpyDeviceToDevice);
    cudaMemcpyAsync(S + O_BQKV + 128,       sa_bk,        128L*4,      cudaMemcpyDeviceToDevice);
    cudaMemcpyAsync(S + O_BQKV + 256,       sa_bv,        1024L*4,     cudaMemcpyDeviceToDevice);

    // Fused GI_f|GI_b|CR projection: (T*B, 6272)
    gemm_tf32<1><<<dim3(49, 16, 1), 256, SMEM_TF32>>>(
        cap_embed, S + O_WGI, S + O_BGI, nullptr, S + O_GIALL,
        2048, 6272, 300, 300, 300, 0, 0, 0, 0);

    // image path: pool + l2norm + reduce projection, fused
    imgvec_k<<<64, 256>>>(img_embed, W_reduce_img, b_reduce_img);

    // generated GRU weights per image
    gemm_tf32<0><<<dim3(384, 1, 1), 256, SMEM_TF32>>>(
        S + O_IGV, gen_Wih, gen_bih, nullptr, S + O_WIH,
        64, 49152, 128, 128, 128, 0, 0, 0, 0);
    gemm_tf32<0><<<dim3(384, 1, 1), 256, SMEM_TF32>>>(
        S + O_IGV, gen_Whh, gen_bhh, nullptr, S + O_WHH,
        64, 49152, 128, 128, 128, 0, 0, 0, 0);
    gemm_tf32<0><<<dim3(3, 1, 1), 256, SMEM_TF32>>>(
        S + O_IGV, gen_Wbih, gen_bbih, nullptr, S + O_BIH,
        64, 384, 128, 128, 128, 0, 0, 0, 0);
    gemm_tf32<0><<<dim3(3, 1, 1), 256, SMEM_TF32>>>(
        S + O_IGV, gen_Wbhh, gen_bbhh, nullptr, S + O_BHH,
        64, 384, 128, 128, 128, 0, 0, 0, 0);

    // gi_gen: A = CR columns of GIALL (lda 6272), batched over 64 images
    gemm_tf32<0><<<dim3(3, 16, 64), 256, SMEM_TF32>>>(
        S + O_GIALL + 6144, S + O_WIH, S + O_BIH, nullptr, S + O_GIG,
        2048, 384, 128, 6272, 128, 0, 49152, 384, 786432);

    // 32 tensor-core recurrent steps (main bi-GRU + gen GRU + TXT fold-in)
    for (int t = 0; t < 32; t++)
        step2_k<<<160, 256, SMEM_STEP>>>(t, gru_Whh_f, gru_bhh_f, gru_Whh_b, gru_bhh_b);

    // fused Q|K|V projection: (B*T, 1280)
    gemm_tf32<0><<<dim3(10, 16, 1), 256, SMEM_TF32>>>(
        S + O_TXT, S + O_WQKV, S + O_BQKV, nullptr, S + O_QKV,
        2048, 1280, 1024, 1024, 1024, 0, 0, 0, 0);
    attn_k<<<256, 256>>>();
    aw_k<<<64, 32>>>(lens);
    txt_embed_k<<<dim3(4, 64), 256>>>(lens, sa_gamma);

    // final FC: shared part + per-image correction
    gemm_tf32<0><<<dim3(8, 1, 1), 256, SMEM_TF32>>>(
        S + O_TE, W_txt_fc, b_txt_fc, nullptr, S + O_FCB,
        64, 1024, 1024, 1024, 1152, 0, 0, 0, 0);
    gemm_tf32<0><<<dim3(8, 1, 64), 256, SMEM_TF32>>>(
        S + O_HMAX, W_txt_fc + 1024, nullptr, S + O_FCB, S + O_Y,
        64, 1024, 128, 128, 1152, 64L * 128, 0, 0, 64L * 1024);

    sims_k<<<dim3(64, 64), 256>>>((float*)d_out);
}

// round 13
// speedup vs baseline: 3.1373x; 1.1084x over previous
#include <cuda_runtime.h>
#include <cuda_bf16.h>
#include <math.h>
#include <stdint.h>

// ---------------------------------------------------------------------------
// Problem constants:  L=1024, R=128, T=32, B=64, DIN=300, REG=36, R3=384, H3=3072
// ---------------------------------------------------------------------------

// ---------------- scratch layout (floats) ----------------
#define SZ_GIALL   (2048L*6272)      // fused [GI_f | GI_b | CR] rows (t*64+b)
#define SZ_TXT     (64L*32*1024)
#define SZ_HST     (2L*2*64*1024)
#define SZ_WGI     (6272L*300)
#define SZ_BGI     (6400L)
#define SZ_QKV     (2048L*1280)
#define SZ_WQKV    (1280L*1024)
#define SZ_BQKV    (1280L)
#define SZ_ATT     (2048L*32)
#define SZ_AW      (64L*32)
#define SZ_TE      (64L*1024)
#define SZ_IEG     (64L*1024)
#define SZ_IVN     (64L*1024)
#define SZ_IGV     (64L*128)
#define SZ_WG      (64L*49152)
#define SZ_BG      (64L*384)
#define SZ_HG      (2L*64*64*128)
#define SZ_HMAX    (64L*64*128)
#define SZ_FCB     (64L*1024)
#define SZ_Y       (64L*64*1024)

#define O_GIALL 0L
#define O_TXT   (O_GIALL + SZ_GIALL)
#define O_HST   (O_TXT + SZ_TXT)
#define O_WGI   (O_HST + SZ_HST)
#define O_BGI   (O_WGI + SZ_WGI)
#define O_QKV   (O_BGI + SZ_BGI)
#define O_WQKV  (O_QKV + SZ_QKV)
#define O_BQKV  (O_WQKV + SZ_WQKV)
#define O_ATT   (O_BQKV + SZ_BQKV)
#define O_AW    (O_ATT + SZ_ATT)
#define O_TE    (O_AW + SZ_AW)
#define O_IEG   (O_TE + SZ_TE)
#define O_IVN   (O_IEG + SZ_IEG)
#define O_IGV   (O_IVN + SZ_IVN)
#define O_WIH   (O_IGV + SZ_IGV)
#define O_WHH   (O_WIH + SZ_WG)
#define O_BIH   (O_WHH + SZ_WG)
#define O_BHH   (O_BIH + SZ_BG)
#define O_HG    (O_BHH + SZ_BG)
#define O_HMAX  (O_HG + SZ_HG)
#define O_FCB   (O_HMAX + SZ_HMAX)
#define O_Y     (O_FCB + SZ_FCB)
#define SCRATCH_TOTAL (O_Y + SZ_Y)

__device__ float g_scratch[SCRATCH_TOTAL];

__device__ __forceinline__ float sigf(float x) { return 1.f / (1.f + expf(-x)); }

__device__ __forceinline__ uint32_t f2tf32(float x) {
    uint32_t r;
    asm("cvt.rna.tf32.f32 %0, %1;" : "=r"(r) : "f"(x));
    return r;
}

__device__ __forceinline__ void ldsm4(uint32_t* r, uint32_t addr) {
    asm volatile("ldmatrix.sync.aligned.m8n8.x4.shared.b16 {%0,%1,%2,%3}, [%4];"
                 : "=r"(r[0]), "=r"(r[1]), "=r"(r[2]), "=r"(r[3]) : "r"(addr));
}

__device__ __forceinline__ void mma_tf32(float* c, const uint32_t* a, const uint32_t* b) {
    asm volatile(
        "mma.sync.aligned.m16n8k8.row.col.f32.tf32.tf32.f32 "
        "{%0,%1,%2,%3}, {%4,%5,%6,%7}, {%8,%9}, {%0,%1,%2,%3};"
        : "+f"(c[0]), "+f"(c[1]), "+f"(c[2]), "+f"(c[3])
        : "r"(a[0]), "r"(a[1]), "r"(a[2]), "r"(a[3]), "r"(b[0]), "r"(b[1]));
}

__device__ __forceinline__ void cpasync16(uint32_t dst, const void* src, bool pred) {
    int sz = pred ? 16 : 0;
    asm volatile("cp.async.cg.shared.global [%0], [%1], 16, %2;"
                 :: "r"(dst), "l"(src), "r"(sz));
}

// ---------------------------------------------------------------------------
__global__ __launch_bounds__(256) void init_k() {
    long idx = (long)blockIdx.x * 256 + threadIdx.x;
    if (idx < SZ_HST)  g_scratch[O_HST + idx] = 0.f;
    if (idx < SZ_HG)   g_scratch[O_HG + idx] = 0.f;
    if (idx < SZ_HMAX) g_scratch[O_HMAX + idx] = -1e30f;
}

// ---------------------------------------------------------------------------
// A indexing modes:
//   0: A[m*lda + k]
//   1: m=t*64+b over cap_embed (B,T,300):  A[(m&63)*9600 + (m>>6)*300 + k]
// ---------------------------------------------------------------------------
template <int MODE>
__device__ __forceinline__ long a_idx(int m, int k, int lda) {
    if (MODE == 0) return (long)m * lda + k;
    { int b = m & 63, t = m >> 6; return (long)b * 9600 + (long)t * 300 + k; }
}

// ---------------------------------------------------------------------------
// TF32 tensor-core GEMM: 128x128 tile, 8 warps, m16n8k8 mma.
// cp.async double-buffered staging, cvt after ldmatrix.
// Dynamic smem: 2 stages x (A+B) x 128x36 floats = 73728 B.
// ---------------------------------------------------------------------------
#define TRS 36
#define STG (128 * TRS)

template <int MODE>
__global__ __launch_bounds__(256) void gemm_tf32(
    const float* __restrict__ A, const float* __restrict__ W,
    const float* __restrict__ bias, const float* __restrict__ Cadd,
    float* __restrict__ C,
    int M, int N, int K, int lda, int ldw,
    long aBS, long wBS, long bBS, long cBS)
{
    extern __shared__ float sm[];

    int bz = blockIdx.z;
    A += (long)bz * aBS;
    W += (long)bz * wBS;
    C += (long)bz * cBS;
    const float* biasp = bias ? (bias + (long)bz * bBS) : nullptr;

    int tid = threadIdx.x;
    int warp = tid >> 5, lane = tid & 31;
    int wr = warp >> 2, wc = warp & 3;
    int m0 = blockIdx.y * 128, n0 = blockIdx.x * 128;

    float acc[4][4][4];
#pragma unroll
    for (int mt = 0; mt < 4; mt++)
#pragma unroll
        for (int nt = 0; nt < 4; nt++)
#pragma unroll
            for (int q = 0; q < 4; q++) acc[mt][nt][q] = 0.f;

    uint32_t smbase = (uint32_t)__cvta_generic_to_shared(sm);

    int rowA = (lane & 7) + ((lane >> 3) & 1) * 8;
    int colA = (lane >> 4) * 4;
    int rowB = (lane & 7) + (lane >> 4) * 8;
    int colB = ((lane >> 3) & 1) * 4;

    const int NIT = (K + 31) / 32;

    auto issue = [&](int it, int s) {
        int k0 = it * 32;
        uint32_t abase = smbase + (uint32_t)(s * 2 * STG) * 4u;
        uint32_t bbase = abase + (uint32_t)STG * 4u;
#pragma unroll
        for (int r = 0; r < 4; r++) {
            int idx = tid + r * 256;
            int mm = idx >> 3, k4 = idx & 7;
            int m = m0 + mm, k = k0 + k4 * 4;
            bool p = (m < M) && (k < K);
            const float* src = p ? &A[a_idx<MODE>(m, k, lda)] : A;
            cpasync16(abase + (uint32_t)(mm * TRS + k4 * 4) * 4u, src, p);
        }
#pragma unroll
        for (int r = 0; r < 4; r++) {
            int idx = tid + r * 256;
            int nn = idx >> 3, k4 = idx & 7;
            int n = n0 + nn, k = k0 + k4 * 4;
            bool p = (n < N) && (k < K);
            const float* src = p ? &W[(long)n * ldw + k] : W;
            cpasync16(bbase + (uint32_t)(nn * TRS + k4 * 4) * 4u, src, p);
        }
        asm volatile("cp.async.commit_group;");
    };

    issue(0, 0);
    for (int it = 0; it < NIT; it++) {
        int cur = it & 1;
        if (it + 1 < NIT) {
            issue(it + 1, cur ^ 1);
            asm volatile("cp.async.wait_group 1;");
        } else {
            asm volatile("cp.async.wait_group 0;");
        }
        __syncthreads();

        uint32_t asb = smbase + (uint32_t)(cur * 2 * STG) * 4u;
        uint32_t bsb = asb + (uint32_t)STG * 4u;
#pragma unroll
        for (int kk = 0; kk < 32; kk += 8) {
            uint32_t a[4][4], b[4][2];
#pragma unroll
            for (int mt = 0; mt < 4; mt++) {
                ldsm4(a[mt], asb +
                      (uint32_t)(((wr * 64 + mt * 16 + rowA) * TRS + kk + colA) * 4));
#pragma unroll
                for (int q = 0; q < 4; q++)
                    a[mt][q] = f2tf32(__uint_as_float(a[mt][q]));
            }
#pragma unroll
            for (int p = 0; p < 2; p++) {
                uint32_t r4[4];
                ldsm4(r4, bsb +
                      (uint32_t)(((wc * 32 + p * 16 + rowB) * TRS + kk + colB) * 4));
#pragma unroll
                for (int q = 0; q < 4; q++)
                    r4[q] = f2tf32(__uint_as_float(r4[q]));
                b[2 * p][0] = r4[0]; b[2 * p][1] = r4[1];
                b[2 * p + 1][0] = r4[2]; b[2 * p + 1][1] = r4[3];
            }
#pragma unroll
            for (int mt = 0; mt < 4; mt++)
#pragma unroll
                for (int nt = 0; nt < 4; nt++)
                    mma_tf32(acc[mt][nt], a[mt], b[nt]);
        }
        __syncthreads();
    }

    int lr = lane >> 2, lc = (lane & 3) * 2;
#pragma unroll
    for (int mt = 0; mt < 4; mt++) {
#pragma unroll
        for (int part = 0; part < 2; part++) {
            int m = m0 + wr * 64 + mt * 16 + lr + part * 8;
            if (m >= M) continue;
#pragma unroll
            for (int nt = 0; nt < 4; nt++) {
                int n = n0 + wc * 32 + nt * 8 + lc;
                float v0 = acc[mt][nt][part * 2 + 0];
                float v1 = acc[mt][nt][part * 2 + 1];
                if (biasp) { v0 += biasp[n]; v1 += biasp[n + 1]; }
                if (Cadd) {
                    v0 += Cadd[(long)m * N + n];
                    v1 += Cadd[(long)m * N + n + 1];
                }
                C[(long)m * N + n] = v0;
                C[(long)m * N + n + 1] = v1;
            }
        }
    }
}

// ---------------------------------------------------------------------------
// Tensor-core recurrent step v3. 320 blocks x 256 threads.
//   blocks [0,64):    main bi-GRU. dir = bx>>5, 32-col group (bx&31). K=1024.
//   blocks [64,320):  gen GRU. img = (bx-64)>>2, 32-col group. K=128 x 2
//                     passes (gh vs h/Whh_g, gi vs cr_t/Wih_g -- GIG removed).
// Unified GEMM: M=64, N=96 (3 gates x 32 cols), 8 warps (4x2), warp 16x48.
// SMEM (floats): staging 2 x 5760 = [0,11520); gh at 11520; gi at 17664.
// Total 23808 floats -> 98304 B dynamic (2 blocks/SM).
// ---------------------------------------------------------------------------
#define SSTRIDE 5760
#define X_GH 11520
#define X_GI 17664

__global__ __launch_bounds__(256, 2) void step3_k(
    int t,
    const float* __restrict__ Whh_f, const float* __restrict__ bhh_f,
    const float* __restrict__ Whh_b, const float* __restrict__ bhh_b)
{
    extern __shared__ float sm[];
    int tid = threadIdx.x;
    int warp = tid >> 5, lane = tid & 31;
    int wr = warp >> 1, wc = warp & 1;
    uint32_t smbase = (uint32_t)__cvta_generic_to_shared(sm);

    int rowA = (lane & 7) + ((lane >> 3) & 1) * 8;
    int colA = (lane >> 4) * 4;
    int rowB = (lane & 7) + (lane >> 4) * 8;
    int colB = ((lane >> 3) & 1) * 4;
    int lr = lane >> 2, lc = (lane & 3) * 2;

    bool isMain = blockIdx.x < 64;

    // unified GEMM: C(64 x 96) = A(64 x K) @ B^T, B rows = (g*gs + j0 + j)
    auto run_gemm = [&](const float* Ap, int ldA, const float* Bp, int ldb,
                        int gs, int K, int j0, int xoff) {
        float acc[6][4];
#pragma unroll
        for (int nt = 0; nt < 6; nt++)
#pragma unroll
            for (int q = 0; q < 4; q++) acc[nt][q] = 0.f;

        const int NIT = K >> 5;
        auto issue = [&](int it, int s) {
            int k0 = it * 32;
            uint32_t ab = smbase + (uint32_t)(s * SSTRIDE) * 4u;
            uint32_t bb = ab + 2304u * 4u;   // 64*36 floats
#pragma unroll
            for (int r = 0; r < 2; r++) {
                int idx = tid + r * 256;
                int mm = idx >> 3, k4 = idx & 7;
                cpasync16(ab + (uint32_t)(mm * 36 + k4 * 4) * 4u,
                          Ap + (long)mm * ldA + k0 + k4 * 4, true);
            }
#pragma unroll
            for (int r = 0; r < 3; r++) {
                int idx = tid + r * 256;
                int rr = idx >> 3, k4 = idx & 7;
                int g = rr >> 5, j = j0 + (rr & 31);
                cpasync16(bb + (uint32_t)(rr * 36 + k4 * 4) * 4u,
                          Bp + (long)(g * gs + j) * ldb + k0 + k4 * 4, true);
            }
            asm volatile("cp.async.commit_group;");
        };

        issue(0, 0);
        for (int it = 0; it < NIT; it++) {
            int cur = it & 1;
            if (it + 1 < NIT) {
                issue(it + 1, cur ^ 1);
                asm volatile("cp.async.wait_group 1;");
            } else {
                asm volatile("cp.async.wait_group 0;");
            }
            __syncthreads();

            uint32_t ab = smbase + (uint32_t)(cur * SSTRIDE) * 4u;
            uint32_t bb = ab + 2304u * 4u;
#pragma unroll
            for (int kk = 0; kk < 32; kk += 8) {
                uint32_t a[4], b[6][2];
                ldsm4(a, ab + (uint32_t)(((wr * 16 + rowA) * 36 + kk + colA) * 4));
#pragma unroll
                for (int q = 0; q < 4; q++)
                    a[q] = f2tf32(__uint_as_float(a[q]));
#pragma unroll
                for (int p = 0; p < 3; p++) {
                    uint32_t r4[4];
                    ldsm4(r4, bb + (uint32_t)(((wc * 48 + p * 16 + rowB) * 36 + kk + colB) * 4));
#pragma unroll
                    for (int q = 0; q < 4; q++)
                        r4[q] = f2tf32(__uint_as_float(r4[q]));
                    b[2 * p][0] = r4[0]; b[2 * p][1] = r4[1];
                    b[2 * p + 1][0] = r4[2]; b[2 * p + 1][1] = r4[3];
                }
#pragma unroll
                for (int nt = 0; nt < 6; nt++)
                    mma_tf32(acc[nt], a, b[nt]);
            }
            __syncthreads();
        }

        // fragment -> smem exchange (row stride 96)
#pragma unroll
        for (int nt = 0; nt < 6; nt++)
#pragma unroll
            for (int q = 0; q < 4; q++) {
                int m = wr * 16 + lr + (q >> 1) * 8;
                int rr = wc * 48 + nt * 8 + lc + (q & 1);
                sm[xoff + m * 96 + rr] = acc[nt][q];
            }
        __syncthreads();
    };

    if (isMain) {
        int dir = blockIdx.x >> 5;
        int j0 = (blockIdx.x & 31) * 32;
        const float* Whh = dir ? Whh_b : Whh_f;
        const float* bhh = dir ? bhh_b : bhh_f;
        float* hbase = g_scratch + O_HST + (long)dir * 131072;
        const float* hin = hbase + (long)(t & 1) * 65536;
        float* hout = hbase + (long)((t + 1) & 1) * 65536;
        int tt = dir ? (31 - t) : t;

        run_gemm(hin, 1024, Whh, 1024, 1024, 1024, j0, X_GH);

        int j = tid & 31, mg = tid >> 5;
        int col = j0 + j;
        const float* gi = g_scratch + O_GIALL + (long)dir * 3072;
        float* txt = g_scratch + O_TXT;
        float br = bhh[col], bz2 = bhh[1024 + col], bn = bhh[2048 + col];
        bool storeFirst = dir == 0 ? (tt < 16) : (tt >= 16);
#pragma unroll
        for (int i = 0; i < 8; i++) {
            int m = mg * 8 + i;
            const float* girow = gi + ((long)tt * 64 + m) * 6272;
            float gh_r = sm[X_GH + m * 96 + j];
            float gh_z = sm[X_GH + m * 96 + 32 + j];
            float gh_n = sm[X_GH + m * 96 + 64 + j];
            float r = sigf(girow[col] + gh_r + br);
            float z = sigf(girow[1024 + col] + gh_z + bz2);
            float n = tanhf(girow[2048 + col] + r * (gh_n + bn));
            float hold = hin[m * 1024 + col];
            float hn = (1.f - z) * n + z * hold;
            hout[m * 1024 + col] = hn;
            long ti = ((long)m * 32 + tt) * 1024 + col;
            if (storeFirst) txt[ti] = 0.5f * hn;
            else            txt[ti] += 0.5f * hn;
        }
    } else {
        int b2 = blockIdx.x - 64;
        int img = b2 >> 2;
        int j0 = (b2 & 3) * 32;
        const float* Whh = g_scratch + O_WHH + (long)img * 49152;
        const float* Wih = g_scratch + O_WIH + (long)img * 49152;
        const float* bhh = g_scratch + O_BHH + (long)img * 384;
        const float* bih = g_scratch + O_BIH + (long)img * 384;
        float* hb = g_scratch + O_HG;
        const float* hin = hb + (long)(t & 1) * 524288 + (long)img * 8192;
        float* hout = hb + (long)((t + 1) & 1) * 524288 + (long)img * 8192;
        float* hmax = g_scratch + O_HMAX + (long)img * 8192;
        const float* crbase = g_scratch + O_GIALL + (long)t * 64 * 6272 + 6144;

        run_gemm(hin, 128, Whh, 128, 128, 128, j0, X_GH);
        run_gemm(crbase, 6272, Wih, 128, 128, 128, j0, X_GI);

        int j = tid & 31, mg = tid >> 5;
        int col = j0 + j;
        float cr_ = bih[col] + bhh[col];
        float cz_ = bih[128 + col] + bhh[128 + col];
        float bni = bih[256 + col], bnh = bhh[256 + col];
#pragma unroll
        for (int i = 0; i < 8; i++) {
            int m = mg * 8 + i;
            float gh_r = sm[X_GH + m * 96 + j];
            float gh_z = sm[X_GH + m * 96 + 32 + j];
            float gh_n = sm[X_GH + m * 96 + 64 + j];
            float gi_r = sm[X_GI + m * 96 + j];
            float gi_z = sm[X_GI + m * 96 + 32 + j];
            float gi_n = sm[X_GI + m * 96 + 64 + j];
            float r = sigf(gi_r + gh_r + cr_);
            float z = sigf(gi_z + gh_z + cz_);
            float n = tanhf(gi_n + bni + r * (gh_n + bnh));
            float hold = hin[m * 128 + col];
            float hn = (1.f - z) * n + z * hold;
            hout[m * 128 + col] = hn;
            hmax[m * 128 + col] = fmaxf(hmax[m * 128 + col], hn);
        }
    }
}

// ---------------------------------------------------------------------------
// Fused image path: region mean -> IEG, l2norm -> IVN, reduce-proj -> IGV.
// ---------------------------------------------------------------------------
__global__ __launch_bounds__(256) void imgvec_k(
    const float* __restrict__ img_embed,
    const float* __restrict__ W_reduce_img, const float* __restrict__ b_reduce_img)
{
    __shared__ float s_ieg[1024];
    __shared__ float red[256];
    int b = blockIdx.x, tid = threadIdx.x;
    float vals[4], ss = 0.f;
#pragma unroll
    for (int i = 0; i < 4; i++) {
        int c = i * 256 + tid;
        float s = 0.f;
        for (int g = 0; g < 36; g++) s += img_embed[(long)b * 36864 + (long)g * 1024 + c];
        s *= (1.f / 36.f);
        vals[i] = s;
        ss += s * s;
        s_ieg[c] = s;
        g_scratch[O_IEG + (long)b * 1024 + c] = s;
    }
    red[tid] = ss;
    __syncthreads();
    for (int o = 128; o > 0; o >>= 1) { if (tid < o) red[tid] += red[tid + o]; __syncthreads(); }
    float inv = 1.f / (sqrtf(red[0]) + 1e-8f);
#pragma unroll
    for (int i = 0; i < 4; i++) {
        int c = i * 256 + tid;
        g_scratch[O_IVN + (long)b * 1024 + c] = vals[i] * inv;
    }
    int o = tid >> 1, half = tid & 1;
    const float* wrow = W_reduce_img + (long)o * 1024 + half * 512;
    const float* xrow = s_ieg + half * 512;
    float acc = 0.f;
#pragma unroll 4
    for (int k = 0; k < 512; k += 4) {
        float4 w = *reinterpret_cast<const float4*>(&wrow[k]);
        float4 x = *reinterpret_cast<const float4*>(&xrow[k]);
        acc += w.x * x.x + w.y * x.y + w.z * x.z + w.w * x.w;
    }
    acc += __shfl_xor_sync(0xffffffffu, acc, 1);
    if (half == 0)
        g_scratch[O_IGV + (long)b * 128 + o] = acc + b_reduce_img[o];
}

// attention scores + softmax over fused QKV buffer (row stride 1280)
__global__ __launch_bounds__(256) void attn_k() {
    int gw = (blockIdx.x * blockDim.x + threadIdx.x) >> 5;
    int lane = threadIdx.x & 31;
    if (gw >= 2048) return;
    int b = gw >> 5;
    const float* qr = g_scratch + O_QKV + (long)gw * 1280;
    const float* kr = g_scratch + O_QKV + ((long)b * 32 + lane) * 1280 + 128;
    float s = 0.f;
#pragma unroll 8
    for (int o = 0; o < 128; o++) s += qr[o] * kr[o];
    float mx = s;
#pragma unroll
    for (int off = 16; off > 0; off >>= 1) mx = fmaxf(mx, __shfl_xor_sync(0xffffffffu, mx, off));
    float e = expf(s - mx);
    float sum = e;
#pragma unroll
    for (int off = 16; off > 0; off >>= 1) sum += __shfl_xor_sync(0xffffffffu, sum, off);
    g_scratch[O_ATT + (long)gw * 32 + lane] = e / sum;
}

__global__ __launch_bounds__(32) void aw_k(const int* __restrict__ lens) {
    int b = blockIdx.x, s = threadIdx.x;
    int len = lens[b];
    float a = 0.f;
    for (int tt = 0; tt < len; tt++) a += g_scratch[O_ATT + ((long)b * 32 + tt) * 32 + s];
    g_scratch[O_AW + b * 32 + s] = a;
}

__global__ __launch_bounds__(256) void txt_embed_k(const int* __restrict__ lens,
                                                   const float* __restrict__ gamma) {
    int b = blockIdx.y;
    int c = blockIdx.x * 256 + threadIdx.x;
    __shared__ float saw[32];
    if (threadIdx.x < 32) saw[threadIdx.x] = g_scratch[O_AW + b * 32 + threadIdx.x];
    __syncthreads();
    int len = lens[b];
    float g = *gamma;
    float a1 = 0.f;
    for (int tt = 0; tt < len; tt++) a1 += g_scratch[O_TXT + ((long)b * 32 + tt) * 1024 + c];
    float a2 = 0.f;
#pragma unroll
    for (int s = 0; s < 32; s++)
        a2 += saw[s] * g_scratch[O_QKV + ((long)b * 32 + s) * 1280 + 256 + c];
    g_scratch[O_TE + (long)b * 1024 + c] = (a1 + g * a2) / (float)len;
}

// sims[i,b] = (y . iv_i) / (|y| + eps)
__global__ __launch_bounds__(256) void sims_k(float* __restrict__ out) {
    int img = blockIdx.y, b = blockIdx.x;
    int tid = threadIdx.x;
    const float* y = g_scratch + O_Y + (long)img * 65536 + (long)b * 1024;
    const float* iv = g_scratch + O_IVN + (long)img * 1024;
    float ss = 0.f, dp = 0.f;
#pragma unroll
    for (int i = 0; i < 4; i++) {
        int c = i * 256 + tid;
        float v = y[c];
        ss += v * v;
        dp += v * iv[c];
    }
    __shared__ float r1[256], r2[256];
    r1[tid] = ss; r2[tid] = dp;
    __syncthreads();
    for (int o = 128; o > 0; o >>= 1) {
        if (tid < o) { r1[tid] += r1[tid + o]; r2[tid] += r2[tid + o]; }
        __syncthreads();
    }
    if (tid == 0) out[img * 64 + b] = r2[0] / (sqrtf(r1[0]) + 1e-8f);
}

// ---------------------------------------------------------------------------
extern "C" void kernel_launch(void* const* d_in, const int* in_sizes, int n_in,
                              void* d_out, int out_size) {
    const float* img_embed    = (const float*)d_in[0];
    const float* cap_embed    = (const float*)d_in[1];
    const int*   lens         = (const int*)d_in[2];
    const float* W_reduce_img = (const float*)d_in[3];
    const float* b_reduce_img = (const float*)d_in[4];
    const float* W_reduce_txt = (const float*)d_in[5];
    const float* b_reduce_txt = (const float*)d_in[6];
    const float* gru_Wih_f    = (const float*)d_in[7];
    const float* gru_Whh_f    = (const float*)d_in[8];
    const float* gru_bih_f    = (const float*)d_in[9];
    const float* gru_bhh_f    = (const float*)d_in[10];
    const float* gru_Wih_b    = (const float*)d_in[11];
    const float* gru_Whh_b    = (const float*)d_in[12];
    const float* gru_bih_b    = (const float*)d_in[13];
    const float* gru_bhh_b    = (const float*)d_in[14];
    const float* sa_Wq        = (const float*)d_in[15];
    const float* sa_bq        = (const float*)d_in[16];
    const float* sa_Wk        = (const float*)d_in[17];
    const float* sa_bk        = (const float*)d_in[18];
    const float* sa_Wv        = (const float*)d_in[19];
    const float* sa_bv        = (const float*)d_in[20];
    const float* sa_gamma     = (const float*)d_in[21];
    const float* gen_Wih      = (const float*)d_in[22];
    const float* gen_bih      = (const float*)d_in[23];
    const float* gen_Whh      = (const float*)d_in[24];
    const float* gen_bhh      = (const float*)d_in[25];
    const float* gen_Wbih     = (const float*)d_in[26];
    const float* gen_bbih     = (const float*)d_in[27];
    const float* gen_Wbhh     = (const float*)d_in[28];
    const float* gen_bbhh     = (const float*)d_in[29];
    const float* W_txt_fc     = (const float*)d_in[30];
    const float* b_txt_fc     = (const float*)d_in[31];

    float* S = nullptr;
    cudaGetSymbolAddress((void**)&S, g_scratch);

    const int SMEM_TF32 = 2 * 2 * STG * 4;   // 73728 B
    const int SMEM_STEP = 98304;
    cudaFuncSetAttribute(gemm_tf32<0>, cudaFuncAttributeMaxDynamicSharedMemorySize, SMEM_TF32);
    cudaFuncSetAttribute(gemm_tf32<1>, cudaFuncAttributeMaxDynamicSharedMemorySize, SMEM_TF32);
    cudaFuncSetAttribute(step3_k, cudaFuncAttributeMaxDynamicSharedMemorySize, SMEM_STEP);

    init_k<<<4096, 256>>>();

    // Concatenate weights for fused GEMMs (D2D copies, graph-capturable)
    cudaMemcpyAsync(S + O_WGI,              gru_Wih_f,    3072L*300*4, cudaMemcpyDeviceToDevice);
    cudaMemcpyAsync(S + O_WGI + 3072L*300,  gru_Wih_b,    3072L*300*4, cudaMemcpyDeviceToDevice);
    cudaMemcpyAsync(S + O_WGI + 6144L*300,  W_reduce_txt, 128L*300*4,  cudaMemcpyDeviceToDevice);
    cudaMemcpyAsync(S + O_BGI,              gru_bih_f,    3072L*4,     cudaMemcpyDeviceToDevice);
    cudaMemcpyAsync(S + O_BGI + 3072,       gru_bih_b,    3072L*4,     cudaMemcpyDeviceToDevice);
    cudaMemcpyAsync(S + O_BGI + 6144,       b_reduce_txt, 128L*4,      cudaMemcpyDeviceToDevice);
    cudaMemcpyAsync(S + O_WQKV,             sa_Wq,        128L*1024*4, cudaMemcpyDeviceToDevice);
    cudaMemcpyAsync(S + O_WQKV + 128L*1024, sa_Wk,        128L*1024*4, cudaMemcpyDeviceToDevice);
    cudaMemcpyAsync(S + O_WQKV + 256L*1024, sa_Wv,        1024L*1024*4,cudaMemcpyDeviceToDevice);
    cudaMemcpyAsync(S + O_BQKV,             sa_bq,        128L*4,      cudaMemcpyDeviceToDevice);
    cudaMemcpyAsync(S + O_BQKV + 128,       sa_bk,        128L*4,      cudaMemcpyDeviceToDevice);
    cudaMemcpyAsync(S + O_BQKV + 256,       sa_bv,        1024L*4,     cudaMemcpyDeviceToDevice);

    // Fused GI_f|GI_b|CR projection: (T*B, 6272)
    gemm_tf32<1><<<dim3(49, 16, 1), 256, SMEM_TF32>>>(
        cap_embed, S + O_WGI, S + O_BGI, nullptr, S + O_GIALL,
        2048, 6272, 300, 300, 300, 0, 0, 0, 0);

    // image path: pool + l2norm + reduce projection, fused
    imgvec_k<<<64, 256>>>(img_embed, W_reduce_img, b_reduce_img);

    // generated GRU weights per image
    gemm_tf32<0><<<dim3(384, 1, 1), 256, SMEM_TF32>>>(
        S + O_IGV, gen_Wih, gen_bih, nullptr, S + O_WIH,
        64, 49152, 128, 128, 128, 0, 0, 0, 0);
    gemm_tf32<0><<<dim3(384, 1, 1), 256, SMEM_TF32>>>(
        S + O_IGV, gen_Whh, gen_bhh, nullptr, S + O_WHH,
        64, 49152, 128, 128, 128, 0, 0, 0, 0);
    gemm_tf32<0><<<dim3(3, 1, 1), 256, SMEM_TF32>>>(
        S + O_IGV, gen_Wbih, gen_bbih, nullptr, S + O_BIH,
        64, 384, 128, 128, 128, 0, 0, 0, 0);
    gemm_tf32<0><<<dim3(3, 1, 1), 256, SMEM_TF32>>>(
        S + O_IGV, gen_Wbhh, gen_bbhh, nullptr, S + O_BHH,
        64, 384, 128, 128, 128, 0, 0, 0, 0);

    // 32 tensor-core recurrent steps (main bi-GRU + gen GRU with in-step gi)
    for (int t = 0; t < 32; t++)
        step3_k<<<320, 256, SMEM_STEP>>>(t, gru_Whh_f, gru_bhh_f, gru_Whh_b, gru_bhh_b);

    // fused Q|K|V projection: (B*T, 1280)
    gemm_tf32<0><<<dim3(10, 16, 1), 256, SMEM_TF32>>>(
        S + O_TXT, S + O_WQKV, S + O_BQKV, nullptr, S + O_QKV,
        2048, 1280, 1024, 1024, 1024, 0, 0, 0, 0);
    attn_k<<<256, 256>>>();
    aw_k<<<64, 32>>>(lens);
    txt_embed_k<<<dim3(4, 64), 256>>>(lens, sa_gamma);

    // final FC: shared part + per-image correction
    gemm_tf32<0><<<dim3(8, 1, 1), 256, SMEM_TF32>>>(
        S + O_TE, W_txt_fc, b_txt_fc, nullptr, S + O_FCB,
        64, 1024, 1024, 1024, 1152, 0, 0, 0, 0);
    gemm_tf32<0><<<dim3(8, 1, 64), 256, SMEM_TF32>>>(
        S + O_HMAX, W_txt_fc + 1024, nullptr, S + O_FCB, S + O_Y,
        64, 1024, 128, 128, 1152, 64L * 128, 0, 0, 64L * 1024);

    sims_k<<<dim3(64, 64), 256>>>((float*)d_out);
}

// round 15
// speedup vs baseline: 4.3916x; 1.3998x over previous
#include <cuda_runtime.h>
#include <cuda_bf16.h>
#include <math.h>
#include <stdint.h>

// ---------------------------------------------------------------------------
// Problem constants:  L=1024, R=128, T=32, B=64, DIN=300, REG=36, R3=384, H3=3072
// ---------------------------------------------------------------------------

// ---------------- scratch layout (floats) ----------------
#define SZ_GIALL   (2048L*6272)      // fused [GI_f | GI_b | CR] rows (t*64+b)
#define SZ_TXT     (64L*32*1024)
#define SZ_HST     (2L*2*64*1024)
#define SZ_WGI     (6272L*300)
#define SZ_BGI     (6400L)
#define SZ_QKV     (2048L*1280)
#define SZ_WQKV    (1280L*1024)
#define SZ_BQKV    (1280L)
#define SZ_ATT     (2048L*32)
#define SZ_AW      (64L*32)
#define SZ_TE      (64L*1024)
#define SZ_IEG     (64L*1024)
#define SZ_IVN     (64L*1024)
#define SZ_IGV     (64L*128)
#define SZ_WG      (64L*49152)
#define SZ_BG      (64L*384)
#define SZ_HG      (2L*64*64*128)
#define SZ_HMAX    (64L*64*128)
#define SZ_FCB     (64L*1024)
#define SZ_Y       (64L*64*1024)
#define SZ_WHP     (3072L*1024)      // pre-rounded main Whh per dir

#define O_GIALL 0L
#define O_TXT   (O_GIALL + SZ_GIALL)
#define O_HST   (O_TXT + SZ_TXT)
#define O_WGI   (O_HST + SZ_HST)
#define O_BGI   (O_WGI + SZ_WGI)
#define O_QKV   (O_BGI + SZ_BGI)
#define O_WQKV  (O_QKV + SZ_QKV)
#define O_BQKV  (O_WQKV + SZ_WQKV)
#define O_ATT   (O_BQKV + SZ_BQKV)
#define O_AW    (O_ATT + SZ_ATT)
#define O_TE    (O_AW + SZ_AW)
#define O_IEG   (O_TE + SZ_TE)
#define O_IVN   (O_IEG + SZ_IEG)
#define O_IGV   (O_IVN + SZ_IVN)
#define O_WIH   (O_IGV + SZ_IGV)
#define O_WHH   (O_WIH + SZ_WG)
#define O_BIH   (O_WHH + SZ_WG)
#define O_BHH   (O_BIH + SZ_BG)
#define O_HG    (O_BHH + SZ_BG)
#define O_HMAX  (O_HG + SZ_HG)
#define O_FCB   (O_HMAX + SZ_HMAX)
#define O_Y     (O_FCB + SZ_FCB)
#define O_WHF   (O_Y + SZ_Y)
#define O_WHB   (O_WHF + SZ_WHP)
#define SCRATCH_TOTAL (O_WHB + SZ_WHP)

__device__ float g_scratch[SCRATCH_TOTAL];
__device__ unsigned int g_barcnt;

#define NBLK_STEP 192

__device__ __forceinline__ float sigf(float x) { return 1.f / (1.f + expf(-x)); }

__device__ __forceinline__ uint32_t f2tf32(float x) {
    uint32_t r;
    asm("cvt.rna.tf32.f32 %0, %1;" : "=r"(r) : "f"(x));
    return r;
}

__device__ __forceinline__ void ldsm4(uint32_t* r, uint32_t addr) {
    asm volatile("ldmatrix.sync.aligned.m8n8.x4.shared.b16 {%0,%1,%2,%3}, [%4];"
                 : "=r"(r[0]), "=r"(r[1]), "=r"(r[2]), "=r"(r[3]) : "r"(addr));
}

__device__ __forceinline__ void mma_tf32(float* c, const uint32_t* a, const uint32_t* b) {
    asm volatile(
        "mma.sync.aligned.m16n8k8.row.col.f32.tf32.tf32.f32 "
        "{%0,%1,%2,%3}, {%4,%5,%6,%7}, {%8,%9}, {%0,%1,%2,%3};"
        : "+f"(c[0]), "+f"(c[1]), "+f"(c[2]), "+f"(c[3])
        : "r"(a[0]), "r"(a[1]), "r"(a[2]), "r"(a[3]), "r"(b[0]), "r"(b[1]));
}

__device__ __forceinline__ void cpasync16(uint32_t dst, const void* src, bool pred) {
    int sz = pred ? 16 : 0;
    asm volatile("cp.async.cg.shared.global [%0], [%1], 16, %2;"
                 :: "r"(dst), "l"(src), "r"(sz));
}

// ---------------------------------------------------------------------------
__global__ __launch_bounds__(256) void init_k() {
    long idx = (long)blockIdx.x * 256 + threadIdx.x;
    if (idx == 0) g_barcnt = 0u;
    if (idx < SZ_HST)  g_scratch[O_HST + idx] = 0.f;
    if (idx < SZ_HG)   g_scratch[O_HG + idx] = 0.f;
    if (idx < SZ_HMAX) g_scratch[O_HMAX + idx] = -1e30f;
}

// convert-copy: dst = tf32_round(src), float4 granularity
__global__ __launch_bounds__(256) void cvtw_k(const float* __restrict__ src,
                                              float* __restrict__ dst, long n4) {
    long i = ((long)blockIdx.x * 256 + threadIdx.x);
    if (i >= n4) return;
    float4 v = reinterpret_cast<const float4*>(src)[i];
    v.x = __uint_as_float(f2tf32(v.x));
    v.y = __uint_as_float(f2tf32(v.y));
    v.z = __uint_as_float(f2tf32(v.z));
    v.w = __uint_as_float(f2tf32(v.w));
    reinterpret_cast<float4*>(dst)[i] = v;
}

// ---------------------------------------------------------------------------
// A indexing modes:
//   0: A[m*lda + k]
//   1: m=t*64+b over cap_embed (B,T,300):  A[(m&63)*9600 + (m>>6)*300 + k]
// ---------------------------------------------------------------------------
template <int MODE>
__device__ __forceinline__ long a_idx(int m, int k, int lda) {
    if (MODE == 0) return (long)m * lda + k;
    { int b = m & 63, t = m >> 6; return (long)b * 9600 + (long)t * 300 + k; }
}

// ---------------------------------------------------------------------------
// TF32 tensor-core GEMM: 128x128 tile, 8 warps, m16n8k8 mma.
// cp.async double-buffered staging, cvt after ldmatrix.
// rnd != 0 -> round outputs to tf32 (for weights consumed by later mma).
// ---------------------------------------------------------------------------
#define TRS 36
#define STG (128 * TRS)

template <int MODE>
__global__ __launch_bounds__(256) void gemm_tf32(
    const float* __restrict__ A, const float* __restrict__ W,
    const float* __restrict__ bias, const float* __restrict__ Cadd,
    float* __restrict__ C,
    int M, int N, int K, int lda, int ldw,
    long aBS, long wBS, long bBS, long cBS, int rnd)
{
    extern __shared__ float sm[];

    int bz = blockIdx.z;
    A += (long)bz * aBS;
    W += (long)bz * wBS;
    C += (long)bz * cBS;
    const float* biasp = bias ? (bias + (long)bz * bBS) : nullptr;

    int tid = threadIdx.x;
    int warp = tid >> 5, lane = tid & 31;
    int wr = warp >> 2, wc = warp & 3;
    int m0 = blockIdx.y * 128, n0 = blockIdx.x * 128;

    float acc[4][4][4];
#pragma unroll
    for (int mt = 0; mt < 4; mt++)
#pragma unroll
        for (int nt = 0; nt < 4; nt++)
#pragma unroll
            for (int q = 0; q < 4; q++) acc[mt][nt][q] = 0.f;

    uint32_t smbase = (uint32_t)__cvta_generic_to_shared(sm);

    int rowA = (lane & 7) + ((lane >> 3) & 1) * 8;
    int colA = (lane >> 4) * 4;
    int rowB = (lane & 7) + (lane >> 4) * 8;
    int colB = ((lane >> 3) & 1) * 4;

    const int NIT = (K + 31) / 32;

    auto issue = [&](int it, int s) {
        int k0 = it * 32;
        uint32_t abase = smbase + (uint32_t)(s * 2 * STG) * 4u;
        uint32_t bbase = abase + (uint32_t)STG * 4u;
#pragma unroll
        for (int r = 0; r < 4; r++) {
            int idx = tid + r * 256;
            int mm = idx >> 3, k4 = idx & 7;
            int m = m0 + mm, k = k0 + k4 * 4;
            bool p = (m < M) && (k < K);
            const float* src = p ? &A[a_idx<MODE>(m, k, lda)] : A;
            cpasync16(abase + (uint32_t)(mm * TRS + k4 * 4) * 4u, src, p);
        }
#pragma unroll
        for (int r = 0; r < 4; r++) {
            int idx = tid + r * 256;
            int nn = idx >> 3, k4 = idx & 7;
            int n = n0 + nn, k = k0 + k4 * 4;
            bool p = (n < N) && (k < K);
            const float* src = p ? &W[(long)n * ldw + k] : W;
            cpasync16(bbase + (uint32_t)(nn * TRS + k4 * 4) * 4u, src, p);
        }
        asm volatile("cp.async.commit_group;");
    };

    issue(0, 0);
    for (int it = 0; it < NIT; it++) {
        int cur = it & 1;
        if (it + 1 < NIT) {
            issue(it + 1, cur ^ 1);
            asm volatile("cp.async.wait_group 1;");
        } else {
            asm volatile("cp.async.wait_group 0;");
        }
        __syncthreads();

        uint32_t asb = smbase + (uint32_t)(cur * 2 * STG) * 4u;
        uint32_t bsb = asb + (uint32_t)STG * 4u;
#pragma unroll
        for (int kk = 0; kk < 32; kk += 8) {
            uint32_t a[4][4], b[4][2];
#pragma unroll
            for (int mt = 0; mt < 4; mt++) {
                ldsm4(a[mt], asb +
                      (uint32_t)(((wr * 64 + mt * 16 + rowA) * TRS + kk + colA) * 4));
#pragma unroll
                for (int q = 0; q < 4; q++)
                    a[mt][q] = f2tf32(__uint_as_float(a[mt][q]));
            }
#pragma unroll
            for (int p = 0; p < 2; p++) {
                uint32_t r4[4];
                ldsm4(r4, bsb +
                      (uint32_t)(((wc * 32 + p * 16 + rowB) * TRS + kk + colB) * 4));
#pragma unroll
                for (int q = 0; q < 4; q++)
                    r4[q] = f2tf32(__uint_as_float(r4[q]));
                b[2 * p][0] = r4[0]; b[2 * p][1] = r4[1];
                b[2 * p + 1][0] = r4[2]; b[2 * p + 1][1] = r4[3];
            }
#pragma unroll
            for (int mt = 0; mt < 4; mt++)
#pragma unroll
                for (int nt = 0; nt < 4; nt++)
                    mma_tf32(acc[mt][nt], a[mt], b[nt]);
        }
        __syncthreads();
    }

    int lr = lane >> 2, lc = (lane & 3) * 2;
#pragma unroll
    for (int mt = 0; mt < 4; mt++) {
#pragma unroll
        for (int part = 0; part < 2; part++) {
            int m = m0 + wr * 64 + mt * 16 + lr + part * 8;
            if (m >= M) continue;
#pragma unroll
            for (int nt = 0; nt < 4; nt++) {
                int n = n0 + wc * 32 + nt * 8 + lc;
                float v0 = acc[mt][nt][part * 2 + 0];
                float v1 = acc[mt][nt][part * 2 + 1];
                if (biasp) { v0 += biasp[n]; v1 += biasp[n + 1]; }
                if (Cadd) {
                    v0 += Cadd[(long)m * N + n];
                    v1 += Cadd[(long)m * N + n + 1];
                }
                if (rnd) {
                    v0 = __uint_as_float(f2tf32(v0));
                    v1 = __uint_as_float(f2tf32(v1));
                }
                C[(long)m * N + n] = v0;
                C[(long)m * N + n + 1] = v1;
            }
        }
    }
}

// ---------------------------------------------------------------------------
// Persistent recurrent kernel: ONE launch, 192 blocks, all 32 steps inside,
// software grid barrier between steps.
//   blocks [0,64):   main bi-GRU. dir = bx>>5, 32-col group (bx&31). K=1024.
//   blocks [64,192): gen GRU. img = (bx-64)>>1, cg = (bx-64)&1; two 32-col
//                    subgroups each: gh (h@Whh_g^T) + gi (cr@Wih_g^T), K=128.
// Weights are PRE-ROUNDED tf32 -> no B-side cvt in the inner loop.
// GEMM: M=64, N=96 (3 gates x 32 cols), 8 warps (4x2), warp 16x48.
// SMEM: staging 2 x 5760 floats; gh @ 11520; gi @ 17664; 98304 B (2/SM).
// ---------------------------------------------------------------------------
#define SSTRIDE 5760
#define X_GH 11520
#define X_GI 17664

__global__ __launch_bounds__(256, 2) void steps_k() {
    extern __shared__ float sm[];
    int tid = threadIdx.x;
    int warp = tid >> 5, lane = tid & 31;
    int wr = warp >> 1, wc = warp & 1;
    uint32_t smbase = (uint32_t)__cvta_generic_to_shared(sm);

    int rowA = (lane & 7) + ((lane >> 3) & 1) * 8;
    int colA = (lane >> 4) * 4;
    int rowB = (lane & 7) + (lane >> 4) * 8;
    int colB = ((lane >> 3) & 1) * 4;
    int lr = lane >> 2, lc = (lane & 3) * 2;

    bool isMain = blockIdx.x < 64;

    // unified GEMM: C(64 x 96) = A(64 x K) @ B^T, B rows = (g*gs + j0 + j).
    // B is pre-rounded tf32: no cvt on B fragments.
    auto run_gemm = [&](const float* Ap, int ldA, const float* Bp, int ldb,
                        int gs, int K, int j0, int xoff) {
        float acc[6][4];
#pragma unroll
        for (int nt = 0; nt < 6; nt++)
#pragma unroll
            for (int q = 0; q < 4; q++) acc[nt][q] = 0.f;

        const int NIT = K >> 5;
        auto issue = [&](int it, int s) {
            int k0 = it * 32;
            uint32_t ab = smbase + (uint32_t)(s * SSTRIDE) * 4u;
            uint32_t bb = ab + 2304u * 4u;
#pragma unroll
            for (int r = 0; r < 2; r++) {
                int idx = tid + r * 256;
                int mm = idx >> 3, k4 = idx & 7;
                cpasync16(ab + (uint32_t)(mm * 36 + k4 * 4) * 4u,
                          Ap + (long)mm * ldA + k0 + k4 * 4, true);
            }
#pragma unroll
            for (int r = 0; r < 3; r++) {
                int idx = tid + r * 256;
                int rr = idx >> 3, k4 = idx & 7;
                int g = rr >> 5, j = j0 + (rr & 31);
                cpasync16(bb + (uint32_t)(rr * 36 + k4 * 4) * 4u,
                          Bp + (long)(g * gs + j) * ldb + k0 + k4 * 4, true);
            }
            asm volatile("cp.async.commit_group;");
        };

        issue(0, 0);
        for (int it = 0; it < NIT; it++) {
            int cur = it & 1;
            if (it + 1 < NIT) {
                issue(it + 1, cur ^ 1);
                asm volatile("cp.async.wait_group 1;");
            } else {
                asm volatile("cp.async.wait_group 0;");
            }
            __syncthreads();

            uint32_t ab = smbase + (uint32_t)(cur * SSTRIDE) * 4u;
            uint32_t bb = ab + 2304u * 4u;
#pragma unroll
            for (int kk = 0; kk < 32; kk += 8) {
                uint32_t a[4], b[6][2];
                ldsm4(a, ab + (uint32_t)(((wr * 16 + rowA) * 36 + kk + colA) * 4));
#pragma unroll
                for (int q = 0; q < 4; q++)
                    a[q] = f2tf32(__uint_as_float(a[q]));
#pragma unroll
                for (int p = 0; p < 3; p++) {
                    uint32_t r4[4];
                    ldsm4(r4, bb + (uint32_t)(((wc * 48 + p * 16 + rowB) * 36 + kk + colB) * 4));
                    b[2 * p][0] = r4[0]; b[2 * p][1] = r4[1];
                    b[2 * p + 1][0] = r4[2]; b[2 * p + 1][1] = r4[3];
                }
#pragma unroll
                for (int nt = 0; nt < 6; nt++)
                    mma_tf32(acc[nt], a, b[nt]);
            }
            __syncthreads();
        }

#pragma unroll
        for (int nt = 0; nt < 6; nt++)
#pragma unroll
            for (int q = 0; q < 4; q++) {
                int m = wr * 16 + lr + (q >> 1) * 8;
                int rr = wc * 48 + nt * 8 + lc + (q & 1);
                sm[xoff + m * 96 + rr] = acc[nt][q];
            }
        __syncthreads();
    };

    for (int t = 0; t < 32; t++) {
        if (isMain) {
            int dir = blockIdx.x >> 5;
            int j0 = (blockIdx.x & 31) * 32;
            const float* Whh = g_scratch + (dir ? O_WHB : O_WHF);
            const float* bhhF;
            {
                // biases live in the original input arrays; fetch via scratch-free
                // path: we stashed pointers in constant-free globals? Instead they
                // are passed below through g_scratch staging (O_BGI unused tail).
            }
            float* hbase = g_scratch + O_HST + (long)dir * 131072;
            const float* hin = hbase + (long)(t & 1) * 65536;
            float* hout = hbase + (long)((t + 1) & 1) * 65536;
            int tt = dir ? (31 - t) : t;

            run_gemm(hin, 1024, Whh, 1024, 1024, 1024, j0, X_GH);

            int j = tid & 31, mg = tid >> 5;
            int col = j0 + j;
            const float* gi = g_scratch + O_GIALL + (long)dir * 3072;
            const float* bhh = g_scratch + O_BGI + 6272 + (long)dir * 3072 * 0; // placeholder, fixed below
            // biases copied to O_BHHM region (see kernel_launch): [dir][3072]
            bhh = g_scratch + O_WHF - 8192 + (long)dir * 3072;  // O_BHHM
            float* txt = g_scratch + O_TXT;
            float br = bhh[col], bz2 = bhh[1024 + col], bn = bhh[2048 + col];
            bool storeFirst = dir == 0 ? (tt < 16) : (tt >= 16);
#pragma unroll
            for (int i = 0; i < 8; i++) {
                int m = mg * 8 + i;
                const float* girow = gi + ((long)tt * 64 + m) * 6272;
                float gh_r = sm[X_GH + m * 96 + j];
                float gh_z = sm[X_GH + m * 96 + 32 + j];
                float gh_n = sm[X_GH + m * 96 + 64 + j];
                float r = sigf(girow[col] + gh_r + br);
                float z = sigf(girow[1024 + col] + gh_z + bz2);
                float n = tanhf(girow[2048 + col] + r * (gh_n + bn));
                float hold = hin[m * 1024 + col];
                float hn = (1.f - z) * n + z * hold;
                hout[m * 1024 + col] = hn;
                long ti = ((long)m * 32 + tt) * 1024 + col;
                if (storeFirst) txt[ti] = 0.5f * hn;
                else            txt[ti] += 0.5f * hn;
            }
        } else {
            int b2 = blockIdx.x - 64;
            int img = b2 >> 1;
            int cg = b2 & 1;
            const float* Whh = g_scratch + O_WHH + (long)img * 49152;
            const float* Wih = g_scratch + O_WIH + (long)img * 49152;
            const float* bhh = g_scratch + O_BHH + (long)img * 384;
            const float* bih = g_scratch + O_BIH + (long)img * 384;
            float* hb = g_scratch + O_HG;
            const float* hin = hb + (long)(t & 1) * 524288 + (long)img * 8192;
            float* hout = hb + (long)((t + 1) & 1) * 524288 + (long)img * 8192;
            float* hmax = g_scratch + O_HMAX + (long)img * 8192;
            const float* crbase = g_scratch + O_GIALL + (long)t * 64 * 6272 + 6144;

#pragma unroll
            for (int sub = 0; sub < 2; sub++) {
                int j0 = cg * 64 + sub * 32;
                run_gemm(hin, 128, Whh, 128, 128, 128, j0, X_GH);
                run_gemm(crbase, 6272, Wih, 128, 128, 128, j0, X_GI);

                int j = tid & 31, mg = tid >> 5;
                int col = j0 + j;
                float cr_ = bih[col] + bhh[col];
                float cz_ = bih[128 + col] + bhh[128 + col];
                float bni = bih[256 + col], bnh = bhh[256 + col];
#pragma unroll
                for (int i = 0; i < 8; i++) {
                    int m = mg * 8 + i;
                    float gh_r = sm[X_GH + m * 96 + j];
                    float gh_z = sm[X_GH + m * 96 + 32 + j];
                    float gh_n = sm[X_GH + m * 96 + 64 + j];
                    float gi_r = sm[X_GI + m * 96 + j];
                    float gi_z = sm[X_GI + m * 96 + 32 + j];
                    float gi_n = sm[X_GI + m * 96 + 64 + j];
                    float r = sigf(gi_r + gh_r + cr_);
                    float z = sigf(gi_z + gh_z + cz_);
                    float n = tanhf(gi_n + bni + r * (gh_n + bnh));
                    float hold = hin[m * 128 + col];
                    float hn = (1.f - z) * n + z * hold;
                    hout[m * 128 + col] = hn;
                    hmax[m * 128 + col] = fmaxf(hmax[m * 128 + col], hn);
                }
            }
        }

        // ---- software grid barrier ----
        __syncthreads();
        __threadfence();
        if (tid == 0) {
            atomicAdd(&g_barcnt, 1u);
            unsigned tgt = (unsigned)NBLK_STEP * (unsigned)(t + 1);
            while (*(volatile unsigned int*)&g_barcnt < tgt) {}
            __threadfence();
        }
        __syncthreads();
    }
}

// ---------------------------------------------------------------------------
// Fused image path: region mean -> IEG, l2norm -> IVN, reduce-proj -> IGV.
// ---------------------------------------------------------------------------
__global__ __launch_bounds__(256) void imgvec_k(
    const float* __restrict__ img_embed,
    const float* __restrict__ W_reduce_img, const float* __restrict__ b_reduce_img)
{
    __shared__ float s_ieg[1024];
    __shared__ float red[256];
    int b = blockIdx.x, tid = threadIdx.x;
    float vals[4], ss = 0.f;
#pragma unroll
    for (int i = 0; i < 4; i++) {
        int c = i * 256 + tid;
        float s = 0.f;
        for (int g = 0; g < 36; g++) s += img_embed[(long)b * 36864 + (long)g * 1024 + c];
        s *= (1.f / 36.f);
        vals[i] = s;
        ss += s * s;
        s_ieg[c] = s;
        g_scratch[O_IEG + (long)b * 1024 + c] = s;
    }
    red[tid] = ss;
    __syncthreads();
    for (int o = 128; o > 0; o >>= 1) { if (tid < o) red[tid] += red[tid + o]; __syncthreads(); }
    float inv = 1.f / (sqrtf(red[0]) + 1e-8f);
#pragma unroll
    for (int i = 0; i < 4; i++) {
        int c = i * 256 + tid;
        g_scratch[O_IVN + (long)b * 1024 + c] = vals[i] * inv;
    }
    int o = tid >> 1, half = tid & 1;
    const float* wrow = W_reduce_img + (long)o * 1024 + half * 512;
    const float* xrow = s_ieg + half * 512;
    float acc = 0.f;
#pragma unroll 4
    for (int k = 0; k < 512; k += 4) {
        float4 w = *reinterpret_cast<const float4*>(&wrow[k]);
        float4 x = *reinterpret_cast<const float4*>(&xrow[k]);
        acc += w.x * x.x + w.y * x.y + w.z * x.z + w.w * x.w;
    }
    acc += __shfl_xor_sync(0xffffffffu, acc, 1);
    if (half == 0)
        g_scratch[O_IGV + (long)b * 128 + o] = acc + b_reduce_img[o];
}

// attention scores + softmax over fused QKV buffer (row stride 1280)
__global__ __launch_bounds__(256) void attn_k() {
    int gw = (blockIdx.x * blockDim.x + threadIdx.x) >> 5;
    int lane = threadIdx.x & 31;
    if (gw >= 2048) return;
    int b = gw >> 5;
    const float* qr = g_scratch + O_QKV + (long)gw * 1280;
    const float* kr = g_scratch + O_QKV + ((long)b * 32 + lane) * 1280 + 128;
    float s = 0.f;
#pragma unroll 8
    for (int o = 0; o < 128; o++) s += qr[o] * kr[o];
    float mx = s;
#pragma unroll
    for (int off = 16; off > 0; off >>= 1) mx = fmaxf(mx, __shfl_xor_sync(0xffffffffu, mx, off));
    float e = expf(s - mx);
    float sum = e;
#pragma unroll
    for (int off = 16; off > 0; off >>= 1) sum += __shfl_xor_sync(0xffffffffu, sum, off);
    g_scratch[O_ATT + (long)gw * 32 + lane] = e / sum;
}

__global__ __launch_bounds__(32) void aw_k(const int* __restrict__ lens) {
    int b = blockIdx.x, s = threadIdx.x;
    int len = lens[b];
    float a = 0.f;
    for (int tt = 0; tt < len; tt++) a += g_scratch[O_ATT + ((long)b * 32 + tt) * 32 + s];
    g_scratch[O_AW + b * 32 + s] = a;
}

__global__ __launch_bounds__(256) void txt_embed_k(const int* __restrict__ lens,
                                                   const float* __restrict__ gamma) {
    int b = blockIdx.y;
    int c = blockIdx.x * 256 + threadIdx.x;
    __shared__ float saw[32];
    if (threadIdx.x < 32) saw[threadIdx.x] = g_scratch[O_AW + b * 32 + threadIdx.x];
    __syncthreads();
    int len = lens[b];
    float g = *gamma;
    float a1 = 0.f;
    for (int tt = 0; tt < len; tt++) a1 += g_scratch[O_TXT + ((long)b * 32 + tt) * 1024 + c];
    float a2 = 0.f;
#pragma unroll
    for (int s = 0; s < 32; s++)
        a2 += saw[s] * g_scratch[O_QKV + ((long)b * 32 + s) * 1280 + 256 + c];
    g_scratch[O_TE + (long)b * 1024 + c] = (a1 + g * a2) / (float)len;
}

// sims[i,b] = (y . iv_i) / (|y| + eps)
__global__ __launch_bounds__(256) void sims_k(float* __restrict__ out) {
    int img = blockIdx.y, b = blockIdx.x;
    int tid = threadIdx.x;
    const float* y = g_scratch + O_Y + (long)img * 65536 + (long)b * 1024;
    const float* iv = g_scratch + O_IVN + (long)img * 1024;
    float ss = 0.f, dp = 0.f;
#pragma unroll
    for (int i = 0; i < 4; i++) {
        int c = i * 256 + tid;
        float v = y[c];
        ss += v * v;
        dp += v * iv[c];
    }
    __shared__ float r1[256], r2[256];
    r1[tid] = ss; r2[tid] = dp;
    __syncthreads();
    for (int o = 128; o > 0; o >>= 1) {
        if (tid < o) { r1[tid] += r1[tid + o]; r2[tid] += r2[tid + o]; }
        __syncthreads();
    }
    if (tid == 0) out[img * 64 + b] = r2[0] / (sqrtf(r1[0]) + 1e-8f);
}

// ---------------------------------------------------------------------------
extern "C" void kernel_launch(void* const* d_in, const int* in_sizes, int n_in,
                              void* d_out, int out_size) {
    const float* img_embed    = (const float*)d_in[0];
    const float* cap_embed    = (const float*)d_in[1];
    const int*   lens         = (const int*)d_in[2];
    const float* W_reduce_img = (const float*)d_in[3];
    const float* b_reduce_img = (const float*)d_in[4];
    const float* W_reduce_txt = (const float*)d_in[5];
    const float* b_reduce_txt = (const float*)d_in[6];
    const float* gru_Wih_f    = (const float*)d_in[7];
    const float* gru_Whh_f    = (const float*)d_in[8];
    const float* gru_bih_f    = (const float*)d_in[9];
    const float* gru_bhh_f    = (const float*)d_in[10];
    const float* gru_Wih_b    = (const float*)d_in[11];
    const float* gru_Whh_b    = (const float*)d_in[12];
    const float* gru_bih_b    = (const float*)d_in[13];
    const float* gru_bhh_b    = (const float*)d_in[14];
    const float* sa_Wq        = (const float*)d_in[15];
    const float* sa_bq        = (const float*)d_in[16];
    const float* sa_Wk        = (const float*)d_in[17];
    const float* sa_bk        = (const float*)d_in[18];
    const float* sa_Wv        = (const float*)d_in[19];
    const float* sa_bv        = (const float*)d_in[20];
    const float* sa_gamma     = (const float*)d_in[21];
    const float* gen_Wih      = (const float*)d_in[22];
    const float* gen_bih      = (const float*)d_in[23];
    const float* gen_Whh      = (const float*)d_in[24];
    const float* gen_bhh      = (const float*)d_in[25];
    const float* gen_Wbih     = (const float*)d_in[26];
    const float* gen_bbih     = (const float*)d_in[27];
    const float* gen_Wbhh     = (const float*)d_in[28];
    const float* gen_bbhh     = (const float*)d_in[29];
    const float* W_txt_fc     = (const float*)d_in[30];
    const float* b_txt_fc     = (const float*)d_in[31];

    float* S = nullptr;
    cudaGetSymbolAddress((void**)&S, g_scratch);

    const int SMEM_TF32 = 2 * 2 * STG * 4;   // 73728 B
    const int SMEM_STEP = 98304;
    cudaFuncSetAttribute(gemm_tf32<0>, cudaFuncAttributeMaxDynamicSharedMemorySize, SMEM_TF32);
    cudaFuncSetAttribute(gemm_tf32<1>, cudaFuncAttributeMaxDynamicSharedMemorySize, SMEM_TF32);
    cudaFuncSetAttribute(steps_k, cudaFuncAttributeMaxDynamicSharedMemorySize, SMEM_STEP);

    init_k<<<4096, 256>>>();

    // Concatenate weights for fused GEMMs (D2D copies, graph-capturable)
    cudaMemcpyAsync(S + O_WGI,              gru_Wih_f,    3072L*300*4, cudaMemcpyDeviceToDevice);
    cudaMemcpyAsync(S + O_WGI + 3072L*300,  gru_Wih_b,    3072L*300*4, cudaMemcpyDeviceToDevice);
    cudaMemcpyAsync(S + O_WGI + 6144L*300,  W_reduce_txt, 128L*300*4,  cudaMemcpyDeviceToDevice);
    cudaMemcpyAsync(S + O_BGI,              gru_bih_f,    3072L*4,     cudaMemcpyDeviceToDevice);
    cudaMemcpyAsync(S + O_BGI + 3072,       gru_bih_b,    3072L*4,     cudaMemcpyDeviceToDevice);
    cudaMemcpyAsync(S + O_BGI + 6144,       b_reduce_txt, 128L*4,      cudaMemcpyDeviceToDevice);
    cudaMemcpyAsync(S + O_WQKV,             sa_Wq,        128L*1024*4, cudaMemcpyDeviceToDevice);
    cudaMemcpyAsync(S + O_WQKV + 128L*1024, sa_Wk,        128L*1024*4, cudaMemcpyDeviceToDevice);
    cudaMemcpyAsync(S + O_WQKV + 256L*1024, sa_Wv,        1024L*1024*4,cudaMemcpyDeviceToDevice);
    cudaMemcpyAsync(S + O_BQKV,             sa_bq,        128L*4,      cudaMemcpyDeviceToDevice);
    cudaMemcpyAsync(S + O_BQKV + 128,       sa_bk,        128L*4,      cudaMemcpyDeviceToDevice);
    cudaMemcpyAsync(S + O_BQKV + 256,       sa_bv,        1024L*4,     cudaMemcpyDeviceToDevice);
    // main-GRU hidden biases into the region just below O_WHF ([O_WHF-8192, O_WHF))
    cudaMemcpyAsync(S + O_WHF - 8192,        gru_bhh_f,   3072L*4,     cudaMemcpyDeviceToDevice);
    cudaMemcpyAsync(S + O_WHF - 8192 + 3072, gru_bhh_b,   3072L*4,     cudaMemcpyDeviceToDevice);

    // pre-rounded tf32 copies of main recurrent weights
    cvtw_k<<<3072, 256>>>(gru_Whh_f, S + O_WHF, 3072L*1024/4);
    cvtw_k<<<3072, 256>>>(gru_Whh_b, S + O_WHB, 3072L*1024/4);

    // Fused GI_f|GI_b|CR projection: (T*B, 6272)
    gemm_tf32<1><<<dim3(49, 16, 1), 256, SMEM_TF32>>>(
        cap_embed, S + O_WGI, S + O_BGI, nullptr, S + O_GIALL,
        2048, 6272, 300, 300, 300, 0, 0, 0, 0, 0);

    // image path: pool + l2norm + reduce projection, fused
    imgvec_k<<<64, 256>>>(img_embed, W_reduce_img, b_reduce_img);

    // generated GRU weights per image (outputs pre-rounded to tf32)
    gemm_tf32<0><<<dim3(384, 1, 1), 256, SMEM_TF32>>>(
        S + O_IGV, gen_Wih, gen_bih, nullptr, S + O_WIH,
        64, 49152, 128, 128, 128, 0, 0, 0, 0, 1);
    gemm_tf32<0><<<dim3(384, 1, 1), 256, SMEM_TF32>>>(
        S + O_IGV, gen_Whh, gen_bhh, nullptr, S + O_WHH,
        64, 49152, 128, 128, 128, 0, 0, 0, 0, 1);
    gemm_tf32<0><<<dim3(3, 1, 1), 256, SMEM_TF32>>>(
        S + O_IGV, gen_Wbih, gen_bbih, nullptr, S + O_BIH,
        64, 384, 128, 128, 128, 0, 0, 0, 0, 0);
    gemm_tf32<0><<<dim3(3, 1, 1), 256, SMEM_TF32>>>(
        S + O_IGV, gen_Wbhh, gen_bbhh, nullptr, S + O_BHH,
        64, 384, 128, 128, 128, 0, 0, 0, 0, 0);

    // ALL 32 recurrent steps in one persistent launch (grid barrier inside)
    steps_k<<<NBLK_STEP, 256, SMEM_STEP>>>();

    // fused Q|K|V projection: (B*T, 1280)
    gemm_tf32<0><<<dim3(10, 16, 1), 256, SMEM_TF32>>>(
        S + O_TXT, S + O_WQKV, S + O_BQKV, nullptr, S + O_QKV,
        2048, 1280, 1024, 1024, 1024, 0, 0, 0, 0, 0);
    attn_k<<<256, 256>>>();
    aw_k<<<64, 32>>>(lens);
    txt_embed_k<<<dim3(4, 64), 256>>>(lens, sa_gamma);

    // final FC: shared part + per-image correction
    gemm_tf32<0><<<dim3(8, 1, 1), 256, SMEM_TF32>>>(
        S + O_TE, W_txt_fc, b_txt_fc, nullptr, S + O_FCB,
        64, 1024, 1024, 1024, 1152, 0, 0, 0, 0, 0);
    gemm_tf32<0><<<dim3(8, 1, 64), 256, SMEM_TF32>>>(
        S + O_HMAX, W_txt_fc + 1024, nullptr, S + O_FCB, S + O_Y,
        64, 1024, 128, 128, 1152, 64L * 128, 0, 0, 64L * 1024, 0);

    sims_k<<<dim3(64, 64), 256>>>((float*)d_out);
}

// round 16
// speedup vs baseline: 5.3882x; 1.2269x over previous
#include <cuda_runtime.h>
#include <cuda_bf16.h>
#include <math.h>
#include <stdint.h>

// ---------------------------------------------------------------------------
// Problem constants:  L=1024, R=128, T=32, B=64, DIN=300, REG=36, R3=384, H3=3072
// ---------------------------------------------------------------------------

// ---------------- scratch layout (floats) ----------------
#define SZ_GIALL   (2048L*6272)      // fused [GI_f | GI_b | CR] rows (t*64+b)
#define SZ_TXT     (64L*32*1024)
#define SZ_HST     (2L*2*64*1024)
#define SZ_WGI     (6272L*300)
#define SZ_BGI     (6400L)
#define SZ_QKV     (2048L*1280)
#define SZ_WQKV    (1280L*1024)
#define SZ_BQKV    (1280L)
#define SZ_ATT     (2048L*32)
#define SZ_AW      (64L*32)
#define SZ_TE      (64L*1024)
#define SZ_IEG     (64L*1024)
#define SZ_IVN     (64L*1024)
#define SZ_IGV     (64L*128)
#define SZ_WG      (64L*49152)
#define SZ_BG      (64L*384)
#define SZ_HG      (2L*64*64*128)
#define SZ_HMAX    (64L*64*128)
#define SZ_FCB     (64L*1024)
#define SZ_Y       (64L*64*1024)
#define SZ_WHP     (3072L*1024)      // pre-rounded main Whh per dir

#define O_GIALL 0L
#define O_TXT   (O_GIALL + SZ_GIALL)
#define O_HST   (O_TXT + SZ_TXT)
#define O_WGI   (O_HST + SZ_HST)
#define O_BGI   (O_WGI + SZ_WGI)
#define O_QKV   (O_BGI + SZ_BGI)
#define O_WQKV  (O_QKV + SZ_QKV)
#define O_BQKV  (O_WQKV + SZ_WQKV)
#define O_ATT   (O_BQKV + SZ_BQKV)
#define O_AW    (O_ATT + SZ_ATT)
#define O_TE    (O_AW + SZ_AW)
#define O_IEG   (O_TE + SZ_TE)
#define O_IVN   (O_IEG + SZ_IEG)
#define O_IGV   (O_IVN + SZ_IVN)
#define O_WIH   (O_IGV + SZ_IGV)
#define O_WHH   (O_WIH + SZ_WG)
#define O_BIH   (O_WHH + SZ_WG)
#define O_BHH   (O_BIH + SZ_BG)
#define O_HG    (O_BHH + SZ_BG)
#define O_HMAX  (O_HG + SZ_HG)
#define O_FCB   (O_HMAX + SZ_HMAX)
#define O_Y     (O_FCB + SZ_FCB)
#define O_WHF   (O_Y + SZ_Y)
#define O_WHB   (O_WHF + SZ_WHP)
#define SCRATCH_TOTAL (O_WHB + SZ_WHP)

__device__ float g_scratch[SCRATCH_TOTAL];
__device__ unsigned int g_barcnt;

#define NBLK_STEP 256

__device__ __forceinline__ float sigf(float x) { return 1.f / (1.f + expf(-x)); }

__device__ __forceinline__ uint32_t f2tf32(float x) {
    uint32_t r;
    asm("cvt.rna.tf32.f32 %0, %1;" : "=r"(r) : "f"(x));
    return r;
}
__device__ __forceinline__ float rnd_tf32(float x) {
    return __uint_as_float(f2tf32(x));
}

__device__ __forceinline__ void ldsm4(uint32_t* r, uint32_t addr) {
    asm volatile("ldmatrix.sync.aligned.m8n8.x4.shared.b16 {%0,%1,%2,%3}, [%4];"
                 : "=r"(r[0]), "=r"(r[1]), "=r"(r[2]), "=r"(r[3]) : "r"(addr));
}
__device__ __forceinline__ void ldsm2(uint32_t* r, uint32_t addr) {
    asm volatile("ldmatrix.sync.aligned.m8n8.x2.shared.b16 {%0,%1}, [%2];"
                 : "=r"(r[0]), "=r"(r[1]) : "r"(addr));
}

__device__ __forceinline__ void mma_tf32(float* c, const uint32_t* a, const uint32_t* b) {
    asm volatile(
        "mma.sync.aligned.m16n8k8.row.col.f32.tf32.tf32.f32 "
        "{%0,%1,%2,%3}, {%4,%5,%6,%7}, {%8,%9}, {%0,%1,%2,%3};"
        : "+f"(c[0]), "+f"(c[1]), "+f"(c[2]), "+f"(c[3])
        : "r"(a[0]), "r"(a[1]), "r"(a[2]), "r"(a[3]), "r"(b[0]), "r"(b[1]));
}

__device__ __forceinline__ void cpasync16(uint32_t dst, const void* src, bool pred) {
    int sz = pred ? 16 : 0;
    asm volatile("cp.async.cg.shared.global [%0], [%1], 16, %2;"
                 :: "r"(dst), "l"(src), "r"(sz));
}

// ---------------------------------------------------------------------------
__global__ __launch_bounds__(256) void init_k() {
    long idx = (long)blockIdx.x * 256 + threadIdx.x;
    if (idx == 0) g_barcnt = 0u;
    if (idx < SZ_HST)  g_scratch[O_HST + idx] = 0.f;
    if (idx < SZ_HG)   g_scratch[O_HG + idx] = 0.f;
    if (idx < SZ_HMAX) g_scratch[O_HMAX + idx] = -1e30f;
}

// convert-copy: dst = tf32_round(src), float4 granularity
__global__ __launch_bounds__(256) void cvtw_k(const float* __restrict__ src,
                                              float* __restrict__ dst, long n4) {
    long i = ((long)blockIdx.x * 256 + threadIdx.x);
    if (i >= n4) return;
    float4 v = reinterpret_cast<const float4*>(src)[i];
    v.x = rnd_tf32(v.x);
    v.y = rnd_tf32(v.y);
    v.z = rnd_tf32(v.z);
    v.w = rnd_tf32(v.w);
    reinterpret_cast<float4*>(dst)[i] = v;
}

// ---------------------------------------------------------------------------
// A indexing modes:
//   0: A[m*lda + k]
//   1: m=t*64+b over cap_embed (B,T,300):  A[(m&63)*9600 + (m>>6)*300 + k]
// ---------------------------------------------------------------------------
template <int MODE>
__device__ __forceinline__ long a_idx(int m, int k, int lda) {
    if (MODE == 0) return (long)m * lda + k;
    { int b = m & 63, t = m >> 6; return (long)b * 9600 + (long)t * 300 + k; }
}

// ---------------------------------------------------------------------------
// TF32 tensor-core GEMM: 128x128 tile, 8 warps, m16n8k8 mma.
// cp.async double-buffered staging, cvt after ldmatrix.
// rnd: 0 = none; 1 = round all outputs to tf32; 2 = round outputs with n>=6144.
// ---------------------------------------------------------------------------
#define TRS 36
#define STG (128 * TRS)

template <int MODE>
__global__ __launch_bounds__(256) void gemm_tf32(
    const float* __restrict__ A, const float* __restrict__ W,
    const float* __restrict__ bias, const float* __restrict__ Cadd,
    float* __restrict__ C,
    int M, int N, int K, int lda, int ldw,
    long aBS, long wBS, long bBS, long cBS, int rnd)
{
    extern __shared__ float sm[];

    int bz = blockIdx.z;
    A += (long)bz * aBS;
    W += (long)bz * wBS;
    C += (long)bz * cBS;
    const float* biasp = bias ? (bias + (long)bz * bBS) : nullptr;

    int tid = threadIdx.x;
    int warp = tid >> 5, lane = tid & 31;
    int wr = warp >> 2, wc = warp & 3;
    int m0 = blockIdx.y * 128, n0 = blockIdx.x * 128;

    float acc[4][4][4];
#pragma unroll
    for (int mt = 0; mt < 4; mt++)
#pragma unroll
        for (int nt = 0; nt < 4; nt++)
#pragma unroll
            for (int q = 0; q < 4; q++) acc[mt][nt][q] = 0.f;

    uint32_t smbase = (uint32_t)__cvta_generic_to_shared(sm);

    int rowA = (lane & 7) + ((lane >> 3) & 1) * 8;
    int colA = (lane >> 4) * 4;
    int rowB = (lane & 7) + (lane >> 4) * 8;
    int colB = ((lane >> 3) & 1) * 4;

    const int NIT = (K + 31) / 32;

    auto issue = [&](int it, int s) {
        int k0 = it * 32;
        uint32_t abase = smbase + (uint32_t)(s * 2 * STG) * 4u;
        uint32_t bbase = abase + (uint32_t)STG * 4u;
#pragma unroll
        for (int r = 0; r < 4; r++) {
            int idx = tid + r * 256;
            int mm = idx >> 3, k4 = idx & 7;
            int m = m0 + mm, k = k0 + k4 * 4;
            bool p = (m < M) && (k < K);
            const float* src = p ? &A[a_idx<MODE>(m, k, lda)] : A;
            cpasync16(abase + (uint32_t)(mm * TRS + k4 * 4) * 4u, src, p);
        }
#pragma unroll
        for (int r = 0; r < 4; r++) {
            int idx = tid + r * 256;
            int nn = idx >> 3, k4 = idx & 7;
            int n = n0 + nn, k = k0 + k4 * 4;
            bool p = (n < N) && (k < K);
            const float* src = p ? &W[(long)n * ldw + k] : W;
            cpasync16(bbase + (uint32_t)(nn * TRS + k4 * 4) * 4u, src, p);
        }
        asm volatile("cp.async.commit_group;");
    };

    issue(0, 0);
    for (int it = 0; it < NIT; it++) {
        int cur = it & 1;
        if (it + 1 < NIT) {
            issue(it + 1, cur ^ 1);
            asm volatile("cp.async.wait_group 1;");
        } else {
            asm volatile("cp.async.wait_group 0;");
        }
        __syncthreads();

        uint32_t asb = smbase + (uint32_t)(cur * 2 * STG) * 4u;
        uint32_t bsb = asb + (uint32_t)STG * 4u;
#pragma unroll
        for (int kk = 0; kk < 32; kk += 8) {
            uint32_t a[4][4], b[4][2];
#pragma unroll
            for (int mt = 0; mt < 4; mt++) {
                ldsm4(a[mt], asb +
                      (uint32_t)(((wr * 64 + mt * 16 + rowA) * TRS + kk + colA) * 4));
#pragma unroll
                for (int q = 0; q < 4; q++)
                    a[mt][q] = f2tf32(__uint_as_float(a[mt][q]));
            }
#pragma unroll
            for (int p = 0; p < 2; p++) {
                uint32_t r4[4];
                ldsm4(r4, bsb +
                      (uint32_t)(((wc * 32 + p * 16 + rowB) * TRS + kk + colB) * 4));
#pragma unroll
                for (int q = 0; q < 4; q++)
                    r4[q] = f2tf32(__uint_as_float(r4[q]));
                b[2 * p][0] = r4[0]; b[2 * p][1] = r4[1];
                b[2 * p + 1][0] = r4[2]; b[2 * p + 1][1] = r4[3];
            }
#pragma unroll
            for (int mt = 0; mt < 4; mt++)
#pragma unroll
                for (int nt = 0; nt < 4; nt++)
                    mma_tf32(acc[mt][nt], a[mt], b[nt]);
        }
        __syncthreads();
    }

    int lr = lane >> 2, lc = (lane & 3) * 2;
#pragma unroll
    for (int mt = 0; mt < 4; mt++) {
#pragma unroll
        for (int part = 0; part < 2; part++) {
            int m = m0 + wr * 64 + mt * 16 + lr + part * 8;
            if (m >= M) continue;
#pragma unroll
            for (int nt = 0; nt < 4; nt++) {
                int n = n0 + wc * 32 + nt * 8 + lc;
                float v0 = acc[mt][nt][part * 2 + 0];
                float v1 = acc[mt][nt][part * 2 + 1];
                if (biasp) { v0 += biasp[n]; v1 += biasp[n + 1]; }
                if (Cadd) {
                    v0 += Cadd[(long)m * N + n];
                    v1 += Cadd[(long)m * N + n + 1];
                }
                if (rnd == 1 || (rnd == 2 && n >= 6144)) v0 = rnd_tf32(v0);
                if (rnd == 1 || (rnd == 2 && n + 1 >= 6144)) v1 = rnd_tf32(v1);
                C[(long)m * N + n] = v0;
                C[(long)m * N + n + 1] = v1;
            }
        }
    }
}

// ---------------------------------------------------------------------------
// Persistent recurrent kernel v2: ONE launch, 256 blocks, 32 steps inside.
//   blocks [0,128):   main bi-GRU. dir = bx>>6, 16-col group (bx&63). K=1024.
//                     N=48 (3 gates x 16 cols). Depth-3 cp.async pipeline.
//   blocks [128,256): gen GRU. img = (bx-128)>>1, cg = (bx-128)&1; two 32-col
//                     subgroups: gh (h@Whh_g^T) + gi (cr@Wih_g^T), K=128.
// ALL mma operands pre-rounded tf32 -> zero cvt in inner loops.
// h ping-pong states stored tf32-rounded; txt/hmax keep full precision.
// SMEM layout (floats):
//   main: 3 stages x 4032 = [0,12096); gh @ 12096 (64x48=3072). 15168 total.
//   gen:  2 stages x 5760 = [0,11520); gh @ 11520; gi @ 17664. 23808 total.
// 98304 B dynamic, 2 blocks/SM -> 256 blocks = single wave (<=296).
// ---------------------------------------------------------------------------
#define SSTRIDE 5760
#define X_GH 11520
#define X_GI 17664
#define MSTRIDE 4032
#define X_GH2 12096

__global__ __launch_bounds__(256, 2) void steps_k() {
    extern __shared__ float sm[];
    int tid = threadIdx.x;
    int warp = tid >> 5, lane = tid & 31;
    uint32_t smbase = (uint32_t)__cvta_generic_to_shared(sm);

    int rowA = (lane & 7) + ((lane >> 3) & 1) * 8;
    int colA = (lane >> 4) * 4;
    int rowB = (lane & 7) + (lane >> 4) * 8;
    int colB = ((lane >> 3) & 1) * 4;
    int rowB2 = lane & 7;
    int colB2 = ((lane >> 3) & 1) * 4;
    int lr = lane >> 2, lc = (lane & 3) * 2;

    bool isMain = blockIdx.x < 128;

    // ---- gen GEMM: C(64 x 96) = A(64 x K=128) @ B^T, depth-2 pipeline ----
    int wrg = warp >> 1, wcg = warp & 1;   // 4x2 warps, warp tile 16x48
    auto run_gemm_gen = [&](const float* Ap, int ldA, const float* Bp, int j0, int xoff) {
        float acc[6][4];
#pragma unroll
        for (int nt = 0; nt < 6; nt++)
#pragma unroll
            for (int q = 0; q < 4; q++) acc[nt][q] = 0.f;

        auto issue = [&](int it, int s) {
            int k0 = it * 32;
            uint32_t ab = smbase + (uint32_t)(s * SSTRIDE) * 4u;
            uint32_t bb = ab + 2304u * 4u;
#pragma unroll
            for (int r = 0; r < 2; r++) {
                int idx = tid + r * 256;
                int mm = idx >> 3, k4 = idx & 7;
                cpasync16(ab + (uint32_t)(mm * 36 + k4 * 4) * 4u,
                          Ap + (long)mm * ldA + k0 + k4 * 4, true);
            }
#pragma unroll
            for (int r = 0; r < 3; r++) {
                int idx = tid + r * 256;
                int rr = idx >> 3, k4 = idx & 7;
                int g = rr >> 5, j = j0 + (rr & 31);
                cpasync16(bb + (uint32_t)(rr * 36 + k4 * 4) * 4u,
                          Bp + (long)(g * 128 + j) * 128 + k0 + k4 * 4, true);
            }
            asm volatile("cp.async.commit_group;");
        };

        issue(0, 0);
        for (int it = 0; it < 4; it++) {
            int cur = it & 1;
            if (it + 1 < 4) {
                issue(it + 1, cur ^ 1);
                asm volatile("cp.async.wait_group 1;");
            } else {
                asm volatile("cp.async.wait_group 0;");
            }
            __syncthreads();

            uint32_t ab = smbase + (uint32_t)(cur * SSTRIDE) * 4u;
            uint32_t bb = ab + 2304u * 4u;
#pragma unroll
            for (int kk = 0; kk < 32; kk += 8) {
                uint32_t a[4], b[6][2];
                ldsm4(a, ab + (uint32_t)(((wrg * 16 + rowA) * 36 + kk + colA) * 4));
#pragma unroll
                for (int p = 0; p < 3; p++) {
                    uint32_t r4[4];
                    ldsm4(r4, bb + (uint32_t)(((wcg * 48 + p * 16 + rowB) * 36 + kk + colB) * 4));
                    b[2 * p][0] = r4[0]; b[2 * p][1] = r4[1];
                    b[2 * p + 1][0] = r4[2]; b[2 * p + 1][1] = r4[3];
                }
#pragma unroll
                for (int nt = 0; nt < 6; nt++)
                    mma_tf32(acc[nt], a, b[nt]);
            }
            __syncthreads();
        }

#pragma unroll
        for (int nt = 0; nt < 6; nt++)
#pragma unroll
            for (int q = 0; q < 4; q++) {
                int m = wrg * 16 + lr + (q >> 1) * 8;
                int rr = wcg * 48 + nt * 8 + lc + (q & 1);
                sm[xoff + m * 96 + rr] = acc[nt][q];
            }
        __syncthreads();
    };

    // ---- main GEMM: C(64 x 48) = A(64 x 1024) @ B^T, depth-3 pipeline ----
    int wrm = warp >> 1, wcm = warp & 1;   // 4x2 warps, warp tile 16x24
    auto run_gemm_main = [&](const float* Ap, const float* Bp, int j0) {
        float acc[3][4];
#pragma unroll
        for (int nt = 0; nt < 3; nt++)
#pragma unroll
            for (int q = 0; q < 4; q++) acc[nt][q] = 0.f;

        auto issue = [&](int it, int s) {
            int k0 = it * 32;
            uint32_t ab = smbase + (uint32_t)(s * MSTRIDE) * 4u;
            uint32_t bb = ab + 2304u * 4u;
            // A: 64 rows x 8 f4 = 512, 2/thread
#pragma unroll
            for (int r = 0; r < 2; r++) {
                int idx = tid + r * 256;
                int mm = idx >> 3, k4 = idx & 7;
                cpasync16(ab + (uint32_t)(mm * 36 + k4 * 4) * 4u,
                          Ap + (long)mm * 1024 + k0 + k4 * 4, true);
            }
            // B: 48 rows x 8 f4 = 384
            {
                int idx = tid;
                int rr = idx >> 3, k4 = idx & 7;
                int g = rr >> 4, j = j0 + (rr & 15);
                cpasync16(bb + (uint32_t)(rr * 36 + k4 * 4) * 4u,
                          Bp + (long)(g * 1024 + j) * 1024 + k0 + k4 * 4, true);
            }
            if (tid < 128) {
                int idx = tid + 256;
                int rr = idx >> 3, k4 = idx & 7;
                int g = rr >> 4, j = j0 + (rr & 15);
                cpasync16(bb + (uint32_t)(rr * 36 + k4 * 4) * 4u,
                          Bp + (long)(g * 1024 + j) * 1024 + k0 + k4 * 4, true);
            }
            asm volatile("cp.async.commit_group;");
        };

        issue(0, 0);
        issue(1, 1);
        for (int it = 0; it < 32; it++) {
            int cur = it - (it / 3) * 3;   // it % 3
            if (it + 2 < 32) {
                int nx = it + 2;
                issue(nx, nx - (nx / 3) * 3);
                asm volatile("cp.async.wait_group 2;");
            } else if (it + 1 < 32) {
                asm volatile("cp.async.wait_group 1;");
            } else {
                asm volatile("cp.async.wait_group 0;");
            }
            __syncthreads();

            uint32_t ab = smbase + (uint32_t)(cur * MSTRIDE) * 4u;
            uint32_t bb = ab + 2304u * 4u;
#pragma unroll
            for (int kk = 0; kk < 32; kk += 8) {
                uint32_t a[4], b[3][2];
                ldsm4(a, ab + (uint32_t)(((wrm * 16 + rowA) * 36 + kk + colA) * 4));
                {
                    uint32_t r4[4];
                    ldsm4(r4, bb + (uint32_t)(((wcm * 24 + rowB) * 36 + kk + colB) * 4));
                    b[0][0] = r4[0]; b[0][1] = r4[1];
                    b[1][0] = r4[2]; b[1][1] = r4[3];
                }
                {
                    uint32_t r2[2];
                    ldsm2(r2, bb + (uint32_t)(((wcm * 24 + 16 + rowB2) * 36 + kk + colB2) * 4));
                    b[2][0] = r2[0]; b[2][1] = r2[1];
                }
#pragma unroll
                for (int nt = 0; nt < 3; nt++)
                    mma_tf32(acc[nt], a, b[nt]);
            }
            __syncthreads();
        }

#pragma unroll
        for (int nt = 0; nt < 3; nt++)
#pragma unroll
            for (int q = 0; q < 4; q++) {
                int m = wrm * 16 + lr + (q >> 1) * 8;
                int rr = wcm * 24 + nt * 8 + lc + (q & 1);
                sm[X_GH2 + m * 48 + rr] = acc[nt][q];
            }
        __syncthreads();
    };

    for (int t = 0; t < 32; t++) {
        if (isMain) {
            int dir = blockIdx.x >> 6;
            int j0 = (blockIdx.x & 63) * 16;
            const float* Whh = g_scratch + (dir ? O_WHB : O_WHF);
            float* hbase = g_scratch + O_HST + (long)dir * 131072;
            const float* hin = hbase + (long)(t & 1) * 65536;
            float* hout = hbase + (long)((t + 1) & 1) * 65536;
            int tt = dir ? (31 - t) : t;

            run_gemm_main(hin, Whh, j0);

            int j = tid & 15, mg = tid >> 4;
            int col = j0 + j;
            const float* gi = g_scratch + O_GIALL + (long)dir * 3072;
            const float* bhh = g_scratch + O_WHF - 8192 + (long)dir * 3072;
            float* txt = g_scratch + O_TXT;
            float br = bhh[col], bz2 = bhh[1024 + col], bn = bhh[2048 + col];
            bool storeFirst = dir == 0 ? (tt < 16) : (tt >= 16);
#pragma unroll
            for (int i = 0; i < 4; i++) {
                int m = mg * 4 + i;
                const float* girow = gi + ((long)tt * 64 + m) * 6272;
                float gh_r = sm[X_GH2 + m * 48 + j];
                float gh_z = sm[X_GH2 + m * 48 + 16 + j];
                float gh_n = sm[X_GH2 + m * 48 + 32 + j];
                float r = sigf(girow[col] + gh_r + br);
                float z = sigf(girow[1024 + col] + gh_z + bz2);
                float n = tanhf(girow[2048 + col] + r * (gh_n + bn));
                float hold = hin[m * 1024 + col];
                float hn = (1.f - z) * n + z * hold;
                hout[m * 1024 + col] = rnd_tf32(hn);
                long ti = ((long)m * 32 + tt) * 1024 + col;
                if (storeFirst) txt[ti] = 0.5f * hn;
                else            txt[ti] += 0.5f * hn;
            }
        } else {
            int b2 = blockIdx.x - 128;
            int img = b2 >> 1;
            int cg = b2 & 1;
            const float* Whh = g_scratch + O_WHH + (long)img * 49152;
            const float* Wih = g_scratch + O_WIH + (long)img * 49152;
            const float* bhh = g_scratch + O_BHH + (long)img * 384;
            const float* bih = g_scratch + O_BIH + (long)img * 384;
            float* hb = g_scratch + O_HG;
            const float* hin = hb + (long)(t & 1) * 524288 + (long)img * 8192;
            float* hout = hb + (long)((t + 1) & 1) * 524288 + (long)img * 8192;
            float* hmax = g_scratch + O_HMAX + (long)img * 8192;
            const float* crbase = g_scratch + O_GIALL + (long)t * 64 * 6272 + 6144;

#pragma unroll
            for (int sub = 0; sub < 2; sub++) {
                int j0 = cg * 64 + sub * 32;
                run_gemm_gen(hin, 128, Whh, j0, X_GH);
                run_gemm_gen(crbase, 6272, Wih, j0, X_GI);

                int j = tid & 31, mg = tid >> 5;
                int col = j0 + j;
                float cr_ = bih[col] + bhh[col];
                float cz_ = bih[128 + col] + bhh[128 + col];
                float bni = bih[256 + col], bnh = bhh[256 + col];
#pragma unroll
                for (int i = 0; i < 8; i++) {
                    int m = mg * 8 + i;
                    float gh_r = sm[X_GH + m * 96 + j];
                    float gh_z = sm[X_GH + m * 96 + 32 + j];
                    float gh_n = sm[X_GH + m * 96 + 64 + j];
                    float gi_r = sm[X_GI + m * 96 + j];
                    float gi_z = sm[X_GI + m * 96 + 32 + j];
                    float gi_n = sm[X_GI + m * 96 + 64 + j];
                    float r = sigf(gi_r + gh_r + cr_);
                    float z = sigf(gi_z + gh_z + cz_);
                    float n = tanhf(gi_n + bni + r * (gh_n + bnh));
                    float hold = hin[m * 128 + col];
                    float hn = (1.f - z) * n + z * hold;
                    hout[m * 128 + col] = rnd_tf32(hn);
                    hmax[m * 128 + col] = fmaxf(hmax[m * 128 + col], hn);
                }
            }
        }

        // ---- software grid barrier ----
        __syncthreads();
        __threadfence();
        if (tid == 0) {
            atomicAdd(&g_barcnt, 1u);
            unsigned tgt = (unsigned)NBLK_STEP * (unsigned)(t + 1);
            while (*(volatile unsigned int*)&g_barcnt < tgt) {}
            __threadfence();
        }
        __syncthreads();
    }
}

// ---------------------------------------------------------------------------
// Fused image path: region mean -> IEG, l2norm -> IVN, reduce-proj -> IGV.
// ---------------------------------------------------------------------------
__global__ __launch_bounds__(256) void imgvec_k(
    const float* __restrict__ img_embed,
    const float* __restrict__ W_reduce_img, const float* __restrict__ b_reduce_img)
{
    __shared__ float s_ieg[1024];
    __shared__ float red[256];
    int b = blockIdx.x, tid = threadIdx.x;
    float vals[4], ss = 0.f;
#pragma unroll
    for (int i = 0; i < 4; i++) {
        int c = i * 256 + tid;
        float s = 0.f;
        for (int g = 0; g < 36; g++) s += img_embed[(long)b * 36864 + (long)g * 1024 + c];
        s *= (1.f / 36.f);
        vals[i] = s;
        ss += s * s;
        s_ieg[c] = s;
        g_scratch[O_IEG + (long)b * 1024 + c] = s;
    }
    red[tid] = ss;
    __syncthreads();
    for (int o = 128; o > 0; o >>= 1) { if (tid < o) red[tid] += red[tid + o]; __syncthreads(); }
    float inv = 1.f / (sqrtf(red[0]) + 1e-8f);
#pragma unroll
    for (int i = 0; i < 4; i++) {
        int c = i * 256 + tid;
        g_scratch[O_IVN + (long)b * 1024 + c] = vals[i] * inv;
    }
    int o = tid >> 1, half = tid & 1;
    const float* wrow = W_reduce_img + (long)o * 1024 + half * 512;
    const float* xrow = s_ieg + half * 512;
    float acc = 0.f;
#pragma unroll 4
    for (int k = 0; k < 512; k += 4) {
        float4 w = *reinterpret_cast<const float4*>(&wrow[k]);
        float4 x = *reinterpret_cast<const float4*>(&xrow[k]);
        acc += w.x * x.x + w.y * x.y + w.z * x.z + w.w * x.w;
    }
    acc += __shfl_xor_sync(0xffffffffu, acc, 1);
    if (half == 0)
        g_scratch[O_IGV + (long)b * 128 + o] = acc + b_reduce_img[o];
}

// attention scores + softmax over fused QKV buffer (row stride 1280)
__global__ __launch_bounds__(256) void attn_k() {
    int gw = (blockIdx.x * blockDim.x + threadIdx.x) >> 5;
    int lane = threadIdx.x & 31;
    if (gw >= 2048) return;
    int b = gw >> 5;
    const float* qr = g_scratch + O_QKV + (long)gw * 1280;
    const float* kr = g_scratch + O_QKV + ((long)b * 32 + lane) * 1280 + 128;
    float s = 0.f;
#pragma unroll 8
    for (int o = 0; o < 128; o++) s += qr[o] * kr[o];
    float mx = s;
#pragma unroll
    for (int off = 16; off > 0; off >>= 1) mx = fmaxf(mx, __shfl_xor_sync(0xffffffffu, mx, off));
    float e = expf(s - mx);
    float sum = e;
#pragma unroll
    for (int off = 16; off > 0; off >>= 1) sum += __shfl_xor_sync(0xffffffffu, sum, off);
    g_scratch[O_ATT + (long)gw * 32 + lane] = e / sum;
}

__global__ __launch_bounds__(32) void aw_k(const int* __restrict__ lens) {
    int b = blockIdx.x, s = threadIdx.x;
    int len = lens[b];
    float a = 0.f;
    for (int tt = 0; tt < len; tt++) a += g_scratch[O_ATT + ((long)b * 32 + tt) * 32 + s];
    g_scratch[O_AW + b * 32 + s] = a;
}

__global__ __launch_bounds__(256) void txt_embed_k(const int* __restrict__ lens,
                                                   const float* __restrict__ gamma) {
    int b = blockIdx.y;
    int c = blockIdx.x * 256 + threadIdx.x;
    __shared__ float saw[32];
    if (threadIdx.x < 32) saw[threadIdx.x] = g_scratch[O_AW + b * 32 + threadIdx.x];
    __syncthreads();
    int len = lens[b];
    float g = *gamma;
    float a1 = 0.f;
    for (int tt = 0; tt < len; tt++) a1 += g_scratch[O_TXT + ((long)b * 32 + tt) * 1024 + c];
    float a2 = 0.f;
#pragma unroll
    for (int s = 0; s < 32; s++)
        a2 += saw[s] * g_scratch[O_QKV + ((long)b * 32 + s) * 1280 + 256 + c];
    g_scratch[O_TE + (long)b * 1024 + c] = (a1 + g * a2) / (float)len;
}

// sims[i,b] = (y . iv_i) / (|y| + eps)
__global__ __launch_bounds__(256) void sims_k(float* __restrict__ out) {
    int img = blockIdx.y, b = blockIdx.x;
    int tid = threadIdx.x;
    const float* y = g_scratch + O_Y + (long)img * 65536 + (long)b * 1024;
    const float* iv = g_scratch + O_IVN + (long)img * 1024;
    float ss = 0.f, dp = 0.f;
#pragma unroll
    for (int i = 0; i < 4; i++) {
        int c = i * 256 + tid;
        float v = y[c];
        ss += v * v;
        dp += v * iv[c];
    }
    __shared__ float r1[256], r2[256];
    r1[tid] = ss; r2[tid] = dp;
    __syncthreads();
    for (int o = 128; o > 0; o >>= 1) {
        if (tid < o) { r1[tid] += r1[tid + o]; r2[tid] += r2[tid + o]; }
        __syncthreads();
    }
    if (tid == 0) out[img * 64 + b] = r2[0] / (sqrtf(r1[0]) + 1e-8f);
}

// ---------------------------------------------------------------------------
extern "C" void kernel_launch(void* const* d_in, const int* in_sizes, int n_in,
                              void* d_out, int out_size) {
    const float* img_embed    = (const float*)d_in[0];
    const float* cap_embed    = (const float*)d_in[1];
    const int*   lens         = (const int*)d_in[2];
    const float* W_reduce_img = (const float*)d_in[3];
    const float* b_reduce_img = (const float*)d_in[4];
    const float* W_reduce_txt = (const float*)d_in[5];
    const float* b_reduce_txt = (const float*)d_in[6];
    const float* gru_Wih_f    = (const float*)d_in[7];
    const float* gru_Whh_f    = (const float*)d_in[8];
    const float* gru_bih_f    = (const float*)d_in[9];
    const float* gru_bhh_f    = (const float*)d_in[10];
    const float* gru_Wih_b    = (const float*)d_in[11];
    const float* gru_Whh_b    = (const float*)d_in[12];
    const float* gru_bih_b    = (const float*)d_in[13];
    const float* gru_bhh_b    = (const float*)d_in[14];
    const float* sa_Wq        = (const float*)d_in[15];
    const float* sa_bq        = (const float*)d_in[16];
    const float* sa_Wk        = (const float*)d_in[17];
    const float* sa_bk        = (const float*)d_in[18];
    const float* sa_Wv        = (const float*)d_in[19];
    const float* sa_bv        = (const float*)d_in[20];
    const float* sa_gamma     = (const float*)d_in[21];
    const float* gen_Wih      = (const float*)d_in[22];
    const float* gen_bih      = (const float*)d_in[23];
    const float* gen_Whh      = (const float*)d_in[24];
    const float* gen_bhh      = (const float*)d_in[25];
    const float* gen_Wbih     = (const float*)d_in[26];
    const float* gen_bbih     = (const float*)d_in[27];
    const float* gen_Wbhh     = (const float*)d_in[28];
    const float* gen_bbhh     = (const float*)d_in[29];
    const float* W_txt_fc     = (const float*)d_in[30];
    const float* b_txt_fc     = (const float*)d_in[31];

    float* S = nullptr;
    cudaGetSymbolAddress((void**)&S, g_scratch);

    const int SMEM_TF32 = 2 * 2 * STG * 4;   // 73728 B
    const int SMEM_STEP = 98304;
    cudaFuncSetAttribute(gemm_tf32<0>, cudaFuncAttributeMaxDynamicSharedMemorySize, SMEM_TF32);
    cudaFuncSetAttribute(gemm_tf32<1>, cudaFuncAttributeMaxDynamicSharedMemorySize, SMEM_TF32);
    cudaFuncSetAttribute(steps_k, cudaFuncAttributeMaxDynamicSharedMemorySize, SMEM_STEP);

    init_k<<<4096, 256>>>();

    // Concatenate weights for fused GEMMs (D2D copies, graph-capturable)
    cudaMemcpyAsync(S + O_WGI,              gru_Wih_f,    3072L*300*4, cudaMemcpyDeviceToDevice);
    cudaMemcpyAsync(S + O_WGI + 3072L*300,  gru_Wih_b,    3072L*300*4, cudaMemcpyDeviceToDevice);
    cudaMemcpyAsync(S + O_WGI + 6144L*300,  W_reduce_txt, 128L*300*4,  cudaMemcpyDeviceToDevice);
    cudaMemcpyAsync(S + O_BGI,              gru_bih_f,    3072L*4,     cudaMemcpyDeviceToDevice);
    cudaMemcpyAsync(S + O_BGI + 3072,       gru_bih_b,    3072L*4,     cudaMemcpyDeviceToDevice);
    cudaMemcpyAsync(S + O_BGI + 6144,       b_reduce_txt, 128L*4,      cudaMemcpyDeviceToDevice);
    cudaMemcpyAsync(S + O_WQKV,             sa_Wq,        128L*1024*4, cudaMemcpyDeviceToDevice);
    cudaMemcpyAsync(S + O_WQKV + 128L*1024, sa_Wk,        128L*1024*4, cudaMemcpyDeviceToDevice);
    cudaMemcpyAsync(S + O_WQKV + 256L*1024, sa_Wv,        1024L*1024*4,cudaMemcpyDeviceToDevice);
    cudaMemcpyAsync(S + O_BQKV,             sa_bq,        128L*4,      cudaMemcpyDeviceToDevice);
    cudaMemcpyAsync(S + O_BQKV + 128,       sa_bk,        128L*4,      cudaMemcpyDeviceToDevice);
    cudaMemcpyAsync(S + O_BQKV + 256,       sa_bv,        1024L*4,     cudaMemcpyDeviceToDevice);
    // main-GRU hidden biases just below O_WHF (overlaps tail of Y; Y written later)
    cudaMemcpyAsync(S + O_WHF - 8192,        gru_bhh_f,   3072L*4,     cudaMemcpyDeviceToDevice);
    cudaMemcpyAsync(S + O_WHF - 8192 + 3072, gru_bhh_b,   3072L*4,     cudaMemcpyDeviceToDevice);

    // pre-rounded tf32 copies of main recurrent weights
    cvtw_k<<<3072, 256>>>(gru_Whh_f, S + O_WHF, 3072L*1024/4);
    cvtw_k<<<3072, 256>>>(gru_Whh_b, S + O_WHB, 3072L*1024/4);

    // Fused GI_f|GI_b|CR projection: (T*B, 6272); CR columns pre-rounded (rnd=2)
    gemm_tf32<1><<<dim3(49, 16, 1), 256, SMEM_TF32>>>(
        cap_embed, S + O_WGI, S + O_BGI, nullptr, S + O_GIALL,
        2048, 6272, 300, 300, 300, 0, 0, 0, 0, 2);

    // image path: pool + l2norm + reduce projection, fused
    imgvec_k<<<64, 256>>>(img_embed, W_reduce_img, b_reduce_img);

    // generated GRU weights per image (outputs pre-rounded to tf32)
    gemm_tf32<0><<<dim3(384, 1, 1), 256, SMEM_TF32>>>(
        S + O_IGV, gen_Wih, gen_bih, nullptr, S + O_WIH,
        64, 49152, 128, 128, 128, 0, 0, 0, 0, 1);
    gemm_tf32<0><<<dim3(384, 1, 1), 256, SMEM_TF32>>>(
        S + O_IGV, gen_Whh, gen_bhh, nullptr, S + O_WHH,
        64, 49152, 128, 128, 128, 0, 0, 0, 0, 1);
    gemm_tf32<0><<<dim3(3, 1, 1), 256, SMEM_TF32>>>(
        S + O_IGV, gen_Wbih, gen_bbih, nullptr, S + O_BIH,
        64, 384, 128, 128, 128, 0, 0, 0, 0, 0);
    gemm_tf32<0><<<dim3(3, 1, 1), 256, SMEM_TF32>>>(
        S + O_IGV, gen_Wbhh, gen_bbhh, nullptr, S + O_BHH,
        64, 384, 128, 128, 128, 0, 0, 0, 0, 0);

    // ALL 32 recurrent steps in one persistent launch (grid barrier inside)
    steps_k<<<NBLK_STEP, 256, SMEM_STEP>>>();

    // fused Q|K|V projection: (B*T, 1280)
    gemm_tf32<0><<<dim3(10, 16, 1), 256, SMEM_TF32>>>(
        S + O_TXT, S + O_WQKV, S + O_BQKV, nullptr, S + O_QKV,
        2048, 1280, 1024, 1024, 1024, 0, 0, 0, 0, 0);
    attn_k<<<256, 256>>>();
    aw_k<<<64, 32>>>(lens);
    txt_embed_k<<<dim3(4, 64), 256>>>(lens, sa_gamma);

    // final FC: shared part + per-image correction
    gemm_tf32<0><<<dim3(8, 1, 1), 256, SMEM_TF32>>>(
        S + O_TE, W_txt_fc, b_txt_fc, nullptr, S + O_FCB,
        64, 1024, 1024, 1024, 1152, 0, 0, 0, 0, 0);
    gemm_tf32<0><<<dim3(8, 1, 64), 256, SMEM_TF32>>>(
        S + O_HMAX, W_txt_fc + 1024, nullptr, S + O_FCB, S + O_Y,
        64, 1024, 128, 128, 1152, 64L * 128, 0, 0, 64L * 1024, 0);

    sims_k<<<dim3(64, 64), 256>>>((float*)d_out);
}

// round 17
// speedup vs baseline: 5.6639x; 1.0512x over previous
#include <cuda_runtime.h>
#include <cuda_bf16.h>
#include <math.h>
#include <stdint.h>

// ---------------------------------------------------------------------------
// Problem constants:  L=1024, R=128, T=32, B=64, DIN=300, REG=36, R3=384, H3=3072
// ---------------------------------------------------------------------------

// ---------------- scratch layout (floats) ----------------
#define SZ_GIALL   (2048L*6272)      // fused [GI_f | GI_b | CR] rows (t*64+b)
#define SZ_TXT     (64L*32*1024)
#define SZ_HST     (2L*2*64*1024)
#define SZ_WGI     (6272L*300)
#define SZ_BGI     (6400L)
#define SZ_QKV     (2048L*1280)
#define SZ_WQKV    (1280L*1024)
#define SZ_BQKV    (1280L)
#define SZ_ATT     (2048L*32)
#define SZ_AW      (64L*32)
#define SZ_TE      (64L*1024)
#define SZ_IEG     (64L*1024)
#define SZ_IVN     (64L*1024)
#define SZ_IGV     (64L*128)
#define SZ_WG      (64L*49152)
#define SZ_BG      (64L*384)
#define SZ_HG      (2L*64*64*128)
#define SZ_HMAX    (64L*64*128)
#define SZ_FCB     (64L*1024)
#define SZ_Y       (64L*64*1024)
#define SZ_WHP     (3072L*1024)      // pre-rounded main Whh per dir

#define O_GIALL 0L
#define O_TXT   (O_GIALL + SZ_GIALL)
#define O_HST   (O_TXT + SZ_TXT)
#define O_WGI   (O_HST + SZ_HST)
#define O_BGI   (O_WGI + SZ_WGI)
#define O_QKV   (O_BGI + SZ_BGI)
#define O_WQKV  (O_QKV + SZ_QKV)
#define O_BQKV  (O_WQKV + SZ_WQKV)
#define O_ATT   (O_BQKV + SZ_BQKV)
#define O_AW    (O_ATT + SZ_ATT)
#define O_TE    (O_AW + SZ_AW)
#define O_IEG   (O_TE + SZ_TE)
#define O_IVN   (O_IEG + SZ_IEG)
#define O_IGV   (O_IVN + SZ_IVN)
#define O_WIH   (O_IGV + SZ_IGV)
#define O_WHH   (O_WIH + SZ_WG)
#define O_BIH   (O_WHH + SZ_WG)
#define O_BHH   (O_BIH + SZ_BG)
#define O_HG    (O_BHH + SZ_BG)
#define O_HMAX  (O_HG + SZ_HG)
#define O_FCB   (O_HMAX + SZ_HMAX)
#define O_Y     (O_FCB + SZ_FCB)
#define O_WHF   (O_Y + SZ_Y)
#define O_WHB   (O_WHF + SZ_WHP)
#define SCRATCH_TOTAL (O_WHB + SZ_WHP)

__device__ float g_scratch[SCRATCH_TOTAL];
__device__ unsigned int g_barcnt;

#define NBLK_STEP 256

__device__ __forceinline__ float sigf(float x) { return 1.f / (1.f + expf(-x)); }

__device__ __forceinline__ uint32_t f2tf32(float x) {
    uint32_t r;
    asm("cvt.rna.tf32.f32 %0, %1;" : "=r"(r) : "f"(x));
    return r;
}
__device__ __forceinline__ float rnd_tf32(float x) {
    return __uint_as_float(f2tf32(x));
}

__device__ __forceinline__ void ldsm4(uint32_t* r, uint32_t addr) {
    asm volatile("ldmatrix.sync.aligned.m8n8.x4.shared.b16 {%0,%1,%2,%3}, [%4];"
                 : "=r"(r[0]), "=r"(r[1]), "=r"(r[2]), "=r"(r[3]) : "r"(addr));
}
__device__ __forceinline__ void ldsm2(uint32_t* r, uint32_t addr) {
    asm volatile("ldmatrix.sync.aligned.m8n8.x2.shared.b16 {%0,%1}, [%2];"
                 : "=r"(r[0]), "=r"(r[1]) : "r"(addr));
}

__device__ __forceinline__ void mma_tf32(float* c, const uint32_t* a, const uint32_t* b) {
    asm volatile(
        "mma.sync.aligned.m16n8k8.row.col.f32.tf32.tf32.f32 "
        "{%0,%1,%2,%3}, {%4,%5,%6,%7}, {%8,%9}, {%0,%1,%2,%3};"
        : "+f"(c[0]), "+f"(c[1]), "+f"(c[2]), "+f"(c[3])
        : "r"(a[0]), "r"(a[1]), "r"(a[2]), "r"(a[3]), "r"(b[0]), "r"(b[1]));
}

__device__ __forceinline__ void cpasync16(uint32_t dst, const void* src, bool pred) {
    int sz = pred ? 16 : 0;
    asm volatile("cp.async.cg.shared.global [%0], [%1], 16, %2;"
                 :: "r"(dst), "l"(src), "r"(sz));
}

// ---------------------------------------------------------------------------
__global__ __launch_bounds__(256) void init_k() {
    long idx = (long)blockIdx.x * 256 + threadIdx.x;
    if (idx == 0) g_barcnt = 0u;
    if (idx < SZ_HST)  g_scratch[O_HST + idx] = 0.f;
    if (idx < SZ_HG)   g_scratch[O_HG + idx] = 0.f;
    if (idx < SZ_HMAX) g_scratch[O_HMAX + idx] = -1e30f;
}

// convert-copy: dst = tf32_round(src), float4 granularity
__global__ __launch_bounds__(256) void cvtw_k(const float* __restrict__ src,
                                              float* __restrict__ dst, long n4) {
    long i = ((long)blockIdx.x * 256 + threadIdx.x);
    if (i >= n4) return;
    float4 v = reinterpret_cast<const float4*>(src)[i];
    v.x = rnd_tf32(v.x);
    v.y = rnd_tf32(v.y);
    v.z = rnd_tf32(v.z);
    v.w = rnd_tf32(v.w);
    reinterpret_cast<float4*>(dst)[i] = v;
}

// ---------------------------------------------------------------------------
// A indexing modes:
//   0: A[m*lda + k]
//   1: m=t*64+b over cap_embed (B,T,300):  A[(m&63)*9600 + (m>>6)*300 + k]
// ---------------------------------------------------------------------------
template <int MODE>
__device__ __forceinline__ long a_idx(int m, int k, int lda) {
    if (MODE == 0) return (long)m * lda + k;
    { int b = m & 63, t = m >> 6; return (long)b * 9600 + (long)t * 300 + k; }
}

// ---------------------------------------------------------------------------
// TF32 tensor-core GEMM: 128x128 tile, 8 warps, m16n8k8 mma.
// cp.async double-buffered staging, cvt after ldmatrix.
// rnd: 0 = none; 1 = round all outputs to tf32; 2 = round outputs with n>=6144.
// ---------------------------------------------------------------------------
#define TRS 36
#define STG (128 * TRS)

template <int MODE>
__global__ __launch_bounds__(256) void gemm_tf32(
    const float* __restrict__ A, const float* __restrict__ W,
    const float* __restrict__ bias, const float* __restrict__ Cadd,
    float* __restrict__ C,
    int M, int N, int K, int lda, int ldw,
    long aBS, long wBS, long bBS, long cBS, int rnd)
{
    extern __shared__ float sm[];

    int bz = blockIdx.z;
    A += (long)bz * aBS;
    W += (long)bz * wBS;
    C += (long)bz * cBS;
    const float* biasp = bias ? (bias + (long)bz * bBS) : nullptr;

    int tid = threadIdx.x;
    int warp = tid >> 5, lane = tid & 31;
    int wr = warp >> 2, wc = warp & 3;
    int m0 = blockIdx.y * 128, n0 = blockIdx.x * 128;

    float acc[4][4][4];
#pragma unroll
    for (int mt = 0; mt < 4; mt++)
#pragma unroll
        for (int nt = 0; nt < 4; nt++)
#pragma unroll
            for (int q = 0; q < 4; q++) acc[mt][nt][q] = 0.f;

    uint32_t smbase = (uint32_t)__cvta_generic_to_shared(sm);

    int rowA = (lane & 7) + ((lane >> 3) & 1) * 8;
    int colA = (lane >> 4) * 4;
    int rowB = (lane & 7) + (lane >> 4) * 8;
    int colB = ((lane >> 3) & 1) * 4;

    const int NIT = (K + 31) / 32;

    auto issue = [&](int it, int s) {
        int k0 = it * 32;
        uint32_t abase = smbase + (uint32_t)(s * 2 * STG) * 4u;
        uint32_t bbase = abase + (uint32_t)STG * 4u;
#pragma unroll
        for (int r = 0; r < 4; r++) {
            int idx = tid + r * 256;
            int mm = idx >> 3, k4 = idx & 7;
            int m = m0 + mm, k = k0 + k4 * 4;
            bool p = (m < M) && (k < K);
            const float* src = p ? &A[a_idx<MODE>(m, k, lda)] : A;
            cpasync16(abase + (uint32_t)(mm * TRS + k4 * 4) * 4u, src, p);
        }
#pragma unroll
        for (int r = 0; r < 4; r++) {
            int idx = tid + r * 256;
            int nn = idx >> 3, k4 = idx & 7;
            int n = n0 + nn, k = k0 + k4 * 4;
            bool p = (n < N) && (k < K);
            const float* src = p ? &W[(long)n * ldw + k] : W;
            cpasync16(bbase + (uint32_t)(nn * TRS + k4 * 4) * 4u, src, p);
        }
        asm volatile("cp.async.commit_group;");
    };

    issue(0, 0);
    for (int it = 0; it < NIT; it++) {
        int cur = it & 1;
        if (it + 1 < NIT) {
            issue(it + 1, cur ^ 1);
            asm volatile("cp.async.wait_group 1;");
        } else {
            asm volatile("cp.async.wait_group 0;");
        }
        __syncthreads();

        uint32_t asb = smbase + (uint32_t)(cur * 2 * STG) * 4u;
        uint32_t bsb = asb + (uint32_t)STG * 4u;
#pragma unroll
        for (int kk = 0; kk < 32; kk += 8) {
            uint32_t a[4][4], b[4][2];
#pragma unroll
            for (int mt = 0; mt < 4; mt++) {
                ldsm4(a[mt], asb +
                      (uint32_t)(((wr * 64 + mt * 16 + rowA) * TRS + kk + colA) * 4));
#pragma unroll
                for (int q = 0; q < 4; q++)
                    a[mt][q] = f2tf32(__uint_as_float(a[mt][q]));
            }
#pragma unroll
            for (int p = 0; p < 2; p++) {
                uint32_t r4[4];
                ldsm4(r4, bsb +
                      (uint32_t)(((wc * 32 + p * 16 + rowB) * TRS + kk + colB) * 4));
#pragma unroll
                for (int q = 0; q < 4; q++)
                    r4[q] = f2tf32(__uint_as_float(r4[q]));
                b[2 * p][0] = r4[0]; b[2 * p][1] = r4[1];
                b[2 * p + 1][0] = r4[2]; b[2 * p + 1][1] = r4[3];
            }
#pragma unroll
            for (int mt = 0; mt < 4; mt++)
#pragma unroll
                for (int nt = 0; nt < 4; nt++)
                    mma_tf32(acc[mt][nt], a[mt], b[nt]);
        }
        __syncthreads();
    }

    int lr = lane >> 2, lc = (lane & 3) * 2;
#pragma unroll
    for (int mt = 0; mt < 4; mt++) {
#pragma unroll
        for (int part = 0; part < 2; part++) {
            int m = m0 + wr * 64 + mt * 16 + lr + part * 8;
            if (m >= M) continue;
#pragma unroll
            for (int nt = 0; nt < 4; nt++) {
                int n = n0 + wc * 32 + nt * 8 + lc;
                float v0 = acc[mt][nt][part * 2 + 0];
                float v1 = acc[mt][nt][part * 2 + 1];
                if (biasp) { v0 += biasp[n]; v1 += biasp[n + 1]; }
                if (Cadd) {
                    v0 += Cadd[(long)m * N + n];
                    v1 += Cadd[(long)m * N + n + 1];
                }
                if (rnd == 1 || (rnd == 2 && n >= 6144)) v0 = rnd_tf32(v0);
                if (rnd == 1 || (rnd == 2 && n + 1 >= 6144)) v1 = rnd_tf32(v1);
                C[(long)m * N + n] = v0;
                C[(long)m * N + n + 1] = v1;
            }
        }
    }
}

// ---------------------------------------------------------------------------
// Persistent recurrent kernel v3: ONE launch, 256 blocks, 32 steps inside.
//   blocks [0,128):   main bi-GRU. dir = bx>>6, 16-col group (bx&63). K=1024.
//                     N=48. 64-wide K tiles (16 iters), depth-2 pipeline,
//                     gi tile prefetched to SMEM overlapping the GEMM.
//   blocks [128,256): gen GRU. img = (bx-128)>>1, cg = (bx-128)&1; two 32-col
//                     subgroups: gh (h@Whh_g^T) + gi (cr@Wih_g^T), K=128.
// ALL mma operands pre-rounded tf32 -> zero cvt in inner loops.
// SMEM layouts (floats):
//   main: stage=(64+48)x68=7616, 2 stages [0,15232); gh @15232 (3072);
//         gi @18304 (3072). Total 21376 -> 85504 B.
//   gen:  2 stages x 5760 = [0,11520); gh @11520; gi @17664. 23808 -> 95232 B.
// 98304 B dynamic, 2 blocks/SM -> 256 blocks single wave.
// ---------------------------------------------------------------------------
#define SSTRIDE 5760
#define X_GH 11520
#define X_GI 17664
#define MSTRIDE 7616
#define X_GH2 15232
#define X_GI2 18304

__global__ __launch_bounds__(256, 2) void steps_k() {
    extern __shared__ float sm[];
    int tid = threadIdx.x;
    int warp = tid >> 5, lane = tid & 31;
    uint32_t smbase = (uint32_t)__cvta_generic_to_shared(sm);

    int rowA = (lane & 7) + ((lane >> 3) & 1) * 8;
    int colA = (lane >> 4) * 4;
    int rowB = (lane & 7) + (lane >> 4) * 8;
    int colB = ((lane >> 3) & 1) * 4;
    int rowB2 = lane & 7;
    int colB2 = ((lane >> 3) & 1) * 4;
    int lr = lane >> 2, lc = (lane & 3) * 2;

    bool isMain = blockIdx.x < 128;

    // ---- gen GEMM: C(64 x 96) = A(64 x K=128) @ B^T, depth-2, 32-k tiles ----
    int wrg = warp >> 1, wcg = warp & 1;   // 4x2 warps, warp tile 16x48
    auto run_gemm_gen = [&](const float* Ap, int ldA, const float* Bp, int j0, int xoff) {
        float acc[6][4];
#pragma unroll
        for (int nt = 0; nt < 6; nt++)
#pragma unroll
            for (int q = 0; q < 4; q++) acc[nt][q] = 0.f;

        auto issue = [&](int it, int s) {
            int k0 = it * 32;
            uint32_t ab = smbase + (uint32_t)(s * SSTRIDE) * 4u;
            uint32_t bb = ab + 2304u * 4u;
#pragma unroll
            for (int r = 0; r < 2; r++) {
                int idx = tid + r * 256;
                int mm = idx >> 3, k4 = idx & 7;
                cpasync16(ab + (uint32_t)(mm * 36 + k4 * 4) * 4u,
                          Ap + (long)mm * ldA + k0 + k4 * 4, true);
            }
#pragma unroll
            for (int r = 0; r < 3; r++) {
                int idx = tid + r * 256;
                int rr = idx >> 3, k4 = idx & 7;
                int g = rr >> 5, j = j0 + (rr & 31);
                cpasync16(bb + (uint32_t)(rr * 36 + k4 * 4) * 4u,
                          Bp + (long)(g * 128 + j) * 128 + k0 + k4 * 4, true);
            }
            asm volatile("cp.async.commit_group;");
        };

        issue(0, 0);
        for (int it = 0; it < 4; it++) {
            int cur = it & 1;
            if (it + 1 < 4) {
                issue(it + 1, cur ^ 1);
                asm volatile("cp.async.wait_group 1;");
            } else {
                asm volatile("cp.async.wait_group 0;");
            }
            __syncthreads();

            uint32_t ab = smbase + (uint32_t)(cur * SSTRIDE) * 4u;
            uint32_t bb = ab + 2304u * 4u;
#pragma unroll
            for (int kk = 0; kk < 32; kk += 8) {
                uint32_t a[4], b[6][2];
                ldsm4(a, ab + (uint32_t)(((wrg * 16 + rowA) * 36 + kk + colA) * 4));
#pragma unroll
                for (int p = 0; p < 3; p++) {
                    uint32_t r4[4];
                    ldsm4(r4, bb + (uint32_t)(((wcg * 48 + p * 16 + rowB) * 36 + kk + colB) * 4));
                    b[2 * p][0] = r4[0]; b[2 * p][1] = r4[1];
                    b[2 * p + 1][0] = r4[2]; b[2 * p + 1][1] = r4[3];
                }
#pragma unroll
                for (int nt = 0; nt < 6; nt++)
                    mma_tf32(acc[nt], a, b[nt]);
            }
            __syncthreads();
        }

#pragma unroll
        for (int nt = 0; nt < 6; nt++)
#pragma unroll
            for (int q = 0; q < 4; q++) {
                int m = wrg * 16 + lr + (q >> 1) * 8;
                int rr = wcg * 48 + nt * 8 + lc + (q & 1);
                sm[xoff + m * 96 + rr] = acc[nt][q];
            }
        __syncthreads();
    };

    // ---- main GEMM: C(64 x 48) = A(64 x 1024) @ B^T, 64-k tiles, depth-2 ----
    int wrm = warp >> 1, wcm = warp & 1;   // 4x2 warps, warp tile 16x24
    auto run_gemm_main = [&](const float* Ap, const float* Bp, int j0) {
        float acc[3][4];
#pragma unroll
        for (int nt = 0; nt < 3; nt++)
#pragma unroll
            for (int q = 0; q < 4; q++) acc[nt][q] = 0.f;

        auto issue = [&](int it, int s) {
            int k0 = it * 64;
            uint32_t ab = smbase + (uint32_t)(s * MSTRIDE) * 4u;
            uint32_t bb = ab + 4352u * 4u;   // A = 64*68 floats
            // A: 64 rows x 16 f4 = 1024, 4/thread
#pragma unroll
            for (int r = 0; r < 4; r++) {
                int idx = tid + r * 256;
                int mm = idx >> 4, k4 = idx & 15;
                cpasync16(ab + (uint32_t)(mm * 68 + k4 * 4) * 4u,
                          Ap + (long)mm * 1024 + k0 + k4 * 4, true);
            }
            // B: 48 rows x 16 f4 = 768, 3/thread
#pragma unroll
            for (int r = 0; r < 3; r++) {
                int idx = tid + r * 256;
                int rr = idx >> 4, k4 = idx & 15;
                int g = rr >> 4, j = j0 + (rr & 15);
                cpasync16(bb + (uint32_t)(rr * 68 + k4 * 4) * 4u,
                          Bp + (long)(g * 1024 + j) * 1024 + k0 + k4 * 4, true);
            }
            asm volatile("cp.async.commit_group;");
        };

        issue(0, 0);
        for (int it = 0; it < 16; it++) {
            int cur = it & 1;
            if (it + 1 < 16) {
                issue(it + 1, cur ^ 1);
                asm volatile("cp.async.wait_group 1;");
            } else {
                asm volatile("cp.async.wait_group 0;");
            }
            __syncthreads();

            uint32_t ab = smbase + (uint32_t)(cur * MSTRIDE) * 4u;
            uint32_t bb = ab + 4352u * 4u;
#pragma unroll
            for (int kk = 0; kk < 64; kk += 8) {
                uint32_t a[4], b[3][2];
                ldsm4(a, ab + (uint32_t)(((wrm * 16 + rowA) * 68 + kk + colA) * 4));
                {
                    uint32_t r4[4];
                    ldsm4(r4, bb + (uint32_t)(((wcm * 24 + rowB) * 68 + kk + colB) * 4));
                    b[0][0] = r4[0]; b[0][1] = r4[1];
                    b[1][0] = r4[2]; b[1][1] = r4[3];
                }
                {
                    uint32_t r2[2];
                    ldsm2(r2, bb + (uint32_t)(((wcm * 24 + 16 + rowB2) * 68 + kk + colB2) * 4));
                    b[2][0] = r2[0]; b[2][1] = r2[1];
                }
#pragma unroll
                for (int nt = 0; nt < 3; nt++)
                    mma_tf32(acc[nt], a, b[nt]);
            }
            __syncthreads();
        }

#pragma unroll
        for (int nt = 0; nt < 3; nt++)
#pragma unroll
            for (int q = 0; q < 4; q++) {
                int m = wrm * 16 + lr + (q >> 1) * 8;
                int rr = wcm * 24 + nt * 8 + lc + (q & 1);
                sm[X_GH2 + m * 48 + rr] = acc[nt][q];
            }
        __syncthreads();
    };

    for (int t = 0; t < 32; t++) {
        if (isMain) {
            int dir = blockIdx.x >> 6;
            int j0 = (blockIdx.x & 63) * 16;
            const float* Whh = g_scratch + (dir ? O_WHB : O_WHF);
            float* hbase = g_scratch + O_HST + (long)dir * 131072;
            const float* hin = hbase + (long)(t & 1) * 65536;
            float* hout = hbase + (long)((t + 1) & 1) * 65536;
            int tt = dir ? (31 - t) : t;

            // prefetch gi tile (64 m x 3 gates x 16 cols) into smem,
            // own commit group, overlaps the whole GEMM below.
            {
                const float* gisrc = g_scratch + O_GIALL + (long)dir * 3072 +
                                     (long)tt * 64 * 6272 + j0;
                uint32_t gb = smbase + (uint32_t)X_GI2 * 4u;
#pragma unroll
                for (int r = 0; r < 3; r++) {
                    int idx = tid + r * 256;
                    int m = idx / 12, rem = idx - m * 12;
                    int g = rem >> 2, k4 = rem & 3;
                    cpasync16(gb + (uint32_t)(m * 48 + g * 16 + k4 * 4) * 4u,
                              gisrc + (long)m * 6272 + g * 1024 + k4 * 4, true);
                }
                asm volatile("cp.async.commit_group;");
            }

            run_gemm_main(hin, Whh, j0);

            int j = tid & 15, mg = tid >> 4;
            int col = j0 + j;
            const float* bhh = g_scratch + O_WHF - 8192 + (long)dir * 3072;
            float* txt = g_scratch + O_TXT;
            float br = bhh[col], bz2 = bhh[1024 + col], bn = bhh[2048 + col];
            bool storeFirst = dir == 0 ? (tt < 16) : (tt >= 16);
#pragma unroll
            for (int i = 0; i < 4; i++) {
                int m = mg * 4 + i;
                float gi_r = sm[X_GI2 + m * 48 + j];
                float gi_z = sm[X_GI2 + m * 48 + 16 + j];
                float gi_n = sm[X_GI2 + m * 48 + 32 + j];
                float gh_r = sm[X_GH2 + m * 48 + j];
                float gh_z = sm[X_GH2 + m * 48 + 16 + j];
                float gh_n = sm[X_GH2 + m * 48 + 32 + j];
                float r = sigf(gi_r + gh_r + br);
                float z = sigf(gi_z + gh_z + bz2);
                float n = tanhf(gi_n + r * (gh_n + bn));
                float hold = hin[m * 1024 + col];
                float hn = (1.f - z) * n + z * hold;
                hout[m * 1024 + col] = rnd_tf32(hn);
                long ti = ((long)m * 32 + tt) * 1024 + col;
                if (storeFirst) txt[ti] = 0.5f * hn;
                else            txt[ti] += 0.5f * hn;
            }
        } else {
            int b2 = blockIdx.x - 128;
            int img = b2 >> 1;
            int cg = b2 & 1;
            const float* Whh = g_scratch + O_WHH + (long)img * 49152;
            const float* Wih = g_scratch + O_WIH + (long)img * 49152;
            const float* bhh = g_scratch + O_BHH + (long)img * 384;
            const float* bih = g_scratch + O_BIH + (long)img * 384;
            float* hb = g_scratch + O_HG;
            const float* hin = hb + (long)(t & 1) * 524288 + (long)img * 8192;
            float* hout = hb + (long)((t + 1) & 1) * 524288 + (long)img * 8192;
            float* hmax = g_scratch + O_HMAX + (long)img * 8192;
            const float* crbase = g_scratch + O_GIALL + (long)t * 64 * 6272 + 6144;

#pragma unroll
            for (int sub = 0; sub < 2; sub++) {
                int j0 = cg * 64 + sub * 32;
                run_gemm_gen(hin, 128, Whh, j0, X_GH);
                run_gemm_gen(crbase, 6272, Wih, j0, X_GI);

                int j = tid & 31, mg = tid >> 5;
                int col = j0 + j;
                float cr_ = bih[col] + bhh[col];
                float cz_ = bih[128 + col] + bhh[128 + col];
                float bni = bih[256 + col], bnh = bhh[256 + col];
#pragma unroll
                for (int i = 0; i < 8; i++) {
                    int m = mg * 8 + i;
                    float gh_r = sm[X_GH + m * 96 + j];
                    float gh_z = sm[X_GH + m * 96 + 32 + j];
                    float gh_n = sm[X_GH + m * 96 + 64 + j];
                    float gi_r = sm[X_GI + m * 96 + j];
                    float gi_z = sm[X_GI + m * 96 + 32 + j];
                    float gi_n = sm[X_GI + m * 96 + 64 + j];
                    float r = sigf(gi_r + gh_r + cr_);
                    float z = sigf(gi_z + gh_z + cz_);
                    float n = tanhf(gi_n + bni + r * (gh_n + bnh));
                    float hold = hin[m * 128 + col];
                    float hn = (1.f - z) * n + z * hold;
                    hout[m * 128 + col] = rnd_tf32(hn);
                    hmax[m * 128 + col] = fmaxf(hmax[m * 128 + col], hn);
                }
            }
        }

        // ---- software grid barrier ----
        __syncthreads();
        __threadfence();
        if (tid == 0) {
            atomicAdd(&g_barcnt, 1u);
            unsigned tgt = (unsigned)NBLK_STEP * (unsigned)(t + 1);
            while (*(volatile unsigned int*)&g_barcnt < tgt) {}
            __threadfence();
        }
        __syncthreads();
    }
}

// ---------------------------------------------------------------------------
// Fused image path: region mean -> IEG, l2norm -> IVN, reduce-proj -> IGV.
// ---------------------------------------------------------------------------
__global__ __launch_bounds__(256) void imgvec_k(
    const float* __restrict__ img_embed,
    const float* __restrict__ W_reduce_img, const float* __restrict__ b_reduce_img)
{
    __shared__ float s_ieg[1024];
    __shared__ float red[256];
    int b = blockIdx.x, tid = threadIdx.x;
    float vals[4], ss = 0.f;
#pragma unroll
    for (int i = 0; i < 4; i++) {
        int c = i * 256 + tid;
        float s = 0.f;
        for (int g = 0; g < 36; g++) s += img_embed[(long)b * 36864 + (long)g * 1024 + c];
        s *= (1.f / 36.f);
        vals[i] = s;
        ss += s * s;
        s_ieg[c] = s;
        g_scratch[O_IEG + (long)b * 1024 + c] = s;
    }
    red[tid] = ss;
    __syncthreads();
    for (int o = 128; o > 0; o >>= 1) { if (tid < o) red[tid] += red[tid + o]; __syncthreads(); }
    float inv = 1.f / (sqrtf(red[0]) + 1e-8f);
#pragma unroll
    for (int i = 0; i < 4; i++) {
        int c = i * 256 + tid;
        g_scratch[O_IVN + (long)b * 1024 + c] = vals[i] * inv;
    }
    int o = tid >> 1, half = tid & 1;
    const float* wrow = W_reduce_img + (long)o * 1024 + half * 512;
    const float* xrow = s_ieg + half * 512;
    float acc = 0.f;
#pragma unroll 4
    for (int k = 0; k < 512; k += 4) {
        float4 w = *reinterpret_cast<const float4*>(&wrow[k]);
        float4 x = *reinterpret_cast<const float4*>(&xrow[k]);
        acc += w.x * x.x + w.y * x.y + w.z * x.z + w.w * x.w;
    }
    acc += __shfl_xor_sync(0xffffffffu, acc, 1);
    if (half == 0)
        g_scratch[O_IGV + (long)b * 128 + o] = acc + b_reduce_img[o];
}

// attention scores + softmax over fused QKV buffer (row stride 1280)
__global__ __launch_bounds__(256) void attn_k() {
    int gw = (blockIdx.x * blockDim.x + threadIdx.x) >> 5;
    int lane = threadIdx.x & 31;
    if (gw >= 2048) return;
    int b = gw >> 5;
    const float* qr = g_scratch + O_QKV + (long)gw * 1280;
    const float* kr = g_scratch + O_QKV + ((long)b * 32 + lane) * 1280 + 128;
    float s = 0.f;
#pragma unroll 8
    for (int o = 0; o < 128; o++) s += qr[o] * kr[o];
    float mx = s;
#pragma unroll
    for (int off = 16; off > 0; off >>= 1) mx = fmaxf(mx, __shfl_xor_sync(0xffffffffu, mx, off));
    float e = expf(s - mx);
    float sum = e;
#pragma unroll
    for (int off = 16; off > 0; off >>= 1) sum += __shfl_xor_sync(0xffffffffu, sum, off);
    g_scratch[O_ATT + (long)gw * 32 + lane] = e / sum;
}

__global__ __launch_bounds__(32) void aw_k(const int* __restrict__ lens) {
    int b = blockIdx.x, s = threadIdx.x;
    int len = lens[b];
    float a = 0.f;
    for (int tt = 0; tt < len; tt++) a += g_scratch[O_ATT + ((long)b * 32 + tt) * 32 + s];
    g_scratch[O_AW + b * 32 + s] = a;
}

__global__ __launch_bounds__(256) void txt_embed_k(const int* __restrict__ lens,
                                                   const float* __restrict__ gamma) {
    int b = blockIdx.y;
    int c = blockIdx.x * 256 + threadIdx.x;
    __shared__ float saw[32];
    if (threadIdx.x < 32) saw[threadIdx.x] = g_scratch[O_AW + b * 32 + threadIdx.x];
    __syncthreads();
    int len = lens[b];
    float g = *gamma;
    float a1 = 0.f;
    for (int tt = 0; tt < len; tt++) a1 += g_scratch[O_TXT + ((long)b * 32 + tt) * 1024 + c];
    float a2 = 0.f;
#pragma unroll
    for (int s = 0; s < 32; s++)
        a2 += saw[s] * g_scratch[O_QKV + ((long)b * 32 + s) * 1280 + 256 + c];
    g_scratch[O_TE + (long)b * 1024 + c] = (a1 + g * a2) / (float)len;
}

// sims[i,b] = (y . iv_i) / (|y| + eps)
__global__ __launch_bounds__(256) void sims_k(float* __restrict__ out) {
    int img = blockIdx.y, b = blockIdx.x;
    int tid = threadIdx.x;
    const float* y = g_scratch + O_Y + (long)img * 65536 + (long)b * 1024;
    const float* iv = g_scratch + O_IVN + (long)img * 1024;
    float ss = 0.f, dp = 0.f;
#pragma unroll
    for (int i = 0; i < 4; i++) {
        int c = i * 256 + tid;
        float v = y[c];
        ss += v * v;
        dp += v * iv[c];
    }
    __shared__ float r1[256], r2[256];
    r1[tid] = ss; r2[tid] = dp;
    __syncthreads();
    for (int o = 128; o > 0; o >>= 1) {
        if (tid < o) { r1[tid] += r1[tid + o]; r2[tid] += r2[tid + o]; }
        __syncthreads();
    }
    if (tid == 0) out[img * 64 + b] = r2[0] / (sqrtf(r1[0]) + 1e-8f);
}

// ---------------------------------------------------------------------------
extern "C" void kernel_launch(void* const* d_in, const int* in_sizes, int n_in,
                              void* d_out, int out_size) {
    const float* img_embed    = (const float*)d_in[0];
    const float* cap_embed    = (const float*)d_in[1];
    const int*   lens         = (const int*)d_in[2];
    const float* W_reduce_img = (const float*)d_in[3];
    const float* b_reduce_img = (const float*)d_in[4];
    const float* W_reduce_txt = (const float*)d_in[5];
    const float* b_reduce_txt = (const float*)d_in[6];
    const float* gru_Wih_f    = (const float*)d_in[7];
    const float* gru_Whh_f    = (const float*)d_in[8];
    const float* gru_bih_f    = (const float*)d_in[9];
    const float* gru_bhh_f    = (const float*)d_in[10];
    const float* gru_Wih_b    = (const float*)d_in[11];
    const float* gru_Whh_b    = (const float*)d_in[12];
    const float* gru_bih_b    = (const float*)d_in[13];
    const float* gru_bhh_b    = (const float*)d_in[14];
    const float* sa_Wq        = (const float*)d_in[15];
    const float* sa_bq        = (const float*)d_in[16];
    const float* sa_Wk        = (const float*)d_in[17];
    const float* sa_bk        = (const float*)d_in[18];
    const float* sa_Wv        = (const float*)d_in[19];
    const float* sa_bv        = (const float*)d_in[20];
    const float* sa_gamma     = (const float*)d_in[21];
    const float* gen_Wih      = (const float*)d_in[22];
    const float* gen_bih      = (const float*)d_in[23];
    const float* gen_Whh      = (const float*)d_in[24];
    const float* gen_bhh      = (const float*)d_in[25];
    const float* gen_Wbih     = (const float*)d_in[26];
    const float* gen_bbih     = (const float*)d_in[27];
    const float* gen_Wbhh     = (const float*)d_in[28];
    const float* gen_bbhh     = (const float*)d_in[29];
    const float* W_txt_fc     = (const float*)d_in[30];
    const float* b_txt_fc     = (const float*)d_in[31];

    float* S = nullptr;
    cudaGetSymbolAddress((void**)&S, g_scratch);

    const int SMEM_TF32 = 2 * 2 * STG * 4;   // 73728 B
    const int SMEM_STEP = 98304;
    cudaFuncSetAttribute(gemm_tf32<0>, cudaFuncAttributeMaxDynamicSharedMemorySize, SMEM_TF32);
    cudaFuncSetAttribute(gemm_tf32<1>, cudaFuncAttributeMaxDynamicSharedMemorySize, SMEM_TF32);
    cudaFuncSetAttribute(steps_k, cudaFuncAttributeMaxDynamicSharedMemorySize, SMEM_STEP);

    init_k<<<4096, 256>>>();

    // Concatenate weights for fused GEMMs (D2D copies, graph-capturable)
    cudaMemcpyAsync(S + O_WGI,              gru_Wih_f,    3072L*300*4, cudaMemcpyDeviceToDevice);
    cudaMemcpyAsync(S + O_WGI + 3072L*300,  gru_Wih_b,    3072L*300*4, cudaMemcpyDeviceToDevice);
    cudaMemcpyAsync(S + O_WGI + 6144L*300,  W_reduce_txt, 128L*300*4,  cudaMemcpyDeviceToDevice);
    cudaMemcpyAsync(S + O_BGI,              gru_bih_f,    3072L*4,     cudaMemcpyDeviceToDevice);
    cudaMemcpyAsync(S + O_BGI + 3072,       gru_bih_b,    3072L*4,     cudaMemcpyDeviceToDevice);
    cudaMemcpyAsync(S + O_BGI + 6144,       b_reduce_txt, 128L*4,      cudaMemcpyDeviceToDevice);
    cudaMemcpyAsync(S + O_WQKV,             sa_Wq,        128L*1024*4, cudaMemcpyDeviceToDevice);
    cudaMemcpyAsync(S + O_WQKV + 128L*1024, sa_Wk,        128L*1024*4, cudaMemcpyDeviceToDevice);
    cudaMemcpyAsync(S + O_WQKV + 256L*1024, sa_Wv,        1024L*1024*4,cudaMemcpyDeviceToDevice);
    cudaMemcpyAsync(S + O_BQKV,             sa_bq,        128L*4,      cudaMemcpyDeviceToDevice);
    cudaMemcpyAsync(S + O_BQKV + 128,       sa_bk,        128L*4,      cudaMemcpyDeviceToDevice);
    cudaMemcpyAsync(S + O_BQKV + 256,       sa_bv,        1024L*4,     cudaMemcpyDeviceToDevice);
    // main-GRU hidden biases just below O_WHF (overlaps tail of Y; Y written later)
    cudaMemcpyAsync(S + O_WHF - 8192,        gru_bhh_f,   3072L*4,     cudaMemcpyDeviceToDevice);
    cudaMemcpyAsync(S + O_WHF - 8192 + 3072, gru_bhh_b,   3072L*4,     cudaMemcpyDeviceToDevice);

    // pre-rounded tf32 copies of main recurrent weights
    cvtw_k<<<3072, 256>>>(gru_Whh_f, S + O_WHF, 3072L*1024/4);
    cvtw_k<<<3072, 256>>>(gru_Whh_b, S + O_WHB, 3072L*1024/4);

    // Fused GI_f|GI_b|CR projection: (T*B, 6272); CR columns pre-rounded (rnd=2)
    gemm_tf32<1><<<dim3(49, 16, 1), 256, SMEM_TF32>>>(
        cap_embed, S + O_WGI, S + O_BGI, nullptr, S + O_GIALL,
        2048, 6272, 300, 300, 300, 0, 0, 0, 0, 2);

    // image path: pool + l2norm + reduce projection, fused
    imgvec_k<<<64, 256>>>(img_embed, W_reduce_img, b_reduce_img);

    // generated GRU weights per image (outputs pre-rounded to tf32)
    gemm_tf32<0><<<dim3(384, 1, 1), 256, SMEM_TF32>>>(
        S + O_IGV, gen_Wih, gen_bih, nullptr, S + O_WIH,
        64, 49152, 128, 128, 128, 0, 0, 0, 0, 1);
    gemm_tf32<0><<<dim3(384, 1, 1), 256, SMEM_TF32>>>(
        S + O_IGV, gen_Whh, gen_bhh, nullptr, S + O_WHH,
        64, 49152, 128, 128, 128, 0, 0, 0, 0, 1);
    gemm_tf32<0><<<dim3(3, 1, 1), 256, SMEM_TF32>>>(
        S + O_IGV, gen_Wbih, gen_bbih, nullptr, S + O_BIH,
        64, 384, 128, 128, 128, 0, 0, 0, 0, 0);
    gemm_tf32<0><<<dim3(3, 1, 1), 256, SMEM_TF32>>>(
        S + O_IGV, gen_Wbhh, gen_bbhh, nullptr, S + O_BHH,
        64, 384, 128, 128, 128, 0, 0, 0, 0, 0);

    // ALL 32 recurrent steps in one persistent launch (grid barrier inside)
    steps_k<<<NBLK_STEP, 256, SMEM_STEP>>>();

    // fused Q|K|V projection: (B*T, 1280)
    gemm_tf32<0><<<dim3(10, 16, 1), 256, SMEM_TF32>>>(
        S + O_TXT, S + O_WQKV, S + O_BQKV, nullptr, S + O_QKV,
        2048, 1280, 1024, 1024, 1024, 0, 0, 0, 0, 0);
    attn_k<<<256, 256>>>();
    aw_k<<<64, 32>>>(lens);
    txt_embed_k<<<dim3(4, 64), 256>>>(lens, sa_gamma);

    // final FC: shared part + per-image correction
    gemm_tf32<0><<<dim3(8, 1, 1), 256, SMEM_TF32>>>(
        S + O_TE, W_txt_fc, b_txt_fc, nullptr, S + O_FCB,
        64, 1024, 1024, 1024, 1152, 0, 0, 0, 0, 0);
    gemm_tf32<0><<<dim3(8, 1, 64), 256, SMEM_TF32>>>(
        S + O_HMAX, W_txt_fc + 1024, nullptr, S + O_FCB, S + O_Y,
        64, 1024, 128, 128, 1152, 64L * 128, 0, 0, 64L * 1024, 0);

    sims_k<<<dim3(64, 64), 256>>>((float*)d_out);
}